// round 10
// baseline (speedup 1.0000x reference)
#include <cuda_runtime.h>
#include <cuda_bf16.h>
#include <cstdint>
#include <math.h>

#define BB 8
#define SS 1024
#define DD 1024
#define NH 16
#define HH 64
#define MROWS (BB*SS)            // 8192
#define Y_SIZE (BB*SS*DD)        // 8388608

// ---------------------------------------------------------------------------
// Scratch (device globals; no allocations allowed)
// ---------------------------------------------------------------------------
__device__ float g_ypre[MROWS*DD];                         // pre-layernorm y
__device__ __nv_bfloat16 g_xhi[MROWS*DD], g_xlo[MROWS*DD]; // x split
__device__ __nv_bfloat16 g_wThi[DD*DD], g_wTlo[DD*DD];     // proj B: [c=n*64+h][d]
__device__ __nv_bfloat16 g_lwhi[DD*DD], g_lwlo[DD*DD];     // outproj B: [d][k]
__device__ __nv_bfloat16 g_lhi[MROWS*DD], g_llo[MROWS*DD]; // logits split [r][n*64+h]
__device__ __nv_bfloat16 g_ohhi[MROWS*DD], g_ohlo[MROWS*DD]; // attn heads out split

// ---------------------------------------------------------------------------
// mma.sync / ldmatrix / cp.async helpers (base ISA)
// ---------------------------------------------------------------------------
__device__ __forceinline__ uint32_t smem_u32(const void* p) {
    uint32_t a;
    asm("{ .reg .u64 t; cvta.to.shared.u64 t, %1; cvt.u32.u64 %0, t; }" : "=r"(a) : "l"(p));
    return a;
}

__device__ __forceinline__ void mma_bf16(float c[4],
                                         unsigned a0, unsigned a1, unsigned a2, unsigned a3,
                                         unsigned b0, unsigned b1) {
    asm volatile("mma.sync.aligned.m16n8k16.row.col.f32.bf16.bf16.f32 "
        "{%0,%1,%2,%3}, {%4,%5,%6,%7}, {%8,%9}, {%0,%1,%2,%3};"
        : "+f"(c[0]), "+f"(c[1]), "+f"(c[2]), "+f"(c[3])
        : "r"(a0), "r"(a1), "r"(a2), "r"(a3), "r"(b0), "r"(b1));
}

__device__ __forceinline__ void ldsm4(unsigned r[4], uint32_t addr) {
    asm volatile("ldmatrix.sync.aligned.m8n8.x4.shared.b16 {%0,%1,%2,%3}, [%4];"
        : "=r"(r[0]), "=r"(r[1]), "=r"(r[2]), "=r"(r[3]) : "r"(addr));
}
__device__ __forceinline__ void ldsm4t(unsigned r[4], uint32_t addr) {
    asm volatile("ldmatrix.sync.aligned.m8n8.x4.trans.shared.b16 {%0,%1,%2,%3}, [%4];"
        : "=r"(r[0]), "=r"(r[1]), "=r"(r[2]), "=r"(r[3]) : "r"(addr));
}

__device__ __forceinline__ void cp16(uint32_t dst, const void* src) {
    asm volatile("cp.async.cg.shared.global [%0], [%1], 16;" :: "r"(dst), "l"(src));
}
#define CP_COMMIT() asm volatile("cp.async.commit_group;" ::: "memory")
#define CP_WAIT1()  asm volatile("cp.async.wait_group 1;" ::: "memory")
#define CP_WAIT0()  asm volatile("cp.async.wait_group 0;" ::: "memory")

// hi/lo split of float pair -> two packed bf16x2 regs
__device__ __forceinline__ void split2(float x, float y, unsigned& h, unsigned& l) {
    __nv_bfloat16 hx = __float2bfloat16(x), hy = __float2bfloat16(y);
    __nv_bfloat162 hp(hx, hy);
    __nv_bfloat162 lp(__float2bfloat16(x - __bfloat162float(hx)),
                      __float2bfloat16(y - __bfloat162float(hy)));
    h = *(unsigned*)&hp;
    l = *(unsigned*)&lp;
}

// ---------------------------------------------------------------------------
// Converters: fp32 -> bf16 hi/lo split
// ---------------------------------------------------------------------------
__global__ __launch_bounds__(256) void split4_kernel(const float* __restrict__ s,
                                                     __nv_bfloat16* __restrict__ hi,
                                                     __nv_bfloat16* __restrict__ lo, int n4) {
    int i = blockIdx.x * 256 + threadIdx.x;
    if (i >= n4) return;
    float4 v = ((const float4*)s)[i];
    unsigned h0, l0, h1, l1;
    split2(v.x, v.y, h0, l0);
    split2(v.z, v.w, h1, l1);
    ((unsigned*)hi)[i*2]   = h0;
    ((unsigned*)hi)[i*2+1] = h1;
    ((unsigned*)lo)[i*2]   = l0;
    ((unsigned*)lo)[i*2+1] = l1;
}

// w [NH][DD][HH] -> wT[c=n*64+h][d], split hi/lo
__global__ __launch_bounds__(256) void convw_kernel(const float* __restrict__ w) {
    int o = blockIdx.x * 256 + threadIdx.x;
    int c = o >> 10, d = o & 1023;
    int n = c >> 6, h = c & 63;
    float v = __ldg(&w[(n * 1024 + d) * 64 + h]);
    __nv_bfloat16 hv = __float2bfloat16(v);
    g_wThi[o] = hv;
    g_wTlo[o] = __float2bfloat16(v - __bfloat162float(hv));
}

// ---------------------------------------------------------------------------
// Dense GEMM via mma.sync. Synchronous loads (R5-winning config), K chunk 64,
// single 73.7KB smem buffer -> 2 CTAs/SM. Block 128x128, 8 warps as 4m x 2n,
// warp tile 32x64 (mma:ldsm ratio 4). Smem row stride 72 bf16 (144B).
// EPI 0: C as bf16 hi/lo. EPI 1: fp32 C = acc + RX + BIAS.
// ---------------------------------------------------------------------------
#define GP_AH 0
#define GP_AL 18432
#define GP_BH 36864
#define GP_BL 55296
#define GSMEM 73728

template<int EPI>
__global__ __launch_bounds__(256) void gemm_mma(
    const __nv_bfloat16* __restrict__ Ah, const __nv_bfloat16* __restrict__ Al,
    const __nv_bfloat16* __restrict__ Bh, const __nv_bfloat16* __restrict__ Bl,
    __nv_bfloat16* __restrict__ Chi, __nv_bfloat16* __restrict__ Clo,
    float* __restrict__ Cf, const float* __restrict__ RX, const float* __restrict__ BIAS)
{
    extern __shared__ char sm[];
    const uint32_t sb = smem_u32(sm);
    const int tid = threadIdx.x, w = tid >> 5, lane = tid & 31;
    const int wm = w >> 1, wn = w & 1;            // 4m x 2n
    const int r0 = blockIdx.x * 128, c0 = blockIdx.y * 128;
    const int lrow = tid >> 3, lc8 = tid & 7;

    float acc[2][8][4] = {};      // [mi][n8 group 0..7][4]

    #pragma unroll 1
    for (int k0 = 0; k0 < 1024; k0 += 64) {
        __syncthreads();
        #pragma unroll
        for (int it = 0; it < 4; it++) {
            int rr = lrow + it * 32;
            size_t goA = (size_t)(r0 + rr) * 1024 + k0 + lc8 * 8;
            size_t goB = (size_t)(c0 + rr) * 1024 + k0 + lc8 * 8;
            uint32_t so = rr * 144 + lc8 * 16;
            *(uint4*)(sm + GP_AH + so) = *(const uint4*)(Ah + goA);
            *(uint4*)(sm + GP_AL + so) = *(const uint4*)(Al + goA);
            *(uint4*)(sm + GP_BH + so) = *(const uint4*)(Bh + goB);
            *(uint4*)(sm + GP_BL + so) = *(const uint4*)(Bl + goB);
        }
        __syncthreads();
        #pragma unroll
        for (int ks = 0; ks < 4; ks++) {
            unsigned ah[2][4], al[2][4], bh[4][4], bl[4][4];
            uint32_t abase = sb + (wm * 32 + (lane & 15)) * 144 + ks * 32 + (lane >> 4) * 16;
            #pragma unroll
            for (int mi = 0; mi < 2; mi++) {
                ldsm4(ah[mi], abase + GP_AH + mi * 2304);
                ldsm4(al[mi], abase + GP_AL + mi * 2304);
            }
            uint32_t bbase = sb + (wn * 64 + (lane & 15)) * 144 + ks * 32 + (lane >> 4) * 16;
            #pragma unroll
            for (int ni = 0; ni < 4; ni++) {
                ldsm4(bh[ni], bbase + GP_BH + ni * 2304);
                ldsm4(bl[ni], bbase + GP_BL + ni * 2304);
            }
            #pragma unroll
            for (int mi = 0; mi < 2; mi++)
                #pragma unroll
                for (int ni = 0; ni < 4; ni++) {
                    mma_bf16(acc[mi][2*ni],   ah[mi][0],ah[mi][1],ah[mi][2],ah[mi][3], bh[ni][0], bh[ni][2]);
                    mma_bf16(acc[mi][2*ni+1], ah[mi][0],ah[mi][1],ah[mi][2],ah[mi][3], bh[ni][1], bh[ni][3]);
                    mma_bf16(acc[mi][2*ni],   ah[mi][0],ah[mi][1],ah[mi][2],ah[mi][3], bl[ni][0], bl[ni][2]);
                    mma_bf16(acc[mi][2*ni+1], ah[mi][0],ah[mi][1],ah[mi][2],ah[mi][3], bl[ni][1], bl[ni][3]);
                    mma_bf16(acc[mi][2*ni],   al[mi][0],al[mi][1],al[mi][2],al[mi][3], bh[ni][0], bh[ni][2]);
                    mma_bf16(acc[mi][2*ni+1], al[mi][0],al[mi][1],al[mi][2],al[mi][3], bh[ni][1], bh[ni][3]);
                }
        }
    }

    // epilogue: warp covers rows [wm*32, +32), cols [wn*64, +64)
    #pragma unroll
    for (int mi = 0; mi < 2; mi++) {
        int rr = r0 + wm * 32 + mi * 16 + (lane >> 2);
        #pragma unroll
        for (int nj = 0; nj < 8; nj++) {
            int cc = c0 + wn * 64 + nj * 8 + 2 * (lane & 3);
            if (EPI == 0) {
                #pragma unroll
                for (int half = 0; half < 2; half++) {
                    unsigned h, l;
                    split2(acc[mi][nj][half*2], acc[mi][nj][half*2+1], h, l);
                    size_t go = (size_t)(rr + half*8) * 1024 + cc;
                    *(unsigned*)(Chi + go) = h;
                    *(unsigned*)(Clo + go) = l;
                }
            } else {
                #pragma unroll
                for (int half = 0; half < 2; half++) {
                    size_t go = (size_t)(rr + half*8) * 1024 + cc;
                    float2 xv = *(const float2*)(RX + go);
                    float2 bv = *(const float2*)(BIAS + cc);
                    float2 o;
                    o.x = acc[mi][nj][half*2]   + xv.x + bv.x;
                    o.y = acc[mi][nj][half*2+1] + xv.y + bv.y;
                    *(float2*)(Cf + go) = o;
                }
            }
        }
    }
}

// ---------------------------------------------------------------------------
// Fused attention per (n, b, 32-row tile), tensorized + cp.async dbuf
// (R7-proven version, 256 threads).
// ---------------------------------------------------------------------------
#define SCSTR 1032
#define A_QH  132096                    // 32*72*2 = 4608
#define A_QL  136704
#define A_KB  141312                    // 2 bufs x (KH 18432 + KL 18432)
#define A_KBUF 36864
#define ASMEM (A_KB + 2*A_KBUF)         // 215040

__global__ __launch_bounds__(256) void attn_kernel(
    const __nv_bfloat16* __restrict__ LHI, const __nv_bfloat16* __restrict__ LLO,
    float* __restrict__ out_attn,
    __nv_bfloat16* __restrict__ OHI, __nv_bfloat16* __restrict__ OLO)
{
    extern __shared__ char sm[];
    const uint32_t sb = smem_u32(sm);
    float* scores = (float*)sm;
    __shared__ float rs[32];

    const int rt = blockIdx.x, b = blockIdx.y, n = blockIdx.z;
    const int s0 = rt * 32;
    const int tid = threadIdx.x, w = tid >> 5, lane = tid & 31;
    const size_t rowbase = (size_t)b * 1024;
    const int colbase = n * 64;
    const int lrow = tid >> 3, lc8 = tid & 7;

    auto load_kv = [&](int buf, int tile) {
        const uint32_t bh = sb + A_KB + buf * A_KBUF;
        #pragma unroll
        for (int it = 0; it < 4; it++) {
            int row = lrow + it * 32;
            size_t go = (rowbase + tile * 128 + row) * 1024 + colbase + lc8 * 8;
            uint32_t so = (row * 72 + lc8 * 8) * 2;
            cp16(bh + so,         LHI + go);
            cp16(bh + 18432 + so, LLO + go);
        }
    };

    // load Q tile (32 x 64) hi/lo (direct) + prefetch K tile 0
    load_kv(0, 0);
    CP_COMMIT();
    {
        int row = tid >> 3, c8 = tid & 7;
        uint32_t so = (row * 72 + c8 * 8) * 2;
        size_t go = (rowbase + s0 + row) * 1024 + colbase + c8 * 8;
        *(uint4*)(sm + A_QH + so) = *(const uint4*)(LHI + go);
        *(uint4*)(sm + A_QL + so) = *(const uint4*)(LLO + go);
    }

    const float scale = 0.125f;
    // ---- QK^T: 8 key tiles of 128, double-buffered ----
    #pragma unroll 1
    for (int kt = 0; kt < 8; kt++) {
        if (kt < 7) {
            load_kv((kt + 1) & 1, kt + 1);
            CP_COMMIT();
            CP_WAIT1();
        } else {
            CP_WAIT0();
        }
        __syncthreads();
        const uint32_t kbase = sb + A_KB + (kt & 1) * A_KBUF;

        float sqk[2][2][4] = {};
        #pragma unroll
        for (int ks = 0; ks < 4; ks++) {
            unsigned qh[2][4], ql[2][4], kh[4], kl[4];
            uint32_t qb = sb + (((lane & 15)) * 72 + ks * 16 + (lane >> 4) * 8) * 2;
            ldsm4(qh[0], qb + A_QH);          ldsm4(ql[0], qb + A_QL);
            ldsm4(qh[1], qb + A_QH + 2304);   ldsm4(ql[1], qb + A_QL + 2304);
            uint32_t kb = kbase + ((w * 16 + (lane & 15)) * 72 + ks * 16 + (lane >> 4) * 8) * 2;
            ldsm4(kh, kb);                    ldsm4(kl, kb + 18432);
            #pragma unroll
            for (int mi = 0; mi < 2; mi++) {
                mma_bf16(sqk[mi][0], qh[mi][0],qh[mi][1],qh[mi][2],qh[mi][3], kh[0], kh[2]);
                mma_bf16(sqk[mi][1], qh[mi][0],qh[mi][1],qh[mi][2],qh[mi][3], kh[1], kh[3]);
                mma_bf16(sqk[mi][0], qh[mi][0],qh[mi][1],qh[mi][2],qh[mi][3], kl[0], kl[2]);
                mma_bf16(sqk[mi][1], qh[mi][0],qh[mi][1],qh[mi][2],qh[mi][3], kl[1], kl[3]);
                mma_bf16(sqk[mi][0], ql[mi][0],ql[mi][1],ql[mi][2],ql[mi][3], kh[0], kh[2]);
                mma_bf16(sqk[mi][1], ql[mi][0],ql[mi][1],ql[mi][2],ql[mi][3], kh[1], kh[3]);
            }
        }
        #pragma unroll
        for (int mi = 0; mi < 2; mi++) {
            int sr = mi * 16 + (lane >> 2);
            #pragma unroll
            for (int nj = 0; nj < 2; nj++) {
                int cc = kt * 128 + w * 16 + nj * 8 + 2 * (lane & 3);
                *(float2*)&scores[sr * SCSTR + cc] =
                    make_float2(sqk[mi][nj][0] * scale, sqk[mi][nj][1] * scale);
                *(float2*)&scores[(sr + 8) * SCSTR + cc] =
                    make_float2(sqk[mi][nj][2] * scale, sqk[mi][nj][3] * scale);
            }
        }
        __syncthreads();
    }

    // ---- softmax (fp32 exact): row = tid/8, stride-8 conflict-free scan ----
    {
        const int row = tid >> 3, c = tid & 7;
        float* srow = scores + row * SCSTR;
        float m = -1e30f;
        #pragma unroll 8
        for (int i = 0; i < 128; i++) m = fmaxf(m, srow[c + 8 * i]);
        m = fmaxf(m, __shfl_xor_sync(0xffffffffu, m, 1));
        m = fmaxf(m, __shfl_xor_sync(0xffffffffu, m, 2));
        m = fmaxf(m, __shfl_xor_sync(0xffffffffu, m, 4));
        float sum = 0.f;
        #pragma unroll 8
        for (int i = 0; i < 128; i++) {
            float e = __expf(srow[c + 8 * i] - m);
            srow[c + 8 * i] = e;
            sum += e;
        }
        sum += __shfl_xor_sync(0xffffffffu, sum, 1);
        sum += __shfl_xor_sync(0xffffffffu, sum, 2);
        sum += __shfl_xor_sync(0xffffffffu, sum, 4);
        if (c == 0) rs[row] = 1.0f / sum;
    }
    __syncthreads();

    // prefetch V tile 0 (overlaps the attn gmem write below)
    load_kv(0, 0);
    CP_COMMIT();

    // ---- write normalized attention ----
    {
        float* ap = out_attn + ((size_t)(n * BB + b)) * SS * SS + (size_t)s0 * SS;
        #pragma unroll
        for (int it = 0; it < 32; it++) {
            int idx = tid + it * 256;
            int r = idx >> 8;
            int c4 = (idx & 255) << 2;
            float4 v = *(const float4*)&scores[r * SCSTR + c4];
            float iv = rs[r];
            v.x *= iv; v.y *= iv; v.z *= iv; v.w *= iv;
            *(float4*)&ap[(size_t)r * SS + c4] = v;
        }
    }

    // ---- P @ V: warps 2m x 4n (16q x 16h each); P fp32 from scores,
    //      register hi/lo split; V dbuf ----
    const int wm = w >> 2, wn = w & 3;
    float pacc[2][4] = {};
    const int qr = wm * 16 + (lane >> 2);
    const int kcl = (lane & 3) * 2;
    #pragma unroll 1
    for (int jt = 0; jt < 8; jt++) {
        if (jt < 7) {
            load_kv((jt + 1) & 1, jt + 1);
            CP_COMMIT();
            CP_WAIT1();
        } else {
            CP_WAIT0();
        }
        __syncthreads();
        const uint32_t vbase = sb + A_KB + (jt & 1) * A_KBUF;

        #pragma unroll
        for (int ks = 0; ks < 8; ks++) {
            const int kc = jt * 128 + ks * 16 + kcl;
            float2 p00 = *(const float2*)&scores[qr * SCSTR + kc];
            float2 p10 = *(const float2*)&scores[(qr + 8) * SCSTR + kc];
            float2 p01 = *(const float2*)&scores[qr * SCSTR + kc + 8];
            float2 p11 = *(const float2*)&scores[(qr + 8) * SCSTR + kc + 8];
            unsigned ph4[4], pl4[4];
            split2(p00.x, p00.y, ph4[0], pl4[0]);
            split2(p10.x, p10.y, ph4[1], pl4[1]);
            split2(p01.x, p01.y, ph4[2], pl4[2]);
            split2(p11.x, p11.y, ph4[3], pl4[3]);

            unsigned vh[4], vl[4];
            uint32_t vb = vbase + ((ks * 16 + (lane & 15)) * 72 + wn * 16 + (lane >> 4) * 8) * 2;
            ldsm4t(vh, vb);
            ldsm4t(vl, vb + 18432);

            mma_bf16(pacc[0], ph4[0],ph4[1],ph4[2],ph4[3], vh[0], vh[1]);
            mma_bf16(pacc[1], ph4[0],ph4[1],ph4[2],ph4[3], vh[2], vh[3]);
            mma_bf16(pacc[0], ph4[0],ph4[1],ph4[2],ph4[3], vl[0], vl[1]);
            mma_bf16(pacc[1], ph4[0],ph4[1],ph4[2],ph4[3], vl[2], vl[3]);
            mma_bf16(pacc[0], pl4[0],pl4[1],pl4[2],pl4[3], vh[0], vh[1]);
            mma_bf16(pacc[1], pl4[0],pl4[1],pl4[2],pl4[3], vh[2], vh[3]);
        }
        __syncthreads();
    }

    // ---- epilogue: scale by 1/rowsum, write outh bf16 hi/lo ----
    {
        float iv0 = rs[qr], iv1 = rs[qr + 8];
        #pragma unroll
        for (int nj = 0; nj < 2; nj++) {
            int cc = colbase + wn * 16 + nj * 8 + 2 * (lane & 3);
            size_t go = (rowbase + s0 + qr) * 1024 + cc;
            unsigned h0, l0, h1, l1;
            split2(pacc[nj][0] * iv0, pacc[nj][1] * iv0, h0, l0);
            split2(pacc[nj][2] * iv1, pacc[nj][3] * iv1, h1, l1);
            *(unsigned*)(OHI + go) = h0;
            *(unsigned*)(OLO + go) = l0;
            *(unsigned*)(OHI + go + 8 * 1024) = h1;
            *(unsigned*)(OLO + go + 8 * 1024) = l1;
        }
    }
}

// ---------------------------------------------------------------------------
// Layernorm per row of 1024
// ---------------------------------------------------------------------------
__global__ __launch_bounds__(256) void ln_kernel(float* __restrict__ y,
                                                 const float* __restrict__ g,
                                                 const float* __restrict__ bfn) {
    const int r = blockIdx.x;
    const int tid = threadIdx.x;
    const int lane = tid & 31, wid = tid >> 5;
    __shared__ float red1[8];
    __shared__ float red2[8];
    __shared__ float sh_mu, sh_rstd;

    float4 v = *(const float4*)&g_ypre[r * 1024 + tid * 4];
    float s = v.x + v.y + v.z + v.w;
    #pragma unroll
    for (int o = 16; o > 0; o >>= 1) s += __shfl_xor_sync(0xffffffffu, s, o);
    if (lane == 0) red1[wid] = s;
    __syncthreads();
    if (tid == 0) {
        float t = 0.f;
        #pragma unroll
        for (int i = 0; i < 8; i++) t += red1[i];
        sh_mu = t * (1.0f / 1024.0f);
    }
    __syncthreads();
    float mu = sh_mu;
    float dx = v.x - mu, dy = v.y - mu, dz = v.z - mu, dw = v.w - mu;
    float sq = dx * dx + dy * dy + dz * dz + dw * dw;
    #pragma unroll
    for (int o = 16; o > 0; o >>= 1) sq += __shfl_xor_sync(0xffffffffu, sq, o);
    if (lane == 0) red2[wid] = sq;
    __syncthreads();
    if (tid == 0) {
        float t = 0.f;
        #pragma unroll
        for (int i = 0; i < 8; i++) t += red2[i];
        sh_rstd = rsqrtf(t * (1.0f / 1024.0f) + 1e-5f);
    }
    __syncthreads();
    float rstd = sh_rstd;
    float4 gv = *(const float4*)&g[tid * 4];
    float4 bv = *(const float4*)&bfn[tid * 4];
    float4 o;
    o.x = dx * rstd * gv.x + bv.x;
    o.y = dy * rstd * gv.y + bv.y;
    o.z = dz * rstd * gv.z + bv.z;
    o.w = dw * rstd * gv.w + bv.w;
    *(float4*)&y[r * 1024 + tid * 4] = o;
}

// ---------------------------------------------------------------------------
extern "C" void kernel_launch(void* const* d_in, const int* in_sizes, int n_in,
                              void* d_out, int out_size) {
    const float* x   = (const float*)d_in[0];
    const float* w   = (const float*)d_in[1];
    const float* lw  = (const float*)d_in[2];
    const float* lb  = (const float*)d_in[3];
    const float* lng = (const float*)d_in[4];
    const float* lnb = (const float*)d_in[5];
    float* out = (float*)d_out;

    __nv_bfloat16 *xhi, *xlo, *wthi, *wtlo, *lwhi, *lwlo, *lhi, *llo, *ohhi, *ohlo;
    float *ypre;
    cudaGetSymbolAddress((void**)&xhi, g_xhi);   cudaGetSymbolAddress((void**)&xlo, g_xlo);
    cudaGetSymbolAddress((void**)&wthi, g_wThi); cudaGetSymbolAddress((void**)&wtlo, g_wTlo);
    cudaGetSymbolAddress((void**)&lwhi, g_lwhi); cudaGetSymbolAddress((void**)&lwlo, g_lwlo);
    cudaGetSymbolAddress((void**)&lhi, g_lhi);   cudaGetSymbolAddress((void**)&llo, g_llo);
    cudaGetSymbolAddress((void**)&ohhi, g_ohhi); cudaGetSymbolAddress((void**)&ohlo, g_ohlo);
    cudaGetSymbolAddress((void**)&ypre, g_ypre);

    cudaFuncSetAttribute(gemm_mma<0>, cudaFuncAttributeMaxDynamicSharedMemorySize, GSMEM);
    cudaFuncSetAttribute(gemm_mma<1>, cudaFuncAttributeMaxDynamicSharedMemorySize, GSMEM);
    cudaFuncSetAttribute(attn_kernel, cudaFuncAttributeMaxDynamicSharedMemorySize, ASMEM);

    // input splits
    split4_kernel<<<8192, 256>>>(x, xhi, xlo, MROWS * DD / 4);
    convw_kernel<<<4096, 256>>>(w);
    split4_kernel<<<1024, 256>>>(lw, lwhi, lwlo, DD * DD / 4);

    // head projection -> logits (bf16 hi/lo, concat layout)
    gemm_mma<0><<<dim3(64, 8), 256, GSMEM>>>(xhi, xlo, wthi, wtlo,
                                             lhi, llo, nullptr, nullptr, nullptr);
    // fused attention: writes attn matrix + outh (bf16 hi/lo)
    attn_kernel<<<dim3(32, 8, 16), 256, ASMEM>>>(lhi, llo, out + Y_SIZE, ohhi, ohlo);
    // output projection + residual + bias
    gemm_mma<1><<<dim3(64, 8), 256, GSMEM>>>(ohhi, ohlo, lwhi, lwlo,
                                             nullptr, nullptr, ypre, x, lb);
    // layernorm
    ln_kernel<<<MROWS, 256>>>(out, lng, lnb);
}

// round 12
// speedup vs baseline: 1.5387x; 1.5387x over previous
#include <cuda_runtime.h>
#include <cuda_bf16.h>
#include <cstdint>
#include <math.h>

#define BB 8
#define SS 1024
#define DD 1024
#define NH 16
#define HH 64
#define MROWS (BB*SS)            // 8192
#define Y_SIZE (BB*SS*DD)        // 8388608

// ---------------------------------------------------------------------------
// Scratch (device globals; no allocations allowed)
// ---------------------------------------------------------------------------
__device__ float g_ypre[MROWS*DD];                         // pre-layernorm y
__device__ __nv_bfloat16 g_xhi[MROWS*DD], g_xlo[MROWS*DD]; // x split
__device__ __nv_bfloat16 g_wThi[DD*DD], g_wTlo[DD*DD];     // proj B: [c=n*64+h][d]
__device__ __nv_bfloat16 g_lwhi[DD*DD], g_lwlo[DD*DD];     // outproj B: [d][k]
__device__ __nv_bfloat16 g_lhi[MROWS*DD], g_llo[MROWS*DD]; // logits split [r][n*64+h]
__device__ __nv_bfloat16 g_ohhi[MROWS*DD], g_ohlo[MROWS*DD]; // attn heads out split

// ---------------------------------------------------------------------------
// mma.sync / ldmatrix / cp.async helpers (base ISA)
// ---------------------------------------------------------------------------
__device__ __forceinline__ uint32_t smem_u32(const void* p) {
    uint32_t a;
    asm("{ .reg .u64 t; cvta.to.shared.u64 t, %1; cvt.u32.u64 %0, t; }" : "=r"(a) : "l"(p));
    return a;
}

__device__ __forceinline__ void mma_bf16(float c[4],
                                         unsigned a0, unsigned a1, unsigned a2, unsigned a3,
                                         unsigned b0, unsigned b1) {
    asm volatile("mma.sync.aligned.m16n8k16.row.col.f32.bf16.bf16.f32 "
        "{%0,%1,%2,%3}, {%4,%5,%6,%7}, {%8,%9}, {%0,%1,%2,%3};"
        : "+f"(c[0]), "+f"(c[1]), "+f"(c[2]), "+f"(c[3])
        : "r"(a0), "r"(a1), "r"(a2), "r"(a3), "r"(b0), "r"(b1));
}

__device__ __forceinline__ void ldsm4(unsigned r[4], uint32_t addr) {
    asm volatile("ldmatrix.sync.aligned.m8n8.x4.shared.b16 {%0,%1,%2,%3}, [%4];"
        : "=r"(r[0]), "=r"(r[1]), "=r"(r[2]), "=r"(r[3]) : "r"(addr));
}
__device__ __forceinline__ void ldsm4t(unsigned r[4], uint32_t addr) {
    asm volatile("ldmatrix.sync.aligned.m8n8.x4.trans.shared.b16 {%0,%1,%2,%3}, [%4];"
        : "=r"(r[0]), "=r"(r[1]), "=r"(r[2]), "=r"(r[3]) : "r"(addr));
}

__device__ __forceinline__ void cp16(uint32_t dst, const void* src) {
    asm volatile("cp.async.cg.shared.global [%0], [%1], 16;" :: "r"(dst), "l"(src));
}
#define CP_COMMIT() asm volatile("cp.async.commit_group;" ::: "memory")
#define CP_WAIT1()  asm volatile("cp.async.wait_group 1;" ::: "memory")
#define CP_WAIT0()  asm volatile("cp.async.wait_group 0;" ::: "memory")

__device__ __forceinline__ unsigned prmt(unsigned a, unsigned b, unsigned sel) {
    unsigned r;
    asm("prmt.b32 %0, %1, %2, %3;" : "=r"(r) : "r"(a), "r"(b), "r"(sel));
    return r;
}

// hi/lo split of float pair -> two packed bf16x2 regs
__device__ __forceinline__ void split2(float x, float y, unsigned& h, unsigned& l) {
    __nv_bfloat16 hx = __float2bfloat16(x), hy = __float2bfloat16(y);
    __nv_bfloat162 hp(hx, hy);
    __nv_bfloat162 lp(__float2bfloat16(x - __bfloat162float(hx)),
                      __float2bfloat16(y - __bfloat162float(hy)));
    h = *(unsigned*)&hp;
    l = *(unsigned*)&lp;
}

// pack one float into (bf16hi << 16) | bf16lo
__device__ __forceinline__ unsigned packhl(float v) {
    __nv_bfloat16 h = __float2bfloat16(v);
    __nv_bfloat16 l = __float2bfloat16(v - __bfloat162float(h));
    return ((unsigned)*(unsigned short*)&h << 16) | (unsigned)*(unsigned short*)&l;
}

// ---------------------------------------------------------------------------
// Converters: fp32 -> bf16 hi/lo split
// ---------------------------------------------------------------------------
__global__ __launch_bounds__(256) void split4_kernel(const float* __restrict__ s,
                                                     __nv_bfloat16* __restrict__ hi,
                                                     __nv_bfloat16* __restrict__ lo, int n4) {
    int i = blockIdx.x * 256 + threadIdx.x;
    if (i >= n4) return;
    float4 v = ((const float4*)s)[i];
    unsigned h0, l0, h1, l1;
    split2(v.x, v.y, h0, l0);
    split2(v.z, v.w, h1, l1);
    ((unsigned*)hi)[i*2]   = h0;
    ((unsigned*)hi)[i*2+1] = h1;
    ((unsigned*)lo)[i*2]   = l0;
    ((unsigned*)lo)[i*2+1] = l1;
}

// w [NH][DD][HH] -> wT[c=n*64+h][d], split hi/lo
__global__ __launch_bounds__(256) void convw_kernel(const float* __restrict__ w) {
    int o = blockIdx.x * 256 + threadIdx.x;
    int c = o >> 10, d = o & 1023;
    int n = c >> 6, h = c & 63;
    float v = __ldg(&w[(n * 1024 + d) * 64 + h]);
    __nv_bfloat16 hv = __float2bfloat16(v);
    g_wThi[o] = hv;
    g_wTlo[o] = __float2bfloat16(v - __bfloat162float(hv));
}

// ---------------------------------------------------------------------------
// Dense GEMM via mma.sync (R5-proven config): synchronous loads, K chunk 64,
// single 73.7KB buffer -> 2 CTAs/SM. Block 128x128, 8 warps (2m x 4n),
// warp tile 64x32. Smem row stride 72 bf16 (144B).
// EPI 0: C as bf16 hi/lo. EPI 1: fp32 C = acc + RX + BIAS.
// ---------------------------------------------------------------------------
#define GA_H 0
#define GA_L 18432
#define GB_H 36864
#define GB_L 55296
#define GSMEM 73728

template<int EPI>
__global__ __launch_bounds__(256) void gemm_mma(
    const __nv_bfloat16* __restrict__ Ah, const __nv_bfloat16* __restrict__ Al,
    const __nv_bfloat16* __restrict__ Bh, const __nv_bfloat16* __restrict__ Bl,
    __nv_bfloat16* __restrict__ Chi, __nv_bfloat16* __restrict__ Clo,
    float* __restrict__ Cf, const float* __restrict__ RX, const float* __restrict__ BIAS)
{
    extern __shared__ char sm[];
    const uint32_t sb = smem_u32(sm);
    const int tid = threadIdx.x, w = tid >> 5, lane = tid & 31;
    const int wm = w >> 2, wn = w & 3;
    const int r0 = blockIdx.x * 128, c0 = blockIdx.y * 128;

    float acc[4][4][4] = {};        // [mi][n8 group][4]
    const int lrow = tid >> 3, lc8 = tid & 7;

    #pragma unroll 1
    for (int k0 = 0; k0 < 1024; k0 += 64) {
        __syncthreads();
        #pragma unroll
        for (int it = 0; it < 4; it++) {
            int rr = lrow + it * 32;
            size_t goA = (size_t)(r0 + rr) * 1024 + k0 + lc8 * 8;
            size_t goB = (size_t)(c0 + rr) * 1024 + k0 + lc8 * 8;
            uint32_t so = (rr * 72 + lc8 * 8) * 2;
            *(uint4*)(sm + GA_H + so) = *(const uint4*)(Ah + goA);
            *(uint4*)(sm + GA_L + so) = *(const uint4*)(Al + goA);
            *(uint4*)(sm + GB_H + so) = *(const uint4*)(Bh + goB);
            *(uint4*)(sm + GB_L + so) = *(const uint4*)(Bl + goB);
        }
        __syncthreads();
        #pragma unroll
        for (int ks = 0; ks < 4; ks++) {
            unsigned ah[4][4], al[4][4], bh[2][4], bl[2][4];
            uint32_t abase = sb + ((wm * 64 + (lane & 15)) * 72 + ks * 16 + (lane >> 4) * 8) * 2;
            #pragma unroll
            for (int mi = 0; mi < 4; mi++) {
                ldsm4(ah[mi], abase + GA_H + mi * 2304);
                ldsm4(al[mi], abase + GA_L + mi * 2304);
            }
            uint32_t bbase = sb + ((wn * 32 + (lane & 15)) * 72 + ks * 16 + (lane >> 4) * 8) * 2;
            #pragma unroll
            for (int ni = 0; ni < 2; ni++) {
                ldsm4(bh[ni], bbase + GB_H + ni * 2304);
                ldsm4(bl[ni], bbase + GB_L + ni * 2304);
            }
            #pragma unroll
            for (int mi = 0; mi < 4; mi++)
                #pragma unroll
                for (int ni = 0; ni < 2; ni++) {
                    mma_bf16(acc[mi][2*ni],   ah[mi][0],ah[mi][1],ah[mi][2],ah[mi][3], bh[ni][0], bh[ni][2]);
                    mma_bf16(acc[mi][2*ni+1], ah[mi][0],ah[mi][1],ah[mi][2],ah[mi][3], bh[ni][1], bh[ni][3]);
                    mma_bf16(acc[mi][2*ni],   ah[mi][0],ah[mi][1],ah[mi][2],ah[mi][3], bl[ni][0], bl[ni][2]);
                    mma_bf16(acc[mi][2*ni+1], ah[mi][0],ah[mi][1],ah[mi][2],ah[mi][3], bl[ni][1], bl[ni][3]);
                    mma_bf16(acc[mi][2*ni],   al[mi][0],al[mi][1],al[mi][2],al[mi][3], bh[ni][0], bh[ni][2]);
                    mma_bf16(acc[mi][2*ni+1], al[mi][0],al[mi][1],al[mi][2],al[mi][3], bh[ni][1], bh[ni][3]);
                }
        }
    }

    // epilogue
    #pragma unroll
    for (int mi = 0; mi < 4; mi++) {
        int rr = r0 + wm * 64 + mi * 16 + (lane >> 2);
        #pragma unroll
        for (int nj = 0; nj < 4; nj++) {
            int cc = c0 + wn * 32 + nj * 8 + 2 * (lane & 3);
            if (EPI == 0) {
                #pragma unroll
                for (int half = 0; half < 2; half++) {
                    unsigned h, l;
                    split2(acc[mi][nj][half*2], acc[mi][nj][half*2+1], h, l);
                    size_t go = (size_t)(rr + half*8) * 1024 + cc;
                    *(unsigned*)(Chi + go) = h;
                    *(unsigned*)(Clo + go) = l;
                }
            } else {
                #pragma unroll
                for (int half = 0; half < 2; half++) {
                    size_t go = (size_t)(rr + half*8) * 1024 + cc;
                    float2 xv = *(const float2*)(RX + go);
                    float2 bv = *(const float2*)(BIAS + cc);
                    float2 o;
                    o.x = acc[mi][nj][half*2]   + xv.x + bv.x;
                    o.y = acc[mi][nj][half*2+1] + xv.y + bv.y;
                    *(float2*)(Cf + go) = o;
                }
            }
        }
    }
}

// ---------------------------------------------------------------------------
// Fused attention per (n, b, 32-row tile), 256 threads (R7 base), plus:
//  - Q fragments hoisted into registers (loaded once, reused all 8 key tiles)
//  - scores packed in-place to (bf16hi<<16 | bf16lo) after the attn write;
//    PV extracts fragments with PRMT (no per-use split2 chains)
// ---------------------------------------------------------------------------
#define SCSTR 1032
#define A_QH  132096                    // 32*72*2 = 4608
#define A_QL  136704
#define A_KB  141312                    // 2 bufs x (KH 18432 + KL 18432)
#define A_KBUF 36864
#define ASMEM (A_KB + 2*A_KBUF)         // 215040

__global__ __launch_bounds__(256, 1) void attn_kernel(
    const __nv_bfloat16* __restrict__ LHI, const __nv_bfloat16* __restrict__ LLO,
    float* __restrict__ out_attn,
    __nv_bfloat16* __restrict__ OHI, __nv_bfloat16* __restrict__ OLO)
{
    extern __shared__ char sm[];
    const uint32_t sb = smem_u32(sm);
    float* scores = (float*)sm;
    unsigned* pscore = (unsigned*)sm;
    __shared__ float rs[32];

    const int rt = blockIdx.x, b = blockIdx.y, n = blockIdx.z;
    const int s0 = rt * 32;
    const int tid = threadIdx.x, w = tid >> 5, lane = tid & 31;
    const size_t rowbase = (size_t)b * 1024;
    const int colbase = n * 64;
    const int lrow = tid >> 3, lc8 = tid & 7;

    auto load_kv = [&](int buf, int tile) {
        const uint32_t bh = sb + A_KB + buf * A_KBUF;
        #pragma unroll
        for (int it = 0; it < 4; it++) {
            int row = lrow + it * 32;
            size_t go = (rowbase + tile * 128 + row) * 1024 + colbase + lc8 * 8;
            uint32_t so = (row * 72 + lc8 * 8) * 2;
            cp16(bh + so,         LHI + go);
            cp16(bh + 18432 + so, LLO + go);
        }
    };

    // load Q tile (32 x 64) hi/lo (direct) + prefetch K tile 0
    load_kv(0, 0);
    CP_COMMIT();
    {
        int row = tid >> 3, c8 = tid & 7;
        uint32_t so = (row * 72 + c8 * 8) * 2;
        size_t go = (rowbase + s0 + row) * 1024 + colbase + c8 * 8;
        *(uint4*)(sm + A_QH + so) = *(const uint4*)(LHI + go);
        *(uint4*)(sm + A_QL + so) = *(const uint4*)(LLO + go);
    }
    __syncthreads();

    // hoist Q fragments to registers (kt-invariant)
    unsigned qh[4][2][4], ql[4][2][4];
    #pragma unroll
    for (int ks = 0; ks < 4; ks++) {
        uint32_t qb = sb + (((lane & 15)) * 72 + ks * 16 + (lane >> 4) * 8) * 2;
        #pragma unroll
        for (int mi = 0; mi < 2; mi++) {
            ldsm4(qh[ks][mi], qb + A_QH + mi * 2304);
            ldsm4(ql[ks][mi], qb + A_QL + mi * 2304);
        }
    }

    const float scale = 0.125f;
    // ---- QK^T: 8 key tiles of 128, double-buffered ----
    #pragma unroll 1
    for (int kt = 0; kt < 8; kt++) {
        if (kt < 7) {
            load_kv((kt + 1) & 1, kt + 1);
            CP_COMMIT();
            CP_WAIT1();
        } else {
            CP_WAIT0();
        }
        __syncthreads();
        const uint32_t kbase = sb + A_KB + (kt & 1) * A_KBUF;

        float sqk[2][2][4] = {};
        #pragma unroll
        for (int ks = 0; ks < 4; ks++) {
            unsigned kh[4], kl[4];
            uint32_t kb = kbase + ((w * 16 + (lane & 15)) * 72 + ks * 16 + (lane >> 4) * 8) * 2;
            ldsm4(kh, kb);                    ldsm4(kl, kb + 18432);
            #pragma unroll
            for (int mi = 0; mi < 2; mi++) {
                mma_bf16(sqk[mi][0], qh[ks][mi][0],qh[ks][mi][1],qh[ks][mi][2],qh[ks][mi][3], kh[0], kh[2]);
                mma_bf16(sqk[mi][1], qh[ks][mi][0],qh[ks][mi][1],qh[ks][mi][2],qh[ks][mi][3], kh[1], kh[3]);
                mma_bf16(sqk[mi][0], qh[ks][mi][0],qh[ks][mi][1],qh[ks][mi][2],qh[ks][mi][3], kl[0], kl[2]);
                mma_bf16(sqk[mi][1], qh[ks][mi][0],qh[ks][mi][1],qh[ks][mi][2],qh[ks][mi][3], kl[1], kl[3]);
                mma_bf16(sqk[mi][0], ql[ks][mi][0],ql[ks][mi][1],ql[ks][mi][2],ql[ks][mi][3], kh[0], kh[2]);
                mma_bf16(sqk[mi][1], ql[ks][mi][0],ql[ks][mi][1],ql[ks][mi][2],ql[ks][mi][3], kh[1], kh[3]);
            }
        }
        #pragma unroll
        for (int mi = 0; mi < 2; mi++) {
            int sr = mi * 16 + (lane >> 2);
            #pragma unroll
            for (int nj = 0; nj < 2; nj++) {
                int cc = kt * 128 + w * 16 + nj * 8 + 2 * (lane & 3);
                *(float2*)&scores[sr * SCSTR + cc] =
                    make_float2(sqk[mi][nj][0] * scale, sqk[mi][nj][1] * scale);
                *(float2*)&scores[(sr + 8) * SCSTR + cc] =
                    make_float2(sqk[mi][nj][2] * scale, sqk[mi][nj][3] * scale);
            }
        }
        __syncthreads();
    }

    // ---- softmax (fp32 exact): row = tid/8, stride-8 conflict-free scan ----
    {
        const int row = tid >> 3, c = tid & 7;
        float* srow = scores + row * SCSTR;
        float m = -1e30f;
        #pragma unroll 8
        for (int i = 0; i < 128; i++) m = fmaxf(m, srow[c + 8 * i]);
        m = fmaxf(m, __shfl_xor_sync(0xffffffffu, m, 1));
        m = fmaxf(m, __shfl_xor_sync(0xffffffffu, m, 2));
        m = fmaxf(m, __shfl_xor_sync(0xffffffffu, m, 4));
        float sum = 0.f;
        #pragma unroll 8
        for (int i = 0; i < 128; i++) {
            float e = __expf(srow[c + 8 * i] - m);
            srow[c + 8 * i] = e;
            sum += e;
        }
        sum += __shfl_xor_sync(0xffffffffu, sum, 1);
        sum += __shfl_xor_sync(0xffffffffu, sum, 2);
        sum += __shfl_xor_sync(0xffffffffu, sum, 4);
        if (c == 0) rs[row] = 1.0f / sum;
    }
    __syncthreads();

    // prefetch V tile 0 (overlaps attn write + pack below)
    load_kv(0, 0);
    CP_COMMIT();

    // ---- write normalized attention ----
    {
        float* ap = out_attn + ((size_t)(n * BB + b)) * SS * SS + (size_t)s0 * SS;
        #pragma unroll
        for (int it = 0; it < 32; it++) {
            int idx = tid + it * 256;
            int r = idx >> 8;
            int c4 = (idx & 255) << 2;
            float4 v = *(const float4*)&scores[r * SCSTR + c4];
            float iv = rs[r];
            v.x *= iv; v.y *= iv; v.z *= iv; v.w *= iv;
            *(float4*)&ap[(size_t)r * SS + c4] = v;
        }
    }
    __syncthreads();

    // ---- pack scores in place: fp32 -> (bf16hi<<16)|bf16lo ----
    {
        #pragma unroll
        for (int it = 0; it < 32; it++) {
            int idx = tid + it * 256;
            int r = idx >> 8;
            int c4 = (idx & 255) << 2;
            float4 v = *(const float4*)&scores[r * SCSTR + c4];
            uint4 p;
            p.x = packhl(v.x); p.y = packhl(v.y);
            p.z = packhl(v.z); p.w = packhl(v.w);
            *(uint4*)&pscore[r * SCSTR + c4] = p;
        }
    }

    // ---- P @ V: warps 2m x 4n (16q x 16h each); P from packed scores via
    //      PRMT extraction; V cp.async double-buffered ----
    const int wm = w >> 2, wn = w & 3;
    float pacc[2][4] = {};
    const int qr = wm * 16 + (lane >> 2);
    const int kcl = (lane & 3) * 2;
    #pragma unroll 1
    for (int jt = 0; jt < 8; jt++) {
        if (jt < 7) {
            load_kv((jt + 1) & 1, jt + 1);
            CP_COMMIT();
            CP_WAIT1();
        } else {
            CP_WAIT0();
        }
        __syncthreads();           // also makes the pack visible on jt==0
        const uint32_t vbase = sb + A_KB + (jt & 1) * A_KBUF;

        #pragma unroll
        for (int ks = 0; ks < 8; ks++) {
            const int kc = jt * 128 + ks * 16 + kcl;
            uint2 u00 = *(const uint2*)&pscore[qr * SCSTR + kc];
            uint2 u10 = *(const uint2*)&pscore[(qr + 8) * SCSTR + kc];
            uint2 u01 = *(const uint2*)&pscore[qr * SCSTR + kc + 8];
            uint2 u11 = *(const uint2*)&pscore[(qr + 8) * SCSTR + kc + 8];
            unsigned ph4[4], pl4[4];
            ph4[0] = prmt(u00.x, u00.y, 0x7632); pl4[0] = prmt(u00.x, u00.y, 0x5410);
            ph4[1] = prmt(u10.x, u10.y, 0x7632); pl4[1] = prmt(u10.x, u10.y, 0x5410);
            ph4[2] = prmt(u01.x, u01.y, 0x7632); pl4[2] = prmt(u01.x, u01.y, 0x5410);
            ph4[3] = prmt(u11.x, u11.y, 0x7632); pl4[3] = prmt(u11.x, u11.y, 0x5410);

            unsigned vh[4], vl[4];
            uint32_t vb = vbase + ((ks * 16 + (lane & 15)) * 72 + wn * 16 + (lane >> 4) * 8) * 2;
            ldsm4t(vh, vb);
            ldsm4t(vl, vb + 18432);

            mma_bf16(pacc[0], ph4[0],ph4[1],ph4[2],ph4[3], vh[0], vh[1]);
            mma_bf16(pacc[1], ph4[0],ph4[1],ph4[2],ph4[3], vh[2], vh[3]);
            mma_bf16(pacc[0], ph4[0],ph4[1],ph4[2],ph4[3], vl[0], vl[1]);
            mma_bf16(pacc[1], ph4[0],ph4[1],ph4[2],ph4[3], vl[2], vl[3]);
            mma_bf16(pacc[0], pl4[0],pl4[1],pl4[2],pl4[3], vh[0], vh[1]);
            mma_bf16(pacc[1], pl4[0],pl4[1],pl4[2],pl4[3], vh[2], vh[3]);
        }
        __syncthreads();
    }

    // ---- epilogue: scale by 1/rowsum, write outh bf16 hi/lo ----
    {
        float iv0 = rs[qr], iv1 = rs[qr + 8];
        #pragma unroll
        for (int nj = 0; nj < 2; nj++) {
            int cc = colbase + wn * 16 + nj * 8 + 2 * (lane & 3);
            size_t go = (rowbase + s0 + qr) * 1024 + cc;
            unsigned h0, l0, h1, l1;
            split2(pacc[nj][0] * iv0, pacc[nj][1] * iv0, h0, l0);
            split2(pacc[nj][2] * iv1, pacc[nj][3] * iv1, h1, l1);
            *(unsigned*)(OHI + go) = h0;
            *(unsigned*)(OLO + go) = l0;
            *(unsigned*)(OHI + go + 8 * 1024) = h1;
            *(unsigned*)(OLO + go + 8 * 1024) = l1;
        }
    }
}

// ---------------------------------------------------------------------------
// Layernorm per row of 1024
// ---------------------------------------------------------------------------
__global__ __launch_bounds__(256) void ln_kernel(float* __restrict__ y,
                                                 const float* __restrict__ g,
                                                 const float* __restrict__ bfn) {
    const int r = blockIdx.x;
    const int tid = threadIdx.x;
    const int lane = tid & 31, wid = tid >> 5;
    __shared__ float red1[8];
    __shared__ float red2[8];
    __shared__ float sh_mu, sh_rstd;

    float4 v = *(const float4*)&g_ypre[r * 1024 + tid * 4];
    float s = v.x + v.y + v.z + v.w;
    #pragma unroll
    for (int o = 16; o > 0; o >>= 1) s += __shfl_xor_sync(0xffffffffu, s, o);
    if (lane == 0) red1[wid] = s;
    __syncthreads();
    if (tid == 0) {
        float t = 0.f;
        #pragma unroll
        for (int i = 0; i < 8; i++) t += red1[i];
        sh_mu = t * (1.0f / 1024.0f);
    }
    __syncthreads();
    float mu = sh_mu;
    float dx = v.x - mu, dy = v.y - mu, dz = v.z - mu, dw = v.w - mu;
    float sq = dx * dx + dy * dy + dz * dz + dw * dw;
    #pragma unroll
    for (int o = 16; o > 0; o >>= 1) sq += __shfl_xor_sync(0xffffffffu, sq, o);
    if (lane == 0) red2[wid] = sq;
    __syncthreads();
    if (tid == 0) {
        float t = 0.f;
        #pragma unroll
        for (int i = 0; i < 8; i++) t += red2[i];
        sh_rstd = rsqrtf(t * (1.0f / 1024.0f) + 1e-5f);
    }
    __syncthreads();
    float rstd = sh_rstd;
    float4 gv = *(const float4*)&g[tid * 4];
    float4 bv = *(const float4*)&bfn[tid * 4];
    float4 o;
    o.x = dx * rstd * gv.x + bv.x;
    o.y = dy * rstd * gv.y + bv.y;
    o.z = dz * rstd * gv.z + bv.z;
    o.w = dw * rstd * gv.w + bv.w;
    *(float4*)&y[r * 1024 + tid * 4] = o;
}

// ---------------------------------------------------------------------------
extern "C" void kernel_launch(void* const* d_in, const int* in_sizes, int n_in,
                              void* d_out, int out_size) {
    const float* x   = (const float*)d_in[0];
    const float* w   = (const float*)d_in[1];
    const float* lw  = (const float*)d_in[2];
    const float* lb  = (const float*)d_in[3];
    const float* lng = (const float*)d_in[4];
    const float* lnb = (const float*)d_in[5];
    float* out = (float*)d_out;

    __nv_bfloat16 *xhi, *xlo, *wthi, *wtlo, *lwhi, *lwlo, *lhi, *llo, *ohhi, *ohlo;
    float *ypre;
    cudaGetSymbolAddress((void**)&xhi, g_xhi);   cudaGetSymbolAddress((void**)&xlo, g_xlo);
    cudaGetSymbolAddress((void**)&wthi, g_wThi); cudaGetSymbolAddress((void**)&wtlo, g_wTlo);
    cudaGetSymbolAddress((void**)&lwhi, g_lwhi); cudaGetSymbolAddress((void**)&lwlo, g_lwlo);
    cudaGetSymbolAddress((void**)&lhi, g_lhi);   cudaGetSymbolAddress((void**)&llo, g_llo);
    cudaGetSymbolAddress((void**)&ohhi, g_ohhi); cudaGetSymbolAddress((void**)&ohlo, g_ohlo);
    cudaGetSymbolAddress((void**)&ypre, g_ypre);

    cudaFuncSetAttribute(gemm_mma<0>, cudaFuncAttributeMaxDynamicSharedMemorySize, GSMEM);
    cudaFuncSetAttribute(gemm_mma<1>, cudaFuncAttributeMaxDynamicSharedMemorySize, GSMEM);
    cudaFuncSetAttribute(attn_kernel, cudaFuncAttributeMaxDynamicSharedMemorySize, ASMEM);

    // input splits
    split4_kernel<<<8192, 256>>>(x, xhi, xlo, MROWS * DD / 4);
    convw_kernel<<<4096, 256>>>(w);
    split4_kernel<<<1024, 256>>>(lw, lwhi, lwlo, DD * DD / 4);

    // head projection -> logits (bf16 hi/lo, concat layout)
    gemm_mma<0><<<dim3(64, 8), 256, GSMEM>>>(xhi, xlo, wthi, wtlo,
                                             lhi, llo, nullptr, nullptr, nullptr);
    // fused attention: writes attn matrix + outh (bf16 hi/lo)
    attn_kernel<<<dim3(32, 8, 16), 256, ASMEM>>>(lhi, llo, out + Y_SIZE, ohhi, ohlo);
    // output projection + residual + bias
    gemm_mma<1><<<dim3(64, 8), 256, GSMEM>>>(ohhi, ohlo, lwhi, lwlo,
                                             nullptr, nullptr, ypre, x, lb);
    // layernorm
    ln_kernel<<<MROWS, 256>>>(out, lng, lnb);
}

// round 13
// speedup vs baseline: 1.7521x; 1.1387x over previous
#include <cuda_runtime.h>
#include <cuda_bf16.h>
#include <cstdint>
#include <math.h>

#define BB 8
#define SS 1024
#define DD 1024
#define NH 16
#define HH 64
#define MROWS (BB*SS)            // 8192
#define Y_SIZE (BB*SS*DD)        // 8388608

// ---------------------------------------------------------------------------
// Scratch (device globals; no allocations allowed)
// ---------------------------------------------------------------------------
__device__ float g_ypre[MROWS*DD];                         // pre-layernorm y
__device__ __nv_bfloat16 g_xhi[MROWS*DD], g_xlo[MROWS*DD]; // x split
__device__ __nv_bfloat16 g_wThi[DD*DD], g_wTlo[DD*DD];     // proj B: [c=n*64+h][d]
__device__ __nv_bfloat16 g_lwhi[DD*DD], g_lwlo[DD*DD];     // outproj B: [d][k]
__device__ __nv_bfloat16 g_lhi[MROWS*DD], g_llo[MROWS*DD]; // logits split [r][n*64+h]
__device__ __nv_bfloat16 g_ohhi[MROWS*DD], g_ohlo[MROWS*DD]; // attn heads out split

// ---------------------------------------------------------------------------
// mma.sync / ldmatrix / cp.async helpers (base ISA)
// ---------------------------------------------------------------------------
__device__ __forceinline__ uint32_t smem_u32(const void* p) {
    uint32_t a;
    asm("{ .reg .u64 t; cvta.to.shared.u64 t, %1; cvt.u32.u64 %0, t; }" : "=r"(a) : "l"(p));
    return a;
}

__device__ __forceinline__ void mma_bf16(float c[4],
                                         unsigned a0, unsigned a1, unsigned a2, unsigned a3,
                                         unsigned b0, unsigned b1) {
    asm volatile("mma.sync.aligned.m16n8k16.row.col.f32.bf16.bf16.f32 "
        "{%0,%1,%2,%3}, {%4,%5,%6,%7}, {%8,%9}, {%0,%1,%2,%3};"
        : "+f"(c[0]), "+f"(c[1]), "+f"(c[2]), "+f"(c[3])
        : "r"(a0), "r"(a1), "r"(a2), "r"(a3), "r"(b0), "r"(b1));
}

__device__ __forceinline__ void ldsm4(unsigned r[4], uint32_t addr) {
    asm volatile("ldmatrix.sync.aligned.m8n8.x4.shared.b16 {%0,%1,%2,%3}, [%4];"
        : "=r"(r[0]), "=r"(r[1]), "=r"(r[2]), "=r"(r[3]) : "r"(addr));
}
__device__ __forceinline__ void ldsm4t(unsigned r[4], uint32_t addr) {
    asm volatile("ldmatrix.sync.aligned.m8n8.x4.trans.shared.b16 {%0,%1,%2,%3}, [%4];"
        : "=r"(r[0]), "=r"(r[1]), "=r"(r[2]), "=r"(r[3]) : "r"(addr));
}

__device__ __forceinline__ void cp16(uint32_t dst, const void* src) {
    asm volatile("cp.async.cg.shared.global [%0], [%1], 16;" :: "r"(dst), "l"(src));
}
#define CP_COMMIT() asm volatile("cp.async.commit_group;" ::: "memory")
#define CP_WAIT1()  asm volatile("cp.async.wait_group 1;" ::: "memory")
#define CP_WAIT0()  asm volatile("cp.async.wait_group 0;" ::: "memory")

__device__ __forceinline__ unsigned prmt(unsigned a, unsigned b, unsigned sel) {
    unsigned r;
    asm("prmt.b32 %0, %1, %2, %3;" : "=r"(r) : "r"(a), "r"(b), "r"(sel));
    return r;
}

// hi/lo split of float pair -> two packed bf16x2 regs
__device__ __forceinline__ void split2(float x, float y, unsigned& h, unsigned& l) {
    __nv_bfloat16 hx = __float2bfloat16(x), hy = __float2bfloat16(y);
    __nv_bfloat162 hp(hx, hy);
    __nv_bfloat162 lp(__float2bfloat16(x - __bfloat162float(hx)),
                      __float2bfloat16(y - __bfloat162float(hy)));
    h = *(unsigned*)&hp;
    l = *(unsigned*)&lp;
}

// pack one float into (bf16hi << 16) | bf16lo
__device__ __forceinline__ unsigned packhl(float v) {
    __nv_bfloat16 h = __float2bfloat16(v);
    __nv_bfloat16 l = __float2bfloat16(v - __bfloat162float(h));
    return ((unsigned)*(unsigned short*)&h << 16) | (unsigned)*(unsigned short*)&l;
}
__device__ __forceinline__ float unpack_sum(unsigned u) {
    return __uint_as_float(u & 0xFFFF0000u) + __uint_as_float(u << 16);
}

// ---------------------------------------------------------------------------
// Converters: fp32 -> bf16 hi/lo split
// ---------------------------------------------------------------------------
__global__ __launch_bounds__(256) void split4_kernel(const float* __restrict__ s,
                                                     __nv_bfloat16* __restrict__ hi,
                                                     __nv_bfloat16* __restrict__ lo, int n4) {
    int i = blockIdx.x * 256 + threadIdx.x;
    if (i >= n4) return;
    float4 v = ((const float4*)s)[i];
    unsigned h0, l0, h1, l1;
    split2(v.x, v.y, h0, l0);
    split2(v.z, v.w, h1, l1);
    ((unsigned*)hi)[i*2]   = h0;
    ((unsigned*)hi)[i*2+1] = h1;
    ((unsigned*)lo)[i*2]   = l0;
    ((unsigned*)lo)[i*2+1] = l1;
}

// w [NH][DD][HH] -> wT[c=n*64+h][d], split hi/lo
__global__ __launch_bounds__(256) void convw_kernel(const float* __restrict__ w) {
    int o = blockIdx.x * 256 + threadIdx.x;
    int c = o >> 10, d = o & 1023;
    int n = c >> 6, h = c & 63;
    float v = __ldg(&w[(n * 1024 + d) * 64 + h]);
    __nv_bfloat16 hv = __float2bfloat16(v);
    g_wThi[o] = hv;
    g_wTlo[o] = __float2bfloat16(v - __bfloat162float(hv));
}

// ---------------------------------------------------------------------------
// Dense GEMM via mma.sync (R5-proven config): synchronous loads, K chunk 64,
// single 73.7KB buffer -> 2 CTAs/SM. Block 128x128, 8 warps (2m x 4n),
// warp tile 64x32. Smem row stride 72 bf16 (144B).
// EPI 0: C as bf16 hi/lo. EPI 1: fp32 C = acc + RX + BIAS.
// ---------------------------------------------------------------------------
#define GA_H 0
#define GA_L 18432
#define GB_H 36864
#define GB_L 55296
#define GSMEM 73728

template<int EPI>
__global__ __launch_bounds__(256) void gemm_mma(
    const __nv_bfloat16* __restrict__ Ah, const __nv_bfloat16* __restrict__ Al,
    const __nv_bfloat16* __restrict__ Bh, const __nv_bfloat16* __restrict__ Bl,
    __nv_bfloat16* __restrict__ Chi, __nv_bfloat16* __restrict__ Clo,
    float* __restrict__ Cf, const float* __restrict__ RX, const float* __restrict__ BIAS)
{
    extern __shared__ char sm[];
    const uint32_t sb = smem_u32(sm);
    const int tid = threadIdx.x, w = tid >> 5, lane = tid & 31;
    const int wm = w >> 2, wn = w & 3;
    const int r0 = blockIdx.x * 128, c0 = blockIdx.y * 128;

    float acc[4][4][4] = {};        // [mi][n8 group][4]
    const int lrow = tid >> 3, lc8 = tid & 7;

    #pragma unroll 1
    for (int k0 = 0; k0 < 1024; k0 += 64) {
        __syncthreads();
        #pragma unroll
        for (int it = 0; it < 4; it++) {
            int rr = lrow + it * 32;
            size_t goA = (size_t)(r0 + rr) * 1024 + k0 + lc8 * 8;
            size_t goB = (size_t)(c0 + rr) * 1024 + k0 + lc8 * 8;
            uint32_t so = (rr * 72 + lc8 * 8) * 2;
            *(uint4*)(sm + GA_H + so) = *(const uint4*)(Ah + goA);
            *(uint4*)(sm + GA_L + so) = *(const uint4*)(Al + goA);
            *(uint4*)(sm + GB_H + so) = *(const uint4*)(Bh + goB);
            *(uint4*)(sm + GB_L + so) = *(const uint4*)(Bl + goB);
        }
        __syncthreads();
        #pragma unroll
        for (int ks = 0; ks < 4; ks++) {
            unsigned ah[4][4], al[4][4], bh[2][4], bl[2][4];
            uint32_t abase = sb + ((wm * 64 + (lane & 15)) * 72 + ks * 16 + (lane >> 4) * 8) * 2;
            #pragma unroll
            for (int mi = 0; mi < 4; mi++) {
                ldsm4(ah[mi], abase + GA_H + mi * 2304);
                ldsm4(al[mi], abase + GA_L + mi * 2304);
            }
            uint32_t bbase = sb + ((wn * 32 + (lane & 15)) * 72 + ks * 16 + (lane >> 4) * 8) * 2;
            #pragma unroll
            for (int ni = 0; ni < 2; ni++) {
                ldsm4(bh[ni], bbase + GB_H + ni * 2304);
                ldsm4(bl[ni], bbase + GB_L + ni * 2304);
            }
            #pragma unroll
            for (int mi = 0; mi < 4; mi++)
                #pragma unroll
                for (int ni = 0; ni < 2; ni++) {
                    mma_bf16(acc[mi][2*ni],   ah[mi][0],ah[mi][1],ah[mi][2],ah[mi][3], bh[ni][0], bh[ni][2]);
                    mma_bf16(acc[mi][2*ni+1], ah[mi][0],ah[mi][1],ah[mi][2],ah[mi][3], bh[ni][1], bh[ni][3]);
                    mma_bf16(acc[mi][2*ni],   ah[mi][0],ah[mi][1],ah[mi][2],ah[mi][3], bl[ni][0], bl[ni][2]);
                    mma_bf16(acc[mi][2*ni+1], ah[mi][0],ah[mi][1],ah[mi][2],ah[mi][3], bl[ni][1], bl[ni][3]);
                    mma_bf16(acc[mi][2*ni],   al[mi][0],al[mi][1],al[mi][2],al[mi][3], bh[ni][0], bh[ni][2]);
                    mma_bf16(acc[mi][2*ni+1], al[mi][0],al[mi][1],al[mi][2],al[mi][3], bh[ni][1], bh[ni][3]);
                }
        }
    }

    // epilogue
    #pragma unroll
    for (int mi = 0; mi < 4; mi++) {
        int rr = r0 + wm * 64 + mi * 16 + (lane >> 2);
        #pragma unroll
        for (int nj = 0; nj < 4; nj++) {
            int cc = c0 + wn * 32 + nj * 8 + 2 * (lane & 3);
            if (EPI == 0) {
                #pragma unroll
                for (int half = 0; half < 2; half++) {
                    unsigned h, l;
                    split2(acc[mi][nj][half*2], acc[mi][nj][half*2+1], h, l);
                    size_t go = (size_t)(rr + half*8) * 1024 + cc;
                    *(unsigned*)(Chi + go) = h;
                    *(unsigned*)(Clo + go) = l;
                }
            } else {
                #pragma unroll
                for (int half = 0; half < 2; half++) {
                    size_t go = (size_t)(rr + half*8) * 1024 + cc;
                    float2 xv = *(const float2*)(RX + go);
                    float2 bv = *(const float2*)(BIAS + cc);
                    float2 o;
                    o.x = acc[mi][nj][half*2]   + xv.x + bv.x;
                    o.y = acc[mi][nj][half*2+1] + xv.y + bv.y;
                    *(float2*)(Cf + go) = o;
                }
            }
        }
    }
}

// ---------------------------------------------------------------------------
// Single-pass fused attention per (n, b, 32-row tile), 256 threads.
// Per key tile: QK^T (regs) -> exp in regs (no max-sub; scores bounded) ->
// pack P hi/lo in regs -> P@V on the SAME smem tile (V == K == logits)
// + store packed P to smem for the attn-matrix write. Row sums and out
// fragments accumulate in registers; cross-warp out reduction via the freed
// K-buffer at the end. K tiles loaded from L2 exactly once (was twice).
// ---------------------------------------------------------------------------
#define SCSTR 1032
#define A_QH  132096                    // pscore: 32*1032*4 = 132096
#define A_QL  136704
#define A_KB  141312                    // 2 bufs x (KH 18432 + KL 18432)
#define A_KBUF 36864
#define ASMEM (A_KB + 2*A_KBUF)         // 215040

__global__ __launch_bounds__(256, 1) void attn_kernel(
    const __nv_bfloat16* __restrict__ LHI, const __nv_bfloat16* __restrict__ LLO,
    float* __restrict__ out_attn,
    __nv_bfloat16* __restrict__ OHI, __nv_bfloat16* __restrict__ OLO)
{
    extern __shared__ char sm[];
    const uint32_t sb = smem_u32(sm);
    unsigned* pscore = (unsigned*)sm;
    __shared__ float rs[32];
    __shared__ float rsw[8][32];

    const int rt = blockIdx.x, b = blockIdx.y, n = blockIdx.z;
    const int s0 = rt * 32;
    const int tid = threadIdx.x, w = tid >> 5, lane = tid & 31;
    const size_t rowbase = (size_t)b * 1024;
    const int colbase = n * 64;
    const int lrow = tid >> 3, lc8 = tid & 7;

    auto load_kv = [&](int buf, int tile) {
        const uint32_t bh = sb + A_KB + buf * A_KBUF;
        #pragma unroll
        for (int it = 0; it < 4; it++) {
            int row = lrow + it * 32;
            size_t go = (rowbase + tile * 128 + row) * 1024 + colbase + lc8 * 8;
            uint32_t so = (row * 72 + lc8 * 8) * 2;
            cp16(bh + so,         LHI + go);
            cp16(bh + 18432 + so, LLO + go);
        }
    };

    // load Q tile (32 x 64) hi/lo (direct) + prefetch K tile 0
    load_kv(0, 0);
    CP_COMMIT();
    {
        int row = tid >> 3, c8 = tid & 7;
        uint32_t so = (row * 72 + c8 * 8) * 2;
        size_t go = (rowbase + s0 + row) * 1024 + colbase + c8 * 8;
        *(uint4*)(sm + A_QH + so) = *(const uint4*)(LHI + go);
        *(uint4*)(sm + A_QL + so) = *(const uint4*)(LLO + go);
    }
    __syncthreads();

    // hoist Q fragments to registers (kt-invariant)
    unsigned qh[4][2][4], ql[4][2][4];
    #pragma unroll
    for (int ks = 0; ks < 4; ks++) {
        uint32_t qb = sb + (((lane & 15)) * 72 + ks * 16 + (lane >> 4) * 8) * 2;
        #pragma unroll
        for (int mi = 0; mi < 2; mi++) {
            ldsm4(qh[ks][mi], qb + A_QH + mi * 2304);
            ldsm4(ql[ks][mi], qb + A_QL + mi * 2304);
        }
    }

    const float scale = 0.125f;
    float pacc[2][8][4] = {};       // PV partial (this warp's 16 keys)
    float ssum[4] = {0.f, 0.f, 0.f, 0.f};   // row-sum partials [mi*2+half]

    // ---- fused loop over 8 key tiles (K == V, loaded once) ----
    #pragma unroll 1
    for (int kt = 0; kt < 8; kt++) {
        if (kt < 7) {
            load_kv((kt + 1) & 1, kt + 1);
            CP_COMMIT();
            CP_WAIT1();
        } else {
            CP_WAIT0();
        }
        __syncthreads();
        const uint32_t kbase = sb + A_KB + (kt & 1) * A_KBUF;

        // QK^T for this warp's 16 keys
        float sqk[2][2][4] = {};
        #pragma unroll
        for (int ks = 0; ks < 4; ks++) {
            unsigned kh[4], kl[4];
            uint32_t kb = kbase + ((w * 16 + (lane & 15)) * 72 + ks * 16 + (lane >> 4) * 8) * 2;
            ldsm4(kh, kb);
            ldsm4(kl, kb + 18432);
            #pragma unroll
            for (int mi = 0; mi < 2; mi++) {
                mma_bf16(sqk[mi][0], qh[ks][mi][0],qh[ks][mi][1],qh[ks][mi][2],qh[ks][mi][3], kh[0], kh[2]);
                mma_bf16(sqk[mi][1], qh[ks][mi][0],qh[ks][mi][1],qh[ks][mi][2],qh[ks][mi][3], kh[1], kh[3]);
                mma_bf16(sqk[mi][0], qh[ks][mi][0],qh[ks][mi][1],qh[ks][mi][2],qh[ks][mi][3], kl[0], kl[2]);
                mma_bf16(sqk[mi][1], qh[ks][mi][0],qh[ks][mi][1],qh[ks][mi][2],qh[ks][mi][3], kl[1], kl[3]);
                mma_bf16(sqk[mi][0], ql[ks][mi][0],ql[ks][mi][1],ql[ks][mi][2],ql[ks][mi][3], kh[0], kh[2]);
                mma_bf16(sqk[mi][1], ql[ks][mi][0],ql[ks][mi][1],ql[ks][mi][2],ql[ks][mi][3], kh[1], kh[3]);
            }
        }

        // exp in regs, accumulate row sums, pack P hi/lo (regs + smem)
        unsigned ph[2][4], pl[2][4];
        #pragma unroll
        for (int mi = 0; mi < 2; mi++) {
            int r0q = mi * 16 + (lane >> 2);
            #pragma unroll
            for (int nj = 0; nj < 2; nj++) {
                float e0 = __expf(sqk[mi][nj][0] * scale);
                float e1 = __expf(sqk[mi][nj][1] * scale);
                float e2 = __expf(sqk[mi][nj][2] * scale);
                float e3 = __expf(sqk[mi][nj][3] * scale);
                ssum[mi*2]   += e0 + e1;
                ssum[mi*2+1] += e2 + e3;
                unsigned p0 = packhl(e0), p1 = packhl(e1);
                unsigned p2 = packhl(e2), p3 = packhl(e3);
                int cc = kt * 128 + w * 16 + nj * 8 + 2 * (lane & 3);
                *(uint2*)&pscore[r0q * SCSTR + cc]       = make_uint2(p0, p1);
                *(uint2*)&pscore[(r0q + 8) * SCSTR + cc] = make_uint2(p2, p3);
                ph[mi][nj*2]   = prmt(p0, p1, 0x7632);
                pl[mi][nj*2]   = prmt(p0, p1, 0x5410);
                ph[mi][nj*2+1] = prmt(p2, p3, 0x7632);
                pl[mi][nj*2+1] = prmt(p2, p3, 0x5410);
            }
        }

        // P @ V on the same tile (V rows = this warp's 16 keys), trans frags
        #pragma unroll
        for (int hg = 0; hg < 4; hg++) {
            unsigned vh[4], vl[4];
            uint32_t vb = kbase + ((w * 16 + (lane & 15)) * 72 + hg * 16 + (lane >> 4) * 8) * 2;
            ldsm4t(vh, vb);
            ldsm4t(vl, vb + 18432);
            #pragma unroll
            for (int mi = 0; mi < 2; mi++) {
                mma_bf16(pacc[mi][2*hg],   ph[mi][0],ph[mi][1],ph[mi][2],ph[mi][3], vh[0], vh[1]);
                mma_bf16(pacc[mi][2*hg+1], ph[mi][0],ph[mi][1],ph[mi][2],ph[mi][3], vh[2], vh[3]);
                mma_bf16(pacc[mi][2*hg],   ph[mi][0],ph[mi][1],ph[mi][2],ph[mi][3], vl[0], vl[1]);
                mma_bf16(pacc[mi][2*hg+1], ph[mi][0],ph[mi][1],ph[mi][2],ph[mi][3], vl[2], vl[3]);
                mma_bf16(pacc[mi][2*hg],   pl[mi][0],pl[mi][1],pl[mi][2],pl[mi][3], vh[0], vh[1]);
                mma_bf16(pacc[mi][2*hg+1], pl[mi][0],pl[mi][1],pl[mi][2],pl[mi][3], vh[2], vh[3]);
            }
        }
        __syncthreads();
    }

    // ---- row sums: reduce over the 4 lanes sharing a row, then cross-warp ----
    #pragma unroll
    for (int i = 0; i < 4; i++) {
        ssum[i] += __shfl_xor_sync(0xffffffffu, ssum[i], 1);
        ssum[i] += __shfl_xor_sync(0xffffffffu, ssum[i], 2);
    }
    if ((lane & 3) == 0) {
        int rr = lane >> 2;
        rsw[w][rr]      = ssum[0];
        rsw[w][rr + 8]  = ssum[1];
        rsw[w][rr + 16] = ssum[2];
        rsw[w][rr + 24] = ssum[3];
    }

    // ---- stage out fragments into the freed K-buffer (stride 66 floats) ----
    {
        float* rb = (float*)(sm + A_KB) + w * 2112;
        #pragma unroll
        for (int mi = 0; mi < 2; mi++) {
            int q0 = mi * 16 + (lane >> 2);
            #pragma unroll
            for (int g = 0; g < 8; g++) {
                int c = g * 8 + 2 * (lane & 3);
                *(float2*)&rb[q0 * 66 + c]       = make_float2(pacc[mi][g][0], pacc[mi][g][1]);
                *(float2*)&rb[(q0 + 8) * 66 + c] = make_float2(pacc[mi][g][2], pacc[mi][g][3]);
            }
        }
    }
    __syncthreads();
    if (tid < 32) {
        float t = 0.f;
        #pragma unroll
        for (int ww = 0; ww < 8; ww++) t += rsw[ww][tid];
        rs[tid] = 1.0f / t;
    }
    __syncthreads();

    // ---- write normalized attention from packed P ----
    {
        float* ap = out_attn + ((size_t)(n * BB + b)) * SS * SS + (size_t)s0 * SS;
        #pragma unroll
        for (int it = 0; it < 32; it++) {
            int idx = tid + it * 256;
            int r = idx >> 8;
            int c4 = (idx & 255) << 2;
            uint4 p = *(const uint4*)&pscore[r * SCSTR + c4];
            float iv = rs[r];
            float4 v;
            v.x = unpack_sum(p.x) * iv;
            v.y = unpack_sum(p.y) * iv;
            v.z = unpack_sum(p.z) * iv;
            v.w = unpack_sum(p.w) * iv;
            *(float4*)&ap[(size_t)r * SS + c4] = v;
        }
    }

    // ---- cross-warp out reduction + outh epilogue (bf16 hi/lo) ----
    {
        const float* rbase = (const float*)(sm + A_KB);
        int q = tid >> 3, hb = (tid & 7) * 8;
        float o[8] = {};
        #pragma unroll
        for (int ww = 0; ww < 8; ww++) {
            const float* r2 = rbase + ww * 2112 + q * 66 + hb;
            #pragma unroll
            for (int j = 0; j < 4; j++) {
                float2 a = *(const float2*)(r2 + j * 2);
                o[j*2]   += a.x;
                o[j*2+1] += a.y;
            }
        }
        float iv = rs[q];
        size_t go = (rowbase + s0 + q) * 1024 + colbase + hb;
        #pragma unroll
        for (int j = 0; j < 4; j++) {
            unsigned h, l;
            split2(o[j*2] * iv, o[j*2+1] * iv, h, l);
            *(unsigned*)(OHI + go + j * 2) = h;
            *(unsigned*)(OLO + go + j * 2) = l;
        }
    }
}

// ---------------------------------------------------------------------------
// Layernorm per row of 1024
// ---------------------------------------------------------------------------
__global__ __launch_bounds__(256) void ln_kernel(float* __restrict__ y,
                                                 const float* __restrict__ g,
                                                 const float* __restrict__ bfn) {
    const int r = blockIdx.x;
    const int tid = threadIdx.x;
    const int lane = tid & 31, wid = tid >> 5;
    __shared__ float red1[8];
    __shared__ float red2[8];
    __shared__ float sh_mu, sh_rstd;

    float4 v = *(const float4*)&g_ypre[r * 1024 + tid * 4];
    float s = v.x + v.y + v.z + v.w;
    #pragma unroll
    for (int o = 16; o > 0; o >>= 1) s += __shfl_xor_sync(0xffffffffu, s, o);
    if (lane == 0) red1[wid] = s;
    __syncthreads();
    if (tid == 0) {
        float t = 0.f;
        #pragma unroll
        for (int i = 0; i < 8; i++) t += red1[i];
        sh_mu = t * (1.0f / 1024.0f);
    }
    __syncthreads();
    float mu = sh_mu;
    float dx = v.x - mu, dy = v.y - mu, dz = v.z - mu, dw = v.w - mu;
    float sq = dx * dx + dy * dy + dz * dz + dw * dw;
    #pragma unroll
    for (int o = 16; o > 0; o >>= 1) sq += __shfl_xor_sync(0xffffffffu, sq, o);
    if (lane == 0) red2[wid] = sq;
    __syncthreads();
    if (tid == 0) {
        float t = 0.f;
        #pragma unroll
        for (int i = 0; i < 8; i++) t += red2[i];
        sh_rstd = rsqrtf(t * (1.0f / 1024.0f) + 1e-5f);
    }
    __syncthreads();
    float rstd = sh_rstd;
    float4 gv = *(const float4*)&g[tid * 4];
    float4 bv = *(const float4*)&bfn[tid * 4];
    float4 o;
    o.x = dx * rstd * gv.x + bv.x;
    o.y = dy * rstd * gv.y + bv.y;
    o.z = dz * rstd * gv.z + bv.z;
    o.w = dw * rstd * gv.w + bv.w;
    *(float4*)&y[r * 1024 + tid * 4] = o;
}

// ---------------------------------------------------------------------------
extern "C" void kernel_launch(void* const* d_in, const int* in_sizes, int n_in,
                              void* d_out, int out_size) {
    const float* x   = (const float*)d_in[0];
    const float* w   = (const float*)d_in[1];
    const float* lw  = (const float*)d_in[2];
    const float* lb  = (const float*)d_in[3];
    const float* lng = (const float*)d_in[4];
    const float* lnb = (const float*)d_in[5];
    float* out = (float*)d_out;

    __nv_bfloat16 *xhi, *xlo, *wthi, *wtlo, *lwhi, *lwlo, *lhi, *llo, *ohhi, *ohlo;
    float *ypre;
    cudaGetSymbolAddress((void**)&xhi, g_xhi);   cudaGetSymbolAddress((void**)&xlo, g_xlo);
    cudaGetSymbolAddress((void**)&wthi, g_wThi); cudaGetSymbolAddress((void**)&wtlo, g_wTlo);
    cudaGetSymbolAddress((void**)&lwhi, g_lwhi); cudaGetSymbolAddress((void**)&lwlo, g_lwlo);
    cudaGetSymbolAddress((void**)&lhi, g_lhi);   cudaGetSymbolAddress((void**)&llo, g_llo);
    cudaGetSymbolAddress((void**)&ohhi, g_ohhi); cudaGetSymbolAddress((void**)&ohlo, g_ohlo);
    cudaGetSymbolAddress((void**)&ypre, g_ypre);

    cudaFuncSetAttribute(gemm_mma<0>, cudaFuncAttributeMaxDynamicSharedMemorySize, GSMEM);
    cudaFuncSetAttribute(gemm_mma<1>, cudaFuncAttributeMaxDynamicSharedMemorySize, GSMEM);
    cudaFuncSetAttribute(attn_kernel, cudaFuncAttributeMaxDynamicSharedMemorySize, ASMEM);

    // input splits
    split4_kernel<<<8192, 256>>>(x, xhi, xlo, MROWS * DD / 4);
    convw_kernel<<<4096, 256>>>(w);
    split4_kernel<<<1024, 256>>>(lw, lwhi, lwlo, DD * DD / 4);

    // head projection -> logits (bf16 hi/lo, concat layout)
    gemm_mma<0><<<dim3(64, 8), 256, GSMEM>>>(xhi, xlo, wthi, wtlo,
                                             lhi, llo, nullptr, nullptr, nullptr);
    // fused single-pass attention: writes attn matrix + outh (bf16 hi/lo)
    attn_kernel<<<dim3(32, 8, 16), 256, ASMEM>>>(lhi, llo, out + Y_SIZE, ohhi, ohlo);
    // output projection + residual + bias
    gemm_mma<1><<<dim3(64, 8), 256, GSMEM>>>(ohhi, ohlo, lwhi, lwlo,
                                             nullptr, nullptr, ypre, x, lb);
    // layernorm
    ln_kernel<<<MROWS, 256>>>(out, lng, lnb);
}

// round 14
// speedup vs baseline: 1.8876x; 1.0773x over previous
#include <cuda_runtime.h>
#include <cuda_bf16.h>
#include <cuda_fp16.h>
#include <cstdint>
#include <math.h>

#define BB 8
#define SS 1024
#define DD 1024
#define NH 16
#define HH 64
#define MROWS (BB*SS)            // 8192
#define Y_SIZE (BB*SS*DD)        // 8388608

// ---------------------------------------------------------------------------
// Scratch (device globals; no allocations allowed)
// ---------------------------------------------------------------------------
__device__ float g_ypre[MROWS*DD];                         // pre-layernorm y
__device__ __nv_bfloat16 g_xhi[MROWS*DD], g_xlo[MROWS*DD]; // x split (bf16)
__device__ __nv_bfloat16 g_wThi[DD*DD], g_wTlo[DD*DD];     // proj B: [c=n*64+h][d]
__device__ __half g_lwh[DD*DD], g_lwl[DD*DD];              // outproj B fp16 hi/lo
__device__ __nv_bfloat16 g_lhi[MROWS*DD], g_llo[MROWS*DD]; // logits split [r][n*64+h]
__device__ __half g_oh[MROWS*DD];                          // attn heads out (fp16)

// ---------------------------------------------------------------------------
// mma.sync / ldmatrix / cp.async helpers (base ISA)
// ---------------------------------------------------------------------------
__device__ __forceinline__ uint32_t smem_u32(const void* p) {
    uint32_t a;
    asm("{ .reg .u64 t; cvta.to.shared.u64 t, %1; cvt.u32.u64 %0, t; }" : "=r"(a) : "l"(p));
    return a;
}

__device__ __forceinline__ void mma_bf16(float c[4],
                                         unsigned a0, unsigned a1, unsigned a2, unsigned a3,
                                         unsigned b0, unsigned b1) {
    asm volatile("mma.sync.aligned.m16n8k16.row.col.f32.bf16.bf16.f32 "
        "{%0,%1,%2,%3}, {%4,%5,%6,%7}, {%8,%9}, {%0,%1,%2,%3};"
        : "+f"(c[0]), "+f"(c[1]), "+f"(c[2]), "+f"(c[3])
        : "r"(a0), "r"(a1), "r"(a2), "r"(a3), "r"(b0), "r"(b1));
}
__device__ __forceinline__ void mma_fp16(float c[4],
                                         unsigned a0, unsigned a1, unsigned a2, unsigned a3,
                                         unsigned b0, unsigned b1) {
    asm volatile("mma.sync.aligned.m16n8k16.row.col.f32.f16.f16.f32 "
        "{%0,%1,%2,%3}, {%4,%5,%6,%7}, {%8,%9}, {%0,%1,%2,%3};"
        : "+f"(c[0]), "+f"(c[1]), "+f"(c[2]), "+f"(c[3])
        : "r"(a0), "r"(a1), "r"(a2), "r"(a3), "r"(b0), "r"(b1));
}

__device__ __forceinline__ void ldsm4(unsigned r[4], uint32_t addr) {
    asm volatile("ldmatrix.sync.aligned.m8n8.x4.shared.b16 {%0,%1,%2,%3}, [%4];"
        : "=r"(r[0]), "=r"(r[1]), "=r"(r[2]), "=r"(r[3]) : "r"(addr));
}
__device__ __forceinline__ void ldsm4t(unsigned r[4], uint32_t addr) {
    asm volatile("ldmatrix.sync.aligned.m8n8.x4.trans.shared.b16 {%0,%1,%2,%3}, [%4];"
        : "=r"(r[0]), "=r"(r[1]), "=r"(r[2]), "=r"(r[3]) : "r"(addr));
}

__device__ __forceinline__ void cp16(uint32_t dst, const void* src) {
    asm volatile("cp.async.cg.shared.global [%0], [%1], 16;" :: "r"(dst), "l"(src));
}
#define CP_COMMIT() asm volatile("cp.async.commit_group;" ::: "memory")
#define CP_WAIT0()  asm volatile("cp.async.wait_group 0;" ::: "memory")

__device__ __forceinline__ unsigned prmt(unsigned a, unsigned b, unsigned sel) {
    unsigned r;
    asm("prmt.b32 %0, %1, %2, %3;" : "=r"(r) : "r"(a), "r"(b), "r"(sel));
    return r;
}

// hi/lo split of float pair -> two packed bf16x2 regs
__device__ __forceinline__ void split2(float x, float y, unsigned& h, unsigned& l) {
    __nv_bfloat16 hx = __float2bfloat16(x), hy = __float2bfloat16(y);
    __nv_bfloat162 hp(hx, hy);
    __nv_bfloat162 lp(__float2bfloat16(x - __bfloat162float(hx)),
                      __float2bfloat16(y - __bfloat162float(hy)));
    h = *(unsigned*)&hp;
    l = *(unsigned*)&lp;
}

// pack one float into (bf16hi << 16) | bf16lo
__device__ __forceinline__ unsigned packhl(float v) {
    __nv_bfloat16 h = __float2bfloat16(v);
    __nv_bfloat16 l = __float2bfloat16(v - __bfloat162float(h));
    return ((unsigned)*(unsigned short*)&h << 16) | (unsigned)*(unsigned short*)&l;
}
__device__ __forceinline__ float unpack_sum(unsigned u) {
    return __uint_as_float(u & 0xFFFF0000u) + __uint_as_float(u << 16);
}

// ---------------------------------------------------------------------------
// Converters
// ---------------------------------------------------------------------------
__global__ __launch_bounds__(256) void split4_kernel(const float* __restrict__ s,
                                                     __nv_bfloat16* __restrict__ hi,
                                                     __nv_bfloat16* __restrict__ lo, int n4) {
    int i = blockIdx.x * 256 + threadIdx.x;
    if (i >= n4) return;
    float4 v = ((const float4*)s)[i];
    unsigned h0, l0, h1, l1;
    split2(v.x, v.y, h0, l0);
    split2(v.z, v.w, h1, l1);
    ((unsigned*)hi)[i*2]   = h0;
    ((unsigned*)hi)[i*2+1] = h1;
    ((unsigned*)lo)[i*2]   = l0;
    ((unsigned*)lo)[i*2+1] = l1;
}

// fp16 hi/lo split (for lin_w)
__global__ __launch_bounds__(256) void split4h_kernel(const float* __restrict__ s,
                                                      __half* __restrict__ hi,
                                                      __half* __restrict__ lo, int n4) {
    int i = blockIdx.x * 256 + threadIdx.x;
    if (i >= n4) return;
    float4 v = ((const float4*)s)[i];
    __half h0 = __float2half_rn(v.x), h1 = __float2half_rn(v.y);
    __half h2 = __float2half_rn(v.z), h3 = __float2half_rn(v.w);
    ((__half2*)hi)[i*2]   = __halves2half2(h0, h1);
    ((__half2*)hi)[i*2+1] = __halves2half2(h2, h3);
    ((__half2*)lo)[i*2]   = __halves2half2(__float2half_rn(v.x - __half2float(h0)),
                                           __float2half_rn(v.y - __half2float(h1)));
    ((__half2*)lo)[i*2+1] = __halves2half2(__float2half_rn(v.z - __half2float(h2)),
                                           __float2half_rn(v.w - __half2float(h3)));
}

// w [NH][DD][HH] -> wT[c=n*64+h][d], split hi/lo (bf16)
__global__ __launch_bounds__(256) void convw_kernel(const float* __restrict__ w) {
    int o = blockIdx.x * 256 + threadIdx.x;
    int c = o >> 10, d = o & 1023;
    int n = c >> 6, h = c & 63;
    float v = __ldg(&w[(n * 1024 + d) * 64 + h]);
    __nv_bfloat16 hv = __float2bfloat16(v);
    g_wThi[o] = hv;
    g_wTlo[o] = __float2bfloat16(v - __bfloat162float(hv));
}

// ---------------------------------------------------------------------------
// Proj GEMM (bf16 hi/lo 3-pass, R5-proven): sync loads, K chunk 64,
// 73.7KB smem -> 2 CTAs/SM. Block 128x128, 8 warps (2m x 4n), warp 64x32.
// Writes logits as bf16 hi/lo.
// ---------------------------------------------------------------------------
#define GA_H 0
#define GA_L 18432
#define GB_H 36864
#define GB_L 55296
#define GSMEM 73728

__global__ __launch_bounds__(256) void gemm_proj(
    const __nv_bfloat16* __restrict__ Ah, const __nv_bfloat16* __restrict__ Al,
    const __nv_bfloat16* __restrict__ Bh, const __nv_bfloat16* __restrict__ Bl,
    __nv_bfloat16* __restrict__ Chi, __nv_bfloat16* __restrict__ Clo)
{
    extern __shared__ char sm[];
    const uint32_t sb = smem_u32(sm);
    const int tid = threadIdx.x, w = tid >> 5, lane = tid & 31;
    const int wm = w >> 2, wn = w & 3;
    const int r0 = blockIdx.x * 128, c0 = blockIdx.y * 128;

    float acc[4][4][4] = {};
    const int lrow = tid >> 3, lc8 = tid & 7;

    #pragma unroll 1
    for (int k0 = 0; k0 < 1024; k0 += 64) {
        __syncthreads();
        #pragma unroll
        for (int it = 0; it < 4; it++) {
            int rr = lrow + it * 32;
            size_t goA = (size_t)(r0 + rr) * 1024 + k0 + lc8 * 8;
            size_t goB = (size_t)(c0 + rr) * 1024 + k0 + lc8 * 8;
            uint32_t so = (rr * 72 + lc8 * 8) * 2;
            *(uint4*)(sm + GA_H + so) = *(const uint4*)(Ah + goA);
            *(uint4*)(sm + GA_L + so) = *(const uint4*)(Al + goA);
            *(uint4*)(sm + GB_H + so) = *(const uint4*)(Bh + goB);
            *(uint4*)(sm + GB_L + so) = *(const uint4*)(Bl + goB);
        }
        __syncthreads();
        #pragma unroll
        for (int ks = 0; ks < 4; ks++) {
            unsigned ah[4][4], al[4][4], bh[2][4], bl[2][4];
            uint32_t abase = sb + ((wm * 64 + (lane & 15)) * 72 + ks * 16 + (lane >> 4) * 8) * 2;
            #pragma unroll
            for (int mi = 0; mi < 4; mi++) {
                ldsm4(ah[mi], abase + GA_H + mi * 2304);
                ldsm4(al[mi], abase + GA_L + mi * 2304);
            }
            uint32_t bbase = sb + ((wn * 32 + (lane & 15)) * 72 + ks * 16 + (lane >> 4) * 8) * 2;
            #pragma unroll
            for (int ni = 0; ni < 2; ni++) {
                ldsm4(bh[ni], bbase + GB_H + ni * 2304);
                ldsm4(bl[ni], bbase + GB_L + ni * 2304);
            }
            #pragma unroll
            for (int mi = 0; mi < 4; mi++)
                #pragma unroll
                for (int ni = 0; ni < 2; ni++) {
                    mma_bf16(acc[mi][2*ni],   ah[mi][0],ah[mi][1],ah[mi][2],ah[mi][3], bh[ni][0], bh[ni][2]);
                    mma_bf16(acc[mi][2*ni+1], ah[mi][0],ah[mi][1],ah[mi][2],ah[mi][3], bh[ni][1], bh[ni][3]);
                    mma_bf16(acc[mi][2*ni],   ah[mi][0],ah[mi][1],ah[mi][2],ah[mi][3], bl[ni][0], bl[ni][2]);
                    mma_bf16(acc[mi][2*ni+1], ah[mi][0],ah[mi][1],ah[mi][2],ah[mi][3], bl[ni][1], bl[ni][3]);
                    mma_bf16(acc[mi][2*ni],   al[mi][0],al[mi][1],al[mi][2],al[mi][3], bh[ni][0], bh[ni][2]);
                    mma_bf16(acc[mi][2*ni+1], al[mi][0],al[mi][1],al[mi][2],al[mi][3], bh[ni][1], bh[ni][3]);
                }
        }
    }

    #pragma unroll
    for (int mi = 0; mi < 4; mi++) {
        int rr = r0 + wm * 64 + mi * 16 + (lane >> 2);
        #pragma unroll
        for (int nj = 0; nj < 4; nj++) {
            int cc = c0 + wn * 32 + nj * 8 + 2 * (lane & 3);
            #pragma unroll
            for (int half = 0; half < 2; half++) {
                unsigned h, l;
                split2(acc[mi][nj][half*2], acc[mi][nj][half*2+1], h, l);
                size_t go = (size_t)(rr + half*8) * 1024 + cc;
                *(unsigned*)(Chi + go) = h;
                *(unsigned*)(Clo + go) = l;
            }
        }
    }
}

// ---------------------------------------------------------------------------
// Outproj GEMM, fp16 2-pass: A = outh (plain fp16), B = lin_w fp16 hi/lo.
// C = a*bh + a*bl + RX + BIAS. 32 mma/ks (vs 48). Smem 55.3KB -> 2 CTAs/SM.
// ---------------------------------------------------------------------------
#define GO_A  0
#define GO_BH 18432
#define GO_BL 36864
#define GOSMEM 55296

__global__ __launch_bounds__(256) void gemm_out(
    const __half* __restrict__ A, const __half* __restrict__ Bh,
    const __half* __restrict__ Bl,
    float* __restrict__ Cf, const float* __restrict__ RX, const float* __restrict__ BIAS)
{
    extern __shared__ char sm[];
    const uint32_t sb = smem_u32(sm);
    const int tid = threadIdx.x, w = tid >> 5, lane = tid & 31;
    const int wm = w >> 2, wn = w & 3;
    const int r0 = blockIdx.x * 128, c0 = blockIdx.y * 128;

    float acc[4][4][4] = {};
    const int lrow = tid >> 3, lc8 = tid & 7;

    #pragma unroll 1
    for (int k0 = 0; k0 < 1024; k0 += 64) {
        __syncthreads();
        #pragma unroll
        for (int it = 0; it < 4; it++) {
            int rr = lrow + it * 32;
            size_t goA = (size_t)(r0 + rr) * 1024 + k0 + lc8 * 8;
            size_t goB = (size_t)(c0 + rr) * 1024 + k0 + lc8 * 8;
            uint32_t so = (rr * 72 + lc8 * 8) * 2;
            *(uint4*)(sm + GO_A  + so) = *(const uint4*)(A  + goA);
            *(uint4*)(sm + GO_BH + so) = *(const uint4*)(Bh + goB);
            *(uint4*)(sm + GO_BL + so) = *(const uint4*)(Bl + goB);
        }
        __syncthreads();
        #pragma unroll
        for (int ks = 0; ks < 4; ks++) {
            unsigned ah[4][4], bh[2][4], bl[2][4];
            uint32_t abase = sb + ((wm * 64 + (lane & 15)) * 72 + ks * 16 + (lane >> 4) * 8) * 2;
            #pragma unroll
            for (int mi = 0; mi < 4; mi++) ldsm4(ah[mi], abase + GO_A + mi * 2304);
            uint32_t bbase = sb + ((wn * 32 + (lane & 15)) * 72 + ks * 16 + (lane >> 4) * 8) * 2;
            #pragma unroll
            for (int ni = 0; ni < 2; ni++) {
                ldsm4(bh[ni], bbase + GO_BH + ni * 2304);
                ldsm4(bl[ni], bbase + GO_BL + ni * 2304);
            }
            #pragma unroll
            for (int mi = 0; mi < 4; mi++)
                #pragma unroll
                for (int ni = 0; ni < 2; ni++) {
                    mma_fp16(acc[mi][2*ni],   ah[mi][0],ah[mi][1],ah[mi][2],ah[mi][3], bh[ni][0], bh[ni][2]);
                    mma_fp16(acc[mi][2*ni+1], ah[mi][0],ah[mi][1],ah[mi][2],ah[mi][3], bh[ni][1], bh[ni][3]);
                    mma_fp16(acc[mi][2*ni],   ah[mi][0],ah[mi][1],ah[mi][2],ah[mi][3], bl[ni][0], bl[ni][2]);
                    mma_fp16(acc[mi][2*ni+1], ah[mi][0],ah[mi][1],ah[mi][2],ah[mi][3], bl[ni][1], bl[ni][3]);
                }
        }
    }

    #pragma unroll
    for (int mi = 0; mi < 4; mi++) {
        int rr = r0 + wm * 64 + mi * 16 + (lane >> 2);
        #pragma unroll
        for (int nj = 0; nj < 4; nj++) {
            int cc = c0 + wn * 32 + nj * 8 + 2 * (lane & 3);
            #pragma unroll
            for (int half = 0; half < 2; half++) {
                size_t go = (size_t)(rr + half*8) * 1024 + cc;
                float2 xv = *(const float2*)(RX + go);
                float2 bv = *(const float2*)(BIAS + cc);
                float2 o;
                o.x = acc[mi][nj][half*2]   + xv.x + bv.x;
                o.y = acc[mi][nj][half*2+1] + xv.y + bv.y;
                *(float2*)(Cf + go) = o;
            }
        }
    }
}

// ---------------------------------------------------------------------------
// Single-pass fused attention per (n, b, 32-row tile), 256 threads.
// Race-free single-barrier cp.async pattern; outh written as plain fp16.
// ---------------------------------------------------------------------------
#define SCSTR 1032
#define A_QH  132096                    // pscore: 32*1032*4 = 132096
#define A_QL  136704
#define A_KB  141312                    // 2 bufs x (KH 18432 + KL 18432)
#define A_KBUF 36864
#define ASMEM (A_KB + 2*A_KBUF)         // 215040

__global__ __launch_bounds__(256, 1) void attn_kernel(
    const __nv_bfloat16* __restrict__ LHI, const __nv_bfloat16* __restrict__ LLO,
    float* __restrict__ out_attn, __half* __restrict__ OH)
{
    extern __shared__ char sm[];
    const uint32_t sb = smem_u32(sm);
    unsigned* pscore = (unsigned*)sm;
    __shared__ float rs[32];
    __shared__ float rsw[8][32];

    const int rt = blockIdx.x, b = blockIdx.y, n = blockIdx.z;
    const int s0 = rt * 32;
    const int tid = threadIdx.x, w = tid >> 5, lane = tid & 31;
    const size_t rowbase = (size_t)b * 1024;
    const int colbase = n * 64;
    const int lrow = tid >> 3, lc8 = tid & 7;

    auto load_kv = [&](int buf, int tile) {
        const uint32_t bh = sb + A_KB + buf * A_KBUF;
        #pragma unroll
        for (int it = 0; it < 4; it++) {
            int row = lrow + it * 32;
            size_t go = (rowbase + tile * 128 + row) * 1024 + colbase + lc8 * 8;
            uint32_t so = (row * 72 + lc8 * 8) * 2;
            cp16(bh + so,         LHI + go);
            cp16(bh + 18432 + so, LLO + go);
        }
    };

    // prefetch K tile 0; load Q tile (32 x 64) hi/lo direct
    load_kv(0, 0);
    CP_COMMIT();
    {
        int row = tid >> 3, c8 = tid & 7;
        uint32_t so = (row * 72 + c8 * 8) * 2;
        size_t go = (rowbase + s0 + row) * 1024 + colbase + c8 * 8;
        *(uint4*)(sm + A_QH + so) = *(const uint4*)(LHI + go);
        *(uint4*)(sm + A_QL + so) = *(const uint4*)(LLO + go);
    }
    __syncthreads();

    // hoist Q fragments to registers (kt-invariant)
    unsigned qh[4][2][4], ql[4][2][4];
    #pragma unroll
    for (int ks = 0; ks < 4; ks++) {
        uint32_t qb = sb + (((lane & 15)) * 72 + ks * 16 + (lane >> 4) * 8) * 2;
        #pragma unroll
        for (int mi = 0; mi < 2; mi++) {
            ldsm4(qh[ks][mi], qb + A_QH + mi * 2304);
            ldsm4(ql[ks][mi], qb + A_QL + mi * 2304);
        }
    }

    const float scale = 0.125f;
    float pacc[2][8][4] = {};
    float ssum[4] = {0.f, 0.f, 0.f, 0.f};

    // ---- fused loop over 8 key tiles (K == V, loaded once) ----
    // Race-free single-barrier pattern: wait(tile kt) -> barrier -> issue
    // load(kt+1) -> compute(kt). The barrier guarantees all warps finished
    // tile kt-1 (the previous user of buffer (kt+1)&1) before it is rewritten.
    #pragma unroll 1
    for (int kt = 0; kt < 8; kt++) {
        CP_WAIT0();
        __syncthreads();
        if (kt < 7) {
            load_kv((kt + 1) & 1, kt + 1);
            CP_COMMIT();
        }
        const uint32_t kbase = sb + A_KB + (kt & 1) * A_KBUF;

        // QK^T for this warp's 16 keys
        float sqk[2][2][4] = {};
        #pragma unroll
        for (int ks = 0; ks < 4; ks++) {
            unsigned kh[4], kl[4];
            uint32_t kb = kbase + ((w * 16 + (lane & 15)) * 72 + ks * 16 + (lane >> 4) * 8) * 2;
            ldsm4(kh, kb);
            ldsm4(kl, kb + 18432);
            #pragma unroll
            for (int mi = 0; mi < 2; mi++) {
                mma_bf16(sqk[mi][0], qh[ks][mi][0],qh[ks][mi][1],qh[ks][mi][2],qh[ks][mi][3], kh[0], kh[2]);
                mma_bf16(sqk[mi][1], qh[ks][mi][0],qh[ks][mi][1],qh[ks][mi][2],qh[ks][mi][3], kh[1], kh[3]);
                mma_bf16(sqk[mi][0], qh[ks][mi][0],qh[ks][mi][1],qh[ks][mi][2],qh[ks][mi][3], kl[0], kl[2]);
                mma_bf16(sqk[mi][1], qh[ks][mi][0],qh[ks][mi][1],qh[ks][mi][2],qh[ks][mi][3], kl[1], kl[3]);
                mma_bf16(sqk[mi][0], ql[ks][mi][0],ql[ks][mi][1],ql[ks][mi][2],ql[ks][mi][3], kh[0], kh[2]);
                mma_bf16(sqk[mi][1], ql[ks][mi][0],ql[ks][mi][1],ql[ks][mi][2],ql[ks][mi][3], kh[1], kh[3]);
            }
        }

        // exp in regs, accumulate row sums, pack P hi/lo (regs + smem)
        unsigned ph[2][4], pl[2][4];
        #pragma unroll
        for (int mi = 0; mi < 2; mi++) {
            int r0q = mi * 16 + (lane >> 2);
            #pragma unroll
            for (int nj = 0; nj < 2; nj++) {
                float e0 = __expf(sqk[mi][nj][0] * scale);
                float e1 = __expf(sqk[mi][nj][1] * scale);
                float e2 = __expf(sqk[mi][nj][2] * scale);
                float e3 = __expf(sqk[mi][nj][3] * scale);
                ssum[mi*2]   += e0 + e1;
                ssum[mi*2+1] += e2 + e3;
                unsigned p0 = packhl(e0), p1 = packhl(e1);
                unsigned p2 = packhl(e2), p3 = packhl(e3);
                int cc = kt * 128 + w * 16 + nj * 8 + 2 * (lane & 3);
                *(uint2*)&pscore[r0q * SCSTR + cc]       = make_uint2(p0, p1);
                *(uint2*)&pscore[(r0q + 8) * SCSTR + cc] = make_uint2(p2, p3);
                ph[mi][nj*2]   = prmt(p0, p1, 0x7632);
                pl[mi][nj*2]   = prmt(p0, p1, 0x5410);
                ph[mi][nj*2+1] = prmt(p2, p3, 0x7632);
                pl[mi][nj*2+1] = prmt(p2, p3, 0x5410);
            }
        }

        // P @ V on the same tile (V rows = this warp's 16 keys)
        #pragma unroll
        for (int hg = 0; hg < 4; hg++) {
            unsigned vh[4], vl[4];
            uint32_t vb = kbase + ((w * 16 + (lane & 15)) * 72 + hg * 16 + (lane >> 4) * 8) * 2;
            ldsm4t(vh, vb);
            ldsm4t(vl, vb + 18432);
            #pragma unroll
            for (int mi = 0; mi < 2; mi++) {
                mma_bf16(pacc[mi][2*hg],   ph[mi][0],ph[mi][1],ph[mi][2],ph[mi][3], vh[0], vh[1]);
                mma_bf16(pacc[mi][2*hg+1], ph[mi][0],ph[mi][1],ph[mi][2],ph[mi][3], vh[2], vh[3]);
                mma_bf16(pacc[mi][2*hg],   ph[mi][0],ph[mi][1],ph[mi][2],ph[mi][3], vl[0], vl[1]);
                mma_bf16(pacc[mi][2*hg+1], ph[mi][0],ph[mi][1],ph[mi][2],ph[mi][3], vl[2], vl[3]);
                mma_bf16(pacc[mi][2*hg],   pl[mi][0],pl[mi][1],pl[mi][2],pl[mi][3], vh[0], vh[1]);
                mma_bf16(pacc[mi][2*hg+1], pl[mi][0],pl[mi][1],pl[mi][2],pl[mi][3], vh[2], vh[3]);
            }
        }
    }
    __syncthreads();     // all warps done reading K buffers before reuse

    // ---- row sums: reduce over the 4 lanes sharing a row, then cross-warp ----
    #pragma unroll
    for (int i = 0; i < 4; i++) {
        ssum[i] += __shfl_xor_sync(0xffffffffu, ssum[i], 1);
        ssum[i] += __shfl_xor_sync(0xffffffffu, ssum[i], 2);
    }
    if ((lane & 3) == 0) {
        int rr = lane >> 2;
        rsw[w][rr]      = ssum[0];
        rsw[w][rr + 8]  = ssum[1];
        rsw[w][rr + 16] = ssum[2];
        rsw[w][rr + 24] = ssum[3];
    }

    // ---- stage out fragments into the freed K-buffer (stride 66 floats) ----
    {
        float* rb = (float*)(sm + A_KB) + w * 2112;
        #pragma unroll
        for (int mi = 0; mi < 2; mi++) {
            int q0 = mi * 16 + (lane >> 2);
            #pragma unroll
            for (int g = 0; g < 8; g++) {
                int c = g * 8 + 2 * (lane & 3);
                *(float2*)&rb[q0 * 66 + c]       = make_float2(pacc[mi][g][0], pacc[mi][g][1]);
                *(float2*)&rb[(q0 + 8) * 66 + c] = make_float2(pacc[mi][g][2], pacc[mi][g][3]);
            }
        }
    }
    __syncthreads();
    if (tid < 32) {
        float t = 0.f;
        #pragma unroll
        for (int ww = 0; ww < 8; ww++) t += rsw[ww][tid];
        rs[tid] = 1.0f / t;
    }
    __syncthreads();

    // ---- write normalized attention from packed P ----
    {
        float* ap = out_attn + ((size_t)(n * BB + b)) * SS * SS + (size_t)s0 * SS;
        #pragma unroll
        for (int it = 0; it < 32; it++) {
            int idx = tid + it * 256;
            int r = idx >> 8;
            int c4 = (idx & 255) << 2;
            uint4 p = *(const uint4*)&pscore[r * SCSTR + c4];
            float iv = rs[r];
            float4 v;
            v.x = unpack_sum(p.x) * iv;
            v.y = unpack_sum(p.y) * iv;
            v.z = unpack_sum(p.z) * iv;
            v.w = unpack_sum(p.w) * iv;
            *(float4*)&ap[(size_t)r * SS + c4] = v;
        }
    }

    // ---- cross-warp out reduction + outh epilogue (plain fp16) ----
    {
        const float* rbase = (const float*)(sm + A_KB);
        int q = tid >> 3, hb = (tid & 7) * 8;
        float o[8] = {};
        #pragma unroll
        for (int ww = 0; ww < 8; ww++) {
            const float* r2 = rbase + ww * 2112 + q * 66 + hb;
            #pragma unroll
            for (int j = 0; j < 4; j++) {
                float2 a = *(const float2*)(r2 + j * 2);
                o[j*2]   += a.x;
                o[j*2+1] += a.y;
            }
        }
        float iv = rs[q];
        size_t go = (rowbase + s0 + q) * 1024 + colbase + hb;
        #pragma unroll
        for (int j = 0; j < 4; j++) {
            __half2 hv = __floats2half2_rn(o[j*2] * iv, o[j*2+1] * iv);
            *(__half2*)(OH + go + j * 2) = hv;
        }
    }
}

// ---------------------------------------------------------------------------
// Layernorm per row of 1024
// ---------------------------------------------------------------------------
__global__ __launch_bounds__(256) void ln_kernel(float* __restrict__ y,
                                                 const float* __restrict__ g,
                                                 const float* __restrict__ bfn) {
    const int r = blockIdx.x;
    const int tid = threadIdx.x;
    const int lane = tid & 31, wid = tid >> 5;
    __shared__ float red1[8];
    __shared__ float red2[8];
    __shared__ float sh_mu, sh_rstd;

    float4 v = *(const float4*)&g_ypre[r * 1024 + tid * 4];
    float s = v.x + v.y + v.z + v.w;
    #pragma unroll
    for (int o = 16; o > 0; o >>= 1) s += __shfl_xor_sync(0xffffffffu, s, o);
    if (lane == 0) red1[wid] = s;
    __syncthreads();
    if (tid == 0) {
        float t = 0.f;
        #pragma unroll
        for (int i = 0; i < 8; i++) t += red1[i];
        sh_mu = t * (1.0f / 1024.0f);
    }
    __syncthreads();
    float mu = sh_mu;
    float dx = v.x - mu, dy = v.y - mu, dz = v.z - mu, dw = v.w - mu;
    float sq = dx * dx + dy * dy + dz * dz + dw * dw;
    #pragma unroll
    for (int o = 16; o > 0; o >>= 1) sq += __shfl_xor_sync(0xffffffffu, sq, o);
    if (lane == 0) red2[wid] = sq;
    __syncthreads();
    if (tid == 0) {
        float t = 0.f;
        #pragma unroll
        for (int i = 0; i < 8; i++) t += red2[i];
        sh_rstd = rsqrtf(t * (1.0f / 1024.0f) + 1e-5f);
    }
    __syncthreads();
    float rstd = sh_rstd;
    float4 gv = *(const float4*)&g[tid * 4];
    float4 bv = *(const float4*)&bfn[tid * 4];
    float4 o;
    o.x = dx * rstd * gv.x + bv.x;
    o.y = dy * rstd * gv.y + bv.y;
    o.z = dz * rstd * gv.z + bv.z;
    o.w = dw * rstd * gv.w + bv.w;
    *(float4*)&y[r * 1024 + tid * 4] = o;
}

// ---------------------------------------------------------------------------
extern "C" void kernel_launch(void* const* d_in, const int* in_sizes, int n_in,
                              void* d_out, int out_size) {
    const float* x   = (const float*)d_in[0];
    const float* w   = (const float*)d_in[1];
    const float* lw  = (const float*)d_in[2];
    const float* lb  = (const float*)d_in[3];
    const float* lng = (const float*)d_in[4];
    const float* lnb = (const float*)d_in[5];
    float* out = (float*)d_out;

    __nv_bfloat16 *xhi, *xlo, *wthi, *wtlo, *lhi, *llo;
    __half *lwh, *lwl, *oh;
    float *ypre;
    cudaGetSymbolAddress((void**)&xhi, g_xhi);   cudaGetSymbolAddress((void**)&xlo, g_xlo);
    cudaGetSymbolAddress((void**)&wthi, g_wThi); cudaGetSymbolAddress((void**)&wtlo, g_wTlo);
    cudaGetSymbolAddress((void**)&lwh, g_lwh);   cudaGetSymbolAddress((void**)&lwl, g_lwl);
    cudaGetSymbolAddress((void**)&lhi, g_lhi);   cudaGetSymbolAddress((void**)&llo, g_llo);
    cudaGetSymbolAddress((void**)&oh, g_oh);
    cudaGetSymbolAddress((void**)&ypre, g_ypre);

    cudaFuncSetAttribute(gemm_proj, cudaFuncAttributeMaxDynamicSharedMemorySize, GSMEM);
    cudaFuncSetAttribute(gemm_out, cudaFuncAttributeMaxDynamicSharedMemorySize, GOSMEM);
    cudaFuncSetAttribute(attn_kernel, cudaFuncAttributeMaxDynamicSharedMemorySize, ASMEM);

    // input splits
    split4_kernel<<<8192, 256>>>(x, xhi, xlo, MROWS * DD / 4);
    convw_kernel<<<4096, 256>>>(w);
    split4h_kernel<<<1024, 256>>>(lw, lwh, lwl, DD * DD / 4);

    // head projection -> logits (bf16 hi/lo, concat layout)
    gemm_proj<<<dim3(64, 8), 256, GSMEM>>>(xhi, xlo, wthi, wtlo, lhi, llo);
    // fused single-pass attention: writes attn matrix + outh (fp16)
    attn_kernel<<<dim3(32, 8, 16), 256, ASMEM>>>(lhi, llo, out + Y_SIZE, oh);
    // output projection (fp16 2-pass) + residual + bias
    gemm_out<<<dim3(64, 8), 256, GOSMEM>>>(oh, lwh, lwl, ypre, x, lb);
    // layernorm
    ln_kernel<<<MROWS, 256>>>(out, lng, lnb);
}

// round 15
// speedup vs baseline: 2.0410x; 1.0813x over previous
#include <cuda_runtime.h>
#include <cuda_bf16.h>
#include <cuda_fp16.h>
#include <cstdint>
#include <math.h>

#define BB 8
#define SS 1024
#define DD 1024
#define NH 16
#define HH 64
#define MROWS (BB*SS)            // 8192
#define Y_SIZE (BB*SS*DD)        // 8388608

// ---------------------------------------------------------------------------
// Scratch (device globals; no allocations allowed)
// ---------------------------------------------------------------------------
__device__ float g_ypre[MROWS*DD];                         // pre-layernorm y
__device__ __nv_bfloat16 g_xhi[MROWS*DD], g_xlo[MROWS*DD]; // x split (bf16)
__device__ __nv_bfloat16 g_wThi[DD*DD], g_wTlo[DD*DD];     // proj B: [c=n*64+h][d]
__device__ __half g_lwh[DD*DD];                            // outproj B fp16 plain
__device__ __half g_lhi[MROWS*DD], g_llo[MROWS*DD];        // logits fp16 hi/lo
__device__ __half g_oh[MROWS*DD];                          // attn heads out (fp16)

// ---------------------------------------------------------------------------
// mma.sync / ldmatrix / cp.async helpers (base ISA)
// ---------------------------------------------------------------------------
__device__ __forceinline__ uint32_t smem_u32(const void* p) {
    uint32_t a;
    asm("{ .reg .u64 t; cvta.to.shared.u64 t, %1; cvt.u32.u64 %0, t; }" : "=r"(a) : "l"(p));
    return a;
}

__device__ __forceinline__ void mma_bf16(float c[4],
                                         unsigned a0, unsigned a1, unsigned a2, unsigned a3,
                                         unsigned b0, unsigned b1) {
    asm volatile("mma.sync.aligned.m16n8k16.row.col.f32.bf16.bf16.f32 "
        "{%0,%1,%2,%3}, {%4,%5,%6,%7}, {%8,%9}, {%0,%1,%2,%3};"
        : "+f"(c[0]), "+f"(c[1]), "+f"(c[2]), "+f"(c[3])
        : "r"(a0), "r"(a1), "r"(a2), "r"(a3), "r"(b0), "r"(b1));
}
__device__ __forceinline__ void mma_fp16(float c[4],
                                         unsigned a0, unsigned a1, unsigned a2, unsigned a3,
                                         unsigned b0, unsigned b1) {
    asm volatile("mma.sync.aligned.m16n8k16.row.col.f32.f16.f16.f32 "
        "{%0,%1,%2,%3}, {%4,%5,%6,%7}, {%8,%9}, {%0,%1,%2,%3};"
        : "+f"(c[0]), "+f"(c[1]), "+f"(c[2]), "+f"(c[3])
        : "r"(a0), "r"(a1), "r"(a2), "r"(a3), "r"(b0), "r"(b1));
}

__device__ __forceinline__ void ldsm4(unsigned r[4], uint32_t addr) {
    asm volatile("ldmatrix.sync.aligned.m8n8.x4.shared.b16 {%0,%1,%2,%3}, [%4];"
        : "=r"(r[0]), "=r"(r[1]), "=r"(r[2]), "=r"(r[3]) : "r"(addr));
}
__device__ __forceinline__ void ldsm4t(unsigned r[4], uint32_t addr) {
    asm volatile("ldmatrix.sync.aligned.m8n8.x4.trans.shared.b16 {%0,%1,%2,%3}, [%4];"
        : "=r"(r[0]), "=r"(r[1]), "=r"(r[2]), "=r"(r[3]) : "r"(addr));
}

__device__ __forceinline__ void cp16(uint32_t dst, const void* src) {
    asm volatile("cp.async.cg.shared.global [%0], [%1], 16;" :: "r"(dst), "l"(src));
}
#define CP_COMMIT() asm volatile("cp.async.commit_group;" ::: "memory")
#define CP_WAIT0()  asm volatile("cp.async.wait_group 0;" ::: "memory")

// bf16 hi/lo split of float pair
__device__ __forceinline__ void split2(float x, float y, unsigned& h, unsigned& l) {
    __nv_bfloat16 hx = __float2bfloat16(x), hy = __float2bfloat16(y);
    __nv_bfloat162 hp(hx, hy);
    __nv_bfloat162 lp(__float2bfloat16(x - __bfloat162float(hx)),
                      __float2bfloat16(y - __bfloat162float(hy)));
    h = *(unsigned*)&hp;
    l = *(unsigned*)&lp;
}
// fp16 hi/lo split of float pair
__device__ __forceinline__ void split2h(float x, float y, unsigned& h, unsigned& l) {
    __half hx = __float2half_rn(x), hy = __float2half_rn(y);
    __half2 hp = __halves2half2(hx, hy);
    __half2 lp = __halves2half2(__float2half_rn(x - __half2float(hx)),
                                __float2half_rn(y - __half2float(hy)));
    h = *(unsigned*)&hp;
    l = *(unsigned*)&lp;
}
__device__ __forceinline__ unsigned h2pack(float x, float y) {
    __half2 v = __floats2half2_rn(x, y);
    return *(unsigned*)&v;
}

// ---------------------------------------------------------------------------
// Converters
// ---------------------------------------------------------------------------
__global__ __launch_bounds__(256) void split4_kernel(const float* __restrict__ s,
                                                     __nv_bfloat16* __restrict__ hi,
                                                     __nv_bfloat16* __restrict__ lo, int n4) {
    int i = blockIdx.x * 256 + threadIdx.x;
    if (i >= n4) return;
    float4 v = ((const float4*)s)[i];
    unsigned h0, l0, h1, l1;
    split2(v.x, v.y, h0, l0);
    split2(v.z, v.w, h1, l1);
    ((unsigned*)hi)[i*2]   = h0;
    ((unsigned*)hi)[i*2+1] = h1;
    ((unsigned*)lo)[i*2]   = l0;
    ((unsigned*)lo)[i*2+1] = l1;
}

// plain fp16 convert (for lin_w)
__global__ __launch_bounds__(256) void convlw_kernel(const float* __restrict__ s,
                                                     __half* __restrict__ d, int n4) {
    int i = blockIdx.x * 256 + threadIdx.x;
    if (i >= n4) return;
    float4 v = ((const float4*)s)[i];
    ((unsigned*)d)[i*2]   = h2pack(v.x, v.y);
    ((unsigned*)d)[i*2+1] = h2pack(v.z, v.w);
}

// w [NH][DD][HH] -> wT[c=n*64+h][d], split hi/lo (bf16)
__global__ __launch_bounds__(256) void convw_kernel(const float* __restrict__ w) {
    int o = blockIdx.x * 256 + threadIdx.x;
    int c = o >> 10, d = o & 1023;
    int n = c >> 6, h = c & 63;
    float v = __ldg(&w[(n * 1024 + d) * 64 + h]);
    __nv_bfloat16 hv = __float2bfloat16(v);
    g_wThi[o] = hv;
    g_wTlo[o] = __float2bfloat16(v - __bfloat162float(hv));
}

// ---------------------------------------------------------------------------
// Proj GEMM (bf16 hi/lo 3-pass): sync loads, K chunk 64, 73.7KB smem ->
// 2 CTAs/SM. Block 128x128, 8 warps (2m x 4n), warp 64x32.
// Writes logits as fp16 hi/lo.
// ---------------------------------------------------------------------------
#define GA_H 0
#define GA_L 18432
#define GB_H 36864
#define GB_L 55296
#define GSMEM 73728

__global__ __launch_bounds__(256) void gemm_proj(
    const __nv_bfloat16* __restrict__ Ah, const __nv_bfloat16* __restrict__ Al,
    const __nv_bfloat16* __restrict__ Bh, const __nv_bfloat16* __restrict__ Bl,
    __half* __restrict__ Chi, __half* __restrict__ Clo)
{
    extern __shared__ char sm[];
    const uint32_t sb = smem_u32(sm);
    const int tid = threadIdx.x, w = tid >> 5, lane = tid & 31;
    const int wm = w >> 2, wn = w & 3;
    const int r0 = blockIdx.x * 128, c0 = blockIdx.y * 128;

    float acc[4][4][4] = {};
    const int lrow = tid >> 3, lc8 = tid & 7;

    #pragma unroll 1
    for (int k0 = 0; k0 < 1024; k0 += 64) {
        __syncthreads();
        #pragma unroll
        for (int it = 0; it < 4; it++) {
            int rr = lrow + it * 32;
            size_t goA = (size_t)(r0 + rr) * 1024 + k0 + lc8 * 8;
            size_t goB = (size_t)(c0 + rr) * 1024 + k0 + lc8 * 8;
            uint32_t so = (rr * 72 + lc8 * 8) * 2;
            *(uint4*)(sm + GA_H + so) = *(const uint4*)(Ah + goA);
            *(uint4*)(sm + GA_L + so) = *(const uint4*)(Al + goA);
            *(uint4*)(sm + GB_H + so) = *(const uint4*)(Bh + goB);
            *(uint4*)(sm + GB_L + so) = *(const uint4*)(Bl + goB);
        }
        __syncthreads();
        #pragma unroll
        for (int ks = 0; ks < 4; ks++) {
            unsigned ah[4][4], al[4][4], bh[2][4], bl[2][4];
            uint32_t abase = sb + ((wm * 64 + (lane & 15)) * 72 + ks * 16 + (lane >> 4) * 8) * 2;
            #pragma unroll
            for (int mi = 0; mi < 4; mi++) {
                ldsm4(ah[mi], abase + GA_H + mi * 2304);
                ldsm4(al[mi], abase + GA_L + mi * 2304);
            }
            uint32_t bbase = sb + ((wn * 32 + (lane & 15)) * 72 + ks * 16 + (lane >> 4) * 8) * 2;
            #pragma unroll
            for (int ni = 0; ni < 2; ni++) {
                ldsm4(bh[ni], bbase + GB_H + ni * 2304);
                ldsm4(bl[ni], bbase + GB_L + ni * 2304);
            }
            #pragma unroll
            for (int mi = 0; mi < 4; mi++)
                #pragma unroll
                for (int ni = 0; ni < 2; ni++) {
                    mma_bf16(acc[mi][2*ni],   ah[mi][0],ah[mi][1],ah[mi][2],ah[mi][3], bh[ni][0], bh[ni][2]);
                    mma_bf16(acc[mi][2*ni+1], ah[mi][0],ah[mi][1],ah[mi][2],ah[mi][3], bh[ni][1], bh[ni][3]);
                    mma_bf16(acc[mi][2*ni],   ah[mi][0],ah[mi][1],ah[mi][2],ah[mi][3], bl[ni][0], bl[ni][2]);
                    mma_bf16(acc[mi][2*ni+1], ah[mi][0],ah[mi][1],ah[mi][2],ah[mi][3], bl[ni][1], bl[ni][3]);
                    mma_bf16(acc[mi][2*ni],   al[mi][0],al[mi][1],al[mi][2],al[mi][3], bh[ni][0], bh[ni][2]);
                    mma_bf16(acc[mi][2*ni+1], al[mi][0],al[mi][1],al[mi][2],al[mi][3], bh[ni][1], bh[ni][3]);
                }
        }
    }

    #pragma unroll
    for (int mi = 0; mi < 4; mi++) {
        int rr = r0 + wm * 64 + mi * 16 + (lane >> 2);
        #pragma unroll
        for (int nj = 0; nj < 4; nj++) {
            int cc = c0 + wn * 32 + nj * 8 + 2 * (lane & 3);
            #pragma unroll
            for (int half = 0; half < 2; half++) {
                unsigned h, l;
                split2h(acc[mi][nj][half*2], acc[mi][nj][half*2+1], h, l);
                size_t go = (size_t)(rr + half*8) * 1024 + cc;
                *(unsigned*)(Chi + go) = h;
                *(unsigned*)(Clo + go) = l;
            }
        }
    }
}

// ---------------------------------------------------------------------------
// Outproj GEMM, fp16 1-pass: A = outh (fp16), B = lin_w (fp16).
// C = a*b + RX + BIAS. 16 mma/ks. Smem 36.9KB.
// ---------------------------------------------------------------------------
#define GO_A  0
#define GO_B  18432
#define GOSMEM 36864

__global__ __launch_bounds__(256) void gemm_out(
    const __half* __restrict__ A, const __half* __restrict__ B,
    float* __restrict__ Cf, const float* __restrict__ RX, const float* __restrict__ BIAS)
{
    extern __shared__ char sm[];
    const uint32_t sb = smem_u32(sm);
    const int tid = threadIdx.x, w = tid >> 5, lane = tid & 31;
    const int wm = w >> 2, wn = w & 3;
    const int r0 = blockIdx.x * 128, c0 = blockIdx.y * 128;

    float acc[4][4][4] = {};
    const int lrow = tid >> 3, lc8 = tid & 7;

    #pragma unroll 1
    for (int k0 = 0; k0 < 1024; k0 += 64) {
        __syncthreads();
        #pragma unroll
        for (int it = 0; it < 4; it++) {
            int rr = lrow + it * 32;
            size_t goA = (size_t)(r0 + rr) * 1024 + k0 + lc8 * 8;
            size_t goB = (size_t)(c0 + rr) * 1024 + k0 + lc8 * 8;
            uint32_t so = (rr * 72 + lc8 * 8) * 2;
            *(uint4*)(sm + GO_A + so) = *(const uint4*)(A + goA);
            *(uint4*)(sm + GO_B + so) = *(const uint4*)(B + goB);
        }
        __syncthreads();
        #pragma unroll
        for (int ks = 0; ks < 4; ks++) {
            unsigned ah[4][4], bh[2][4];
            uint32_t abase = sb + ((wm * 64 + (lane & 15)) * 72 + ks * 16 + (lane >> 4) * 8) * 2;
            #pragma unroll
            for (int mi = 0; mi < 4; mi++) ldsm4(ah[mi], abase + GO_A + mi * 2304);
            uint32_t bbase = sb + ((wn * 32 + (lane & 15)) * 72 + ks * 16 + (lane >> 4) * 8) * 2;
            #pragma unroll
            for (int ni = 0; ni < 2; ni++) ldsm4(bh[ni], bbase + GO_B + ni * 2304);
            #pragma unroll
            for (int mi = 0; mi < 4; mi++)
                #pragma unroll
                for (int ni = 0; ni < 2; ni++) {
                    mma_fp16(acc[mi][2*ni],   ah[mi][0],ah[mi][1],ah[mi][2],ah[mi][3], bh[ni][0], bh[ni][2]);
                    mma_fp16(acc[mi][2*ni+1], ah[mi][0],ah[mi][1],ah[mi][2],ah[mi][3], bh[ni][1], bh[ni][3]);
                }
        }
    }

    #pragma unroll
    for (int mi = 0; mi < 4; mi++) {
        int rr = r0 + wm * 64 + mi * 16 + (lane >> 2);
        #pragma unroll
        for (int nj = 0; nj < 4; nj++) {
            int cc = c0 + wn * 32 + nj * 8 + 2 * (lane & 3);
            #pragma unroll
            for (int half = 0; half < 2; half++) {
                size_t go = (size_t)(rr + half*8) * 1024 + cc;
                float2 xv = *(const float2*)(RX + go);
                float2 bv = *(const float2*)(BIAS + cc);
                float2 o;
                o.x = acc[mi][nj][half*2]   + xv.x + bv.x;
                o.y = acc[mi][nj][half*2+1] + xv.y + bv.y;
                *(float2*)(Cf + go) = o;
            }
        }
    }
}

// ---------------------------------------------------------------------------
// Single-pass fused attention per (n, b, 32-row tile), 256 threads.
// Logits fp16 hi/lo. QK^T fp16 3-pass. Per-row shift by diagonal s_ii
// (q == k) makes exp values fit plain fp16; PV fp16 2-pass (p*vh + p*vl)
// with P fragments kept in registers. Scores smem is fp16 (halved).
// ---------------------------------------------------------------------------
#define PSTR 1032                       // halves per score row
#define A_QH  66048                     // pscore: 32*1032*2 = 66048
#define A_QL  70656                     // Q tiles: 32*72*2 = 4608 each
#define A_KB  75264                     // 2 bufs x (KH 18432 + KL 18432)
#define A_KBUF 36864
#define ASMEM (A_KB + 2*A_KBUF)         // 148992

__global__ __launch_bounds__(256, 1) void attn_kernel(
    const __half* __restrict__ LHI, const __half* __restrict__ LLO,
    float* __restrict__ out_attn, __half* __restrict__ OH)
{
    extern __shared__ char sm[];
    const uint32_t sb = smem_u32(sm);
    __half* psc = (__half*)sm;
    __shared__ float rs[32];
    __shared__ float rsw[8][32];
    __shared__ float qsq[32];

    const int rt = blockIdx.x, b = blockIdx.y, n = blockIdx.z;
    const int s0 = rt * 32;
    const int tid = threadIdx.x, w = tid >> 5, lane = tid & 31;
    const size_t rowbase = (size_t)b * 1024;
    const int colbase = n * 64;
    const int lrow = tid >> 3, lc8 = tid & 7;

    auto load_kv = [&](int buf, int tile) {
        const uint32_t bh = sb + A_KB + buf * A_KBUF;
        #pragma unroll
        for (int it = 0; it < 4; it++) {
            int row = lrow + it * 32;
            size_t go = (rowbase + tile * 128 + row) * 1024 + colbase + lc8 * 8;
            uint32_t so = (row * 72 + lc8 * 8) * 2;
            cp16(bh + so,         LHI + go);
            cp16(bh + 18432 + so, LLO + go);
        }
    };

    // prefetch K tile 0; load Q tile (32 x 64) hi/lo direct
    load_kv(0, 0);
    CP_COMMIT();
    {
        int row = tid >> 3, c8 = tid & 7;
        uint32_t so = (row * 72 + c8 * 8) * 2;
        size_t go = (rowbase + s0 + row) * 1024 + colbase + c8 * 8;
        *(uint4*)(sm + A_QH + so) = *(const uint4*)(LHI + go);
        *(uint4*)(sm + A_QL + so) = *(const uint4*)(LLO + go);
    }
    __syncthreads();

    // per-row |q|^2 (for the diagonal softmax shift)
    {
        int row = tid >> 3, c = (tid & 7) * 8;
        const __half* qhp = (const __half*)(sm + A_QH) + row * 72 + c;
        const __half* qlp = (const __half*)(sm + A_QL) + row * 72 + c;
        float s = 0.f;
        #pragma unroll
        for (int j = 0; j < 8; j++) {
            float v = __half2float(qhp[j]) + __half2float(qlp[j]);
            s += v * v;
        }
        s += __shfl_xor_sync(0xffffffffu, s, 1);
        s += __shfl_xor_sync(0xffffffffu, s, 2);
        s += __shfl_xor_sync(0xffffffffu, s, 4);
        if ((tid & 7) == 0) qsq[row] = s;
    }

    // hoist Q fragments to registers (kt-invariant)
    unsigned qh[4][2][4], ql[4][2][4];
    #pragma unroll
    for (int ks = 0; ks < 4; ks++) {
        uint32_t qb = sb + (((lane & 15)) * 72 + ks * 16 + (lane >> 4) * 8) * 2;
        #pragma unroll
        for (int mi = 0; mi < 2; mi++) {
            ldsm4(qh[ks][mi], qb + A_QH + mi * 2304);
            ldsm4(ql[ks][mi], qb + A_QL + mi * 2304);
        }
    }
    __syncthreads();

    // shift values for this thread's 4 row positions
    float mm[4];
    {
        int l4 = lane >> 2;
        mm[0] = qsq[l4];      mm[1] = qsq[l4 + 8];
        mm[2] = qsq[l4 + 16]; mm[3] = qsq[l4 + 24];
    }

    const float scale = 0.125f;
    float pacc[2][8][4] = {};
    float ssum[4] = {0.f, 0.f, 0.f, 0.f};

    // ---- fused loop over 8 key tiles (K == V, loaded once) ----
    #pragma unroll 1
    for (int kt = 0; kt < 8; kt++) {
        CP_WAIT0();
        __syncthreads();
        if (kt < 7) {
            load_kv((kt + 1) & 1, kt + 1);
            CP_COMMIT();
        }
        const uint32_t kbase = sb + A_KB + (kt & 1) * A_KBUF;

        // QK^T for this warp's 16 keys (fp16 3-pass)
        float sqk[2][2][4] = {};
        #pragma unroll
        for (int ks = 0; ks < 4; ks++) {
            unsigned kh[4], kl[4];
            uint32_t kb = kbase + ((w * 16 + (lane & 15)) * 72 + ks * 16 + (lane >> 4) * 8) * 2;
            ldsm4(kh, kb);
            ldsm4(kl, kb + 18432);
            #pragma unroll
            for (int mi = 0; mi < 2; mi++) {
                mma_fp16(sqk[mi][0], qh[ks][mi][0],qh[ks][mi][1],qh[ks][mi][2],qh[ks][mi][3], kh[0], kh[2]);
                mma_fp16(sqk[mi][1], qh[ks][mi][0],qh[ks][mi][1],qh[ks][mi][2],qh[ks][mi][3], kh[1], kh[3]);
                mma_fp16(sqk[mi][0], qh[ks][mi][0],qh[ks][mi][1],qh[ks][mi][2],qh[ks][mi][3], kl[0], kl[2]);
                mma_fp16(sqk[mi][1], qh[ks][mi][0],qh[ks][mi][1],qh[ks][mi][2],qh[ks][mi][3], kl[1], kl[3]);
                mma_fp16(sqk[mi][0], ql[ks][mi][0],ql[ks][mi][1],ql[ks][mi][2],ql[ks][mi][3], kh[0], kh[2]);
                mma_fp16(sqk[mi][1], ql[ks][mi][0],ql[ks][mi][1],ql[ks][mi][2],ql[ks][mi][3], kh[1], kh[3]);
            }
        }

        // exp with per-row diagonal shift; P kept in regs as fp16 + stored
        unsigned pa[2][4];
        #pragma unroll
        for (int mi = 0; mi < 2; mi++) {
            int r0q = mi * 16 + (lane >> 2);
            #pragma unroll
            for (int nj = 0; nj < 2; nj++) {
                float e0 = __expf((sqk[mi][nj][0] - mm[mi*2])   * scale);
                float e1 = __expf((sqk[mi][nj][1] - mm[mi*2])   * scale);
                float e2 = __expf((sqk[mi][nj][2] - mm[mi*2+1]) * scale);
                float e3 = __expf((sqk[mi][nj][3] - mm[mi*2+1]) * scale);
                ssum[mi*2]   += e0 + e1;
                ssum[mi*2+1] += e2 + e3;
                unsigned u01 = h2pack(e0, e1);
                unsigned u23 = h2pack(e2, e3);
                int cc = kt * 128 + w * 16 + nj * 8 + 2 * (lane & 3);
                *(unsigned*)&psc[r0q * PSTR + cc]       = u01;
                *(unsigned*)&psc[(r0q + 8) * PSTR + cc] = u23;
                pa[mi][nj*2]   = u01;
                pa[mi][nj*2+1] = u23;
            }
        }

        // P @ V on the same tile (V rows = this warp's 16 keys), fp16 2-pass
        #pragma unroll
        for (int hg = 0; hg < 4; hg++) {
            unsigned vh[4], vl[4];
            uint32_t vb = kbase + ((w * 16 + (lane & 15)) * 72 + hg * 16 + (lane >> 4) * 8) * 2;
            ldsm4t(vh, vb);
            ldsm4t(vl, vb + 18432);
            #pragma unroll
            for (int mi = 0; mi < 2; mi++) {
                mma_fp16(pacc[mi][2*hg],   pa[mi][0],pa[mi][1],pa[mi][2],pa[mi][3], vh[0], vh[1]);
                mma_fp16(pacc[mi][2*hg+1], pa[mi][0],pa[mi][1],pa[mi][2],pa[mi][3], vh[2], vh[3]);
                mma_fp16(pacc[mi][2*hg],   pa[mi][0],pa[mi][1],pa[mi][2],pa[mi][3], vl[0], vl[1]);
                mma_fp16(pacc[mi][2*hg+1], pa[mi][0],pa[mi][1],pa[mi][2],pa[mi][3], vl[2], vl[3]);
            }
        }
    }
    __syncthreads();     // all warps done reading K buffers before reuse

    // ---- row sums: reduce over the 4 lanes sharing a row, then cross-warp ----
    #pragma unroll
    for (int i = 0; i < 4; i++) {
        ssum[i] += __shfl_xor_sync(0xffffffffu, ssum[i], 1);
        ssum[i] += __shfl_xor_sync(0xffffffffu, ssum[i], 2);
    }
    if ((lane & 3) == 0) {
        int rr = lane >> 2;
        rsw[w][rr]      = ssum[0];
        rsw[w][rr + 8]  = ssum[1];
        rsw[w][rr + 16] = ssum[2];
        rsw[w][rr + 24] = ssum[3];
    }

    // ---- stage out fragments into the freed K-buffer (stride 66 floats) ----
    {
        float* rb = (float*)(sm + A_KB) + w * 2112;
        #pragma unroll
        for (int mi = 0; mi < 2; mi++) {
            int q0 = mi * 16 + (lane >> 2);
            #pragma unroll
            for (int g = 0; g < 8; g++) {
                int c = g * 8 + 2 * (lane & 3);
                *(float2*)&rb[q0 * 66 + c]       = make_float2(pacc[mi][g][0], pacc[mi][g][1]);
                *(float2*)&rb[(q0 + 8) * 66 + c] = make_float2(pacc[mi][g][2], pacc[mi][g][3]);
            }
        }
    }
    __syncthreads();
    if (tid < 32) {
        float t = 0.f;
        #pragma unroll
        for (int ww = 0; ww < 8; ww++) t += rsw[ww][tid];
        rs[tid] = 1.0f / t;
    }
    __syncthreads();

    // ---- write normalized attention from fp16 P ----
    {
        float* ap = out_attn + ((size_t)(n * BB + b)) * SS * SS + (size_t)s0 * SS;
        #pragma unroll
        for (int it = 0; it < 16; it++) {
            int idx = tid + it * 256;        // 4096 chunks of 8 halves
            int r = idx >> 7;
            int c8 = (idx & 127) * 8;
            uint4 p = *(const uint4*)&psc[r * PSTR + c8];
            float iv = rs[r];
            float2 f0 = __half22float2(*(__half2*)&p.x);
            float2 f1 = __half22float2(*(__half2*)&p.y);
            float2 f2 = __half22float2(*(__half2*)&p.z);
            float2 f3 = __half22float2(*(__half2*)&p.w);
            float4 v0 = make_float4(f0.x * iv, f0.y * iv, f1.x * iv, f1.y * iv);
            float4 v1 = make_float4(f2.x * iv, f2.y * iv, f3.x * iv, f3.y * iv);
            *(float4*)&ap[(size_t)r * SS + c8]     = v0;
            *(float4*)&ap[(size_t)r * SS + c8 + 4] = v1;
        }
    }

    // ---- cross-warp out reduction + outh epilogue (plain fp16) ----
    {
        const float* rbase = (const float*)(sm + A_KB);
        int q = tid >> 3, hb = (tid & 7) * 8;
        float o[8] = {};
        #pragma unroll
        for (int ww = 0; ww < 8; ww++) {
            const float* r2 = rbase + ww * 2112 + q * 66 + hb;
            #pragma unroll
            for (int j = 0; j < 4; j++) {
                float2 a = *(const float2*)(r2 + j * 2);
                o[j*2]   += a.x;
                o[j*2+1] += a.y;
            }
        }
        float iv = rs[q];
        size_t go = (rowbase + s0 + q) * 1024 + colbase + hb;
        #pragma unroll
        for (int j = 0; j < 4; j++) {
            __half2 hv = __floats2half2_rn(o[j*2] * iv, o[j*2+1] * iv);
            *(__half2*)(OH + go + j * 2) = hv;
        }
    }
}

// ---------------------------------------------------------------------------
// Layernorm per row of 1024
// ---------------------------------------------------------------------------
__global__ __launch_bounds__(256) void ln_kernel(float* __restrict__ y,
                                                 const float* __restrict__ g,
                                                 const float* __restrict__ bfn) {
    const int r = blockIdx.x;
    const int tid = threadIdx.x;
    const int lane = tid & 31, wid = tid >> 5;
    __shared__ float red1[8];
    __shared__ float red2[8];
    __shared__ float sh_mu, sh_rstd;

    float4 v = *(const float4*)&g_ypre[r * 1024 + tid * 4];
    float s = v.x + v.y + v.z + v.w;
    #pragma unroll
    for (int o = 16; o > 0; o >>= 1) s += __shfl_xor_sync(0xffffffffu, s, o);
    if (lane == 0) red1[wid] = s;
    __syncthreads();
    if (tid == 0) {
        float t = 0.f;
        #pragma unroll
        for (int i = 0; i < 8; i++) t += red1[i];
        sh_mu = t * (1.0f / 1024.0f);
    }
    __syncthreads();
    float mu = sh_mu;
    float dx = v.x - mu, dy = v.y - mu, dz = v.z - mu, dw = v.w - mu;
    float sq = dx * dx + dy * dy + dz * dz + dw * dw;
    #pragma unroll
    for (int o = 16; o > 0; o >>= 1) sq += __shfl_xor_sync(0xffffffffu, sq, o);
    if (lane == 0) red2[wid] = sq;
    __syncthreads();
    if (tid == 0) {
        float t = 0.f;
        #pragma unroll
        for (int i = 0; i < 8; i++) t += red2[i];
        sh_rstd = rsqrtf(t * (1.0f / 1024.0f) + 1e-5f);
    }
    __syncthreads();
    float rstd = sh_rstd;
    float4 gv = *(const float4*)&g[tid * 4];
    float4 bv = *(const float4*)&bfn[tid * 4];
    float4 o;
    o.x = dx * rstd * gv.x + bv.x;
    o.y = dy * rstd * gv.y + bv.y;
    o.z = dz * rstd * gv.z + bv.z;
    o.w = dw * rstd * gv.w + bv.w;
    *(float4*)&y[r * 1024 + tid * 4] = o;
}

// ---------------------------------------------------------------------------
extern "C" void kernel_launch(void* const* d_in, const int* in_sizes, int n_in,
                              void* d_out, int out_size) {
    const float* x   = (const float*)d_in[0];
    const float* w   = (const float*)d_in[1];
    const float* lw  = (const float*)d_in[2];
    const float* lb  = (const float*)d_in[3];
    const float* lng = (const float*)d_in[4];
    const float* lnb = (const float*)d_in[5];
    float* out = (float*)d_out;

    __nv_bfloat16 *xhi, *xlo, *wthi, *wtlo;
    __half *lwh, *lhi, *llo, *oh;
    float *ypre;
    cudaGetSymbolAddress((void**)&xhi, g_xhi);   cudaGetSymbolAddress((void**)&xlo, g_xlo);
    cudaGetSymbolAddress((void**)&wthi, g_wThi); cudaGetSymbolAddress((void**)&wtlo, g_wTlo);
    cudaGetSymbolAddress((void**)&lwh, g_lwh);
    cudaGetSymbolAddress((void**)&lhi, g_lhi);   cudaGetSymbolAddress((void**)&llo, g_llo);
    cudaGetSymbolAddress((void**)&oh, g_oh);
    cudaGetSymbolAddress((void**)&ypre, g_ypre);

    cudaFuncSetAttribute(gemm_proj, cudaFuncAttributeMaxDynamicSharedMemorySize, GSMEM);
    cudaFuncSetAttribute(gemm_out, cudaFuncAttributeMaxDynamicSharedMemorySize, GOSMEM);
    cudaFuncSetAttribute(attn_kernel, cudaFuncAttributeMaxDynamicSharedMemorySize, ASMEM);

    // input splits
    split4_kernel<<<8192, 256>>>(x, xhi, xlo, MROWS * DD / 4);
    convw_kernel<<<4096, 256>>>(w);
    convlw_kernel<<<1024, 256>>>(lw, lwh, DD * DD / 4);

    // head projection -> logits (fp16 hi/lo, concat layout)
    gemm_proj<<<dim3(64, 8), 256, GSMEM>>>(xhi, xlo, wthi, wtlo, lhi, llo);
    // fused single-pass attention: writes attn matrix + outh (fp16)
    attn_kernel<<<dim3(32, 8, 16), 256, ASMEM>>>(lhi, llo, out + Y_SIZE, oh);
    // output projection (fp16 1-pass) + residual + bias
    gemm_out<<<dim3(64, 8), 256, GOSMEM>>>(oh, lwh, ypre, x, lb);
    // layernorm
    ln_kernel<<<MROWS, 256>>>(out, lng, lnb);
}

// round 16
// speedup vs baseline: 2.2373x; 1.0962x over previous
#include <cuda_runtime.h>
#include <cuda_bf16.h>
#include <cuda_fp16.h>
#include <cstdint>
#include <math.h>

#define BB 8
#define SS 1024
#define DD 1024
#define NH 16
#define HH 64
#define MROWS (BB*SS)            // 8192
#define Y_SIZE (BB*SS*DD)        // 8388608

// ---------------------------------------------------------------------------
// Scratch (device globals; no allocations allowed)
// ---------------------------------------------------------------------------
__device__ float g_ypre[MROWS*DD];                         // pre-layernorm y
__device__ __nv_bfloat16 g_xhi[MROWS*DD], g_xlo[MROWS*DD]; // x split (bf16)
__device__ __nv_bfloat16 g_wThi[DD*DD], g_wTlo[DD*DD];     // proj B: [c=n*64+h][d]
__device__ __half g_lwh[DD*DD];                            // outproj B fp16 plain
__device__ __half g_lhi[MROWS*DD], g_llo[MROWS*DD];        // logits fp16 hi/lo
__device__ __half g_oh[MROWS*DD];                          // attn heads out (fp16)

// ---------------------------------------------------------------------------
// mma.sync / ldmatrix / cp.async helpers (base ISA)
// ---------------------------------------------------------------------------
__device__ __forceinline__ uint32_t smem_u32(const void* p) {
    uint32_t a;
    asm("{ .reg .u64 t; cvta.to.shared.u64 t, %1; cvt.u32.u64 %0, t; }" : "=r"(a) : "l"(p));
    return a;
}

__device__ __forceinline__ void mma_bf16(float c[4],
                                         unsigned a0, unsigned a1, unsigned a2, unsigned a3,
                                         unsigned b0, unsigned b1) {
    asm volatile("mma.sync.aligned.m16n8k16.row.col.f32.bf16.bf16.f32 "
        "{%0,%1,%2,%3}, {%4,%5,%6,%7}, {%8,%9}, {%0,%1,%2,%3};"
        : "+f"(c[0]), "+f"(c[1]), "+f"(c[2]), "+f"(c[3])
        : "r"(a0), "r"(a1), "r"(a2), "r"(a3), "r"(b0), "r"(b1));
}
__device__ __forceinline__ void mma_fp16(float c[4],
                                         unsigned a0, unsigned a1, unsigned a2, unsigned a3,
                                         unsigned b0, unsigned b1) {
    asm volatile("mma.sync.aligned.m16n8k16.row.col.f32.f16.f16.f32 "
        "{%0,%1,%2,%3}, {%4,%5,%6,%7}, {%8,%9}, {%0,%1,%2,%3};"
        : "+f"(c[0]), "+f"(c[1]), "+f"(c[2]), "+f"(c[3])
        : "r"(a0), "r"(a1), "r"(a2), "r"(a3), "r"(b0), "r"(b1));
}

__device__ __forceinline__ void ldsm4(unsigned r[4], uint32_t addr) {
    asm volatile("ldmatrix.sync.aligned.m8n8.x4.shared.b16 {%0,%1,%2,%3}, [%4];"
        : "=r"(r[0]), "=r"(r[1]), "=r"(r[2]), "=r"(r[3]) : "r"(addr));
}
__device__ __forceinline__ void ldsm4t(unsigned r[4], uint32_t addr) {
    asm volatile("ldmatrix.sync.aligned.m8n8.x4.trans.shared.b16 {%0,%1,%2,%3}, [%4];"
        : "=r"(r[0]), "=r"(r[1]), "=r"(r[2]), "=r"(r[3]) : "r"(addr));
}

__device__ __forceinline__ void cp16(uint32_t dst, const void* src) {
    asm volatile("cp.async.cg.shared.global [%0], [%1], 16;" :: "r"(dst), "l"(src));
}
#define CP_COMMIT() asm volatile("cp.async.commit_group;" ::: "memory")
#define CP_WAIT0()  asm volatile("cp.async.wait_group 0;" ::: "memory")

// bf16 hi/lo split of float pair
__device__ __forceinline__ void split2(float x, float y, unsigned& h, unsigned& l) {
    __nv_bfloat16 hx = __float2bfloat16(x), hy = __float2bfloat16(y);
    __nv_bfloat162 hp(hx, hy);
    __nv_bfloat162 lp(__float2bfloat16(x - __bfloat162float(hx)),
                      __float2bfloat16(y - __bfloat162float(hy)));
    h = *(unsigned*)&hp;
    l = *(unsigned*)&lp;
}
// fp16 hi/lo split of float pair
__device__ __forceinline__ void split2h(float x, float y, unsigned& h, unsigned& l) {
    __half hx = __float2half_rn(x), hy = __float2half_rn(y);
    __half2 hp = __halves2half2(hx, hy);
    __half2 lp = __halves2half2(__float2half_rn(x - __half2float(hx)),
                                __float2half_rn(y - __half2float(hy)));
    h = *(unsigned*)&hp;
    l = *(unsigned*)&lp;
}
__device__ __forceinline__ unsigned h2pack(float x, float y) {
    __half2 v = __floats2half2_rn(x, y);
    return *(unsigned*)&v;
}

// ---------------------------------------------------------------------------
// Converters
// ---------------------------------------------------------------------------
__global__ __launch_bounds__(256) void split4_kernel(const float* __restrict__ s,
                                                     __nv_bfloat16* __restrict__ hi,
                                                     __nv_bfloat16* __restrict__ lo, int n4) {
    int i = blockIdx.x * 256 + threadIdx.x;
    if (i >= n4) return;
    float4 v = ((const float4*)s)[i];
    unsigned h0, l0, h1, l1;
    split2(v.x, v.y, h0, l0);
    split2(v.z, v.w, h1, l1);
    ((unsigned*)hi)[i*2]   = h0;
    ((unsigned*)hi)[i*2+1] = h1;
    ((unsigned*)lo)[i*2]   = l0;
    ((unsigned*)lo)[i*2+1] = l1;
}

// plain fp16 convert (for lin_w)
__global__ __launch_bounds__(256) void convlw_kernel(const float* __restrict__ s,
                                                     __half* __restrict__ d, int n4) {
    int i = blockIdx.x * 256 + threadIdx.x;
    if (i >= n4) return;
    float4 v = ((const float4*)s)[i];
    ((unsigned*)d)[i*2]   = h2pack(v.x, v.y);
    ((unsigned*)d)[i*2+1] = h2pack(v.z, v.w);
}

// w [NH][DD][HH] -> wT[c=n*64+h][d], split hi/lo (bf16)
__global__ __launch_bounds__(256) void convw_kernel(const float* __restrict__ w) {
    int o = blockIdx.x * 256 + threadIdx.x;
    int c = o >> 10, d = o & 1023;
    int n = c >> 6, h = c & 63;
    float v = __ldg(&w[(n * 1024 + d) * 64 + h]);
    __nv_bfloat16 hv = __float2bfloat16(v);
    g_wThi[o] = hv;
    g_wTlo[o] = __float2bfloat16(v - __bfloat162float(hv));
}

// ---------------------------------------------------------------------------
// Proj GEMM (bf16 hi/lo 3-pass): sync loads, K chunk 64, 73.7KB smem ->
// 2 CTAs/SM. Block 128x128, 8 warps (2m x 4n), warp 64x32.
// Writes logits as fp16 hi/lo.
// ---------------------------------------------------------------------------
#define GA_H 0
#define GA_L 18432
#define GB_H 36864
#define GB_L 55296
#define GSMEM 73728

__global__ __launch_bounds__(256) void gemm_proj(
    const __nv_bfloat16* __restrict__ Ah, const __nv_bfloat16* __restrict__ Al,
    const __nv_bfloat16* __restrict__ Bh, const __nv_bfloat16* __restrict__ Bl,
    __half* __restrict__ Chi, __half* __restrict__ Clo)
{
    extern __shared__ char sm[];
    const uint32_t sb = smem_u32(sm);
    const int tid = threadIdx.x, w = tid >> 5, lane = tid & 31;
    const int wm = w >> 2, wn = w & 3;
    const int r0 = blockIdx.x * 128, c0 = blockIdx.y * 128;

    float acc[4][4][4] = {};
    const int lrow = tid >> 3, lc8 = tid & 7;

    #pragma unroll 1
    for (int k0 = 0; k0 < 1024; k0 += 64) {
        __syncthreads();
        #pragma unroll
        for (int it = 0; it < 4; it++) {
            int rr = lrow + it * 32;
            size_t goA = (size_t)(r0 + rr) * 1024 + k0 + lc8 * 8;
            size_t goB = (size_t)(c0 + rr) * 1024 + k0 + lc8 * 8;
            uint32_t so = (rr * 72 + lc8 * 8) * 2;
            *(uint4*)(sm + GA_H + so) = *(const uint4*)(Ah + goA);
            *(uint4*)(sm + GA_L + so) = *(const uint4*)(Al + goA);
            *(uint4*)(sm + GB_H + so) = *(const uint4*)(Bh + goB);
            *(uint4*)(sm + GB_L + so) = *(const uint4*)(Bl + goB);
        }
        __syncthreads();
        #pragma unroll
        for (int ks = 0; ks < 4; ks++) {
            unsigned ah[4][4], al[4][4], bh[2][4], bl[2][4];
            uint32_t abase = sb + ((wm * 64 + (lane & 15)) * 72 + ks * 16 + (lane >> 4) * 8) * 2;
            #pragma unroll
            for (int mi = 0; mi < 4; mi++) {
                ldsm4(ah[mi], abase + GA_H + mi * 2304);
                ldsm4(al[mi], abase + GA_L + mi * 2304);
            }
            uint32_t bbase = sb + ((wn * 32 + (lane & 15)) * 72 + ks * 16 + (lane >> 4) * 8) * 2;
            #pragma unroll
            for (int ni = 0; ni < 2; ni++) {
                ldsm4(bh[ni], bbase + GB_H + ni * 2304);
                ldsm4(bl[ni], bbase + GB_L + ni * 2304);
            }
            #pragma unroll
            for (int mi = 0; mi < 4; mi++)
                #pragma unroll
                for (int ni = 0; ni < 2; ni++) {
                    mma_bf16(acc[mi][2*ni],   ah[mi][0],ah[mi][1],ah[mi][2],ah[mi][3], bh[ni][0], bh[ni][2]);
                    mma_bf16(acc[mi][2*ni+1], ah[mi][0],ah[mi][1],ah[mi][2],ah[mi][3], bh[ni][1], bh[ni][3]);
                    mma_bf16(acc[mi][2*ni],   ah[mi][0],ah[mi][1],ah[mi][2],ah[mi][3], bl[ni][0], bl[ni][2]);
                    mma_bf16(acc[mi][2*ni+1], ah[mi][0],ah[mi][1],ah[mi][2],ah[mi][3], bl[ni][1], bl[ni][3]);
                    mma_bf16(acc[mi][2*ni],   al[mi][0],al[mi][1],al[mi][2],al[mi][3], bh[ni][0], bh[ni][2]);
                    mma_bf16(acc[mi][2*ni+1], al[mi][0],al[mi][1],al[mi][2],al[mi][3], bh[ni][1], bh[ni][3]);
                }
        }
    }

    #pragma unroll
    for (int mi = 0; mi < 4; mi++) {
        int rr = r0 + wm * 64 + mi * 16 + (lane >> 2);
        #pragma unroll
        for (int nj = 0; nj < 4; nj++) {
            int cc = c0 + wn * 32 + nj * 8 + 2 * (lane & 3);
            #pragma unroll
            for (int half = 0; half < 2; half++) {
                unsigned h, l;
                split2h(acc[mi][nj][half*2], acc[mi][nj][half*2+1], h, l);
                size_t go = (size_t)(rr + half*8) * 1024 + cc;
                *(unsigned*)(Chi + go) = h;
                *(unsigned*)(Clo + go) = l;
            }
        }
    }
}

// ---------------------------------------------------------------------------
// Outproj GEMM, fp16 1-pass: A = outh (fp16), B = lin_w (fp16).
// ---------------------------------------------------------------------------
#define GO_A  0
#define GO_B  18432
#define GOSMEM 36864

__global__ __launch_bounds__(256) void gemm_out(
    const __half* __restrict__ A, const __half* __restrict__ B,
    float* __restrict__ Cf, const float* __restrict__ RX, const float* __restrict__ BIAS)
{
    extern __shared__ char sm[];
    const uint32_t sb = smem_u32(sm);
    const int tid = threadIdx.x, w = tid >> 5, lane = tid & 31;
    const int wm = w >> 2, wn = w & 3;
    const int r0 = blockIdx.x * 128, c0 = blockIdx.y * 128;

    float acc[4][4][4] = {};
    const int lrow = tid >> 3, lc8 = tid & 7;

    #pragma unroll 1
    for (int k0 = 0; k0 < 1024; k0 += 64) {
        __syncthreads();
        #pragma unroll
        for (int it = 0; it < 4; it++) {
            int rr = lrow + it * 32;
            size_t goA = (size_t)(r0 + rr) * 1024 + k0 + lc8 * 8;
            size_t goB = (size_t)(c0 + rr) * 1024 + k0 + lc8 * 8;
            uint32_t so = (rr * 72 + lc8 * 8) * 2;
            *(uint4*)(sm + GO_A + so) = *(const uint4*)(A + goA);
            *(uint4*)(sm + GO_B + so) = *(const uint4*)(B + goB);
        }
        __syncthreads();
        #pragma unroll
        for (int ks = 0; ks < 4; ks++) {
            unsigned ah[4][4], bh[2][4];
            uint32_t abase = sb + ((wm * 64 + (lane & 15)) * 72 + ks * 16 + (lane >> 4) * 8) * 2;
            #pragma unroll
            for (int mi = 0; mi < 4; mi++) ldsm4(ah[mi], abase + GO_A + mi * 2304);
            uint32_t bbase = sb + ((wn * 32 + (lane & 15)) * 72 + ks * 16 + (lane >> 4) * 8) * 2;
            #pragma unroll
            for (int ni = 0; ni < 2; ni++) ldsm4(bh[ni], bbase + GO_B + ni * 2304);
            #pragma unroll
            for (int mi = 0; mi < 4; mi++)
                #pragma unroll
                for (int ni = 0; ni < 2; ni++) {
                    mma_fp16(acc[mi][2*ni],   ah[mi][0],ah[mi][1],ah[mi][2],ah[mi][3], bh[ni][0], bh[ni][2]);
                    mma_fp16(acc[mi][2*ni+1], ah[mi][0],ah[mi][1],ah[mi][2],ah[mi][3], bh[ni][1], bh[ni][3]);
                }
        }
    }

    #pragma unroll
    for (int mi = 0; mi < 4; mi++) {
        int rr = r0 + wm * 64 + mi * 16 + (lane >> 2);
        #pragma unroll
        for (int nj = 0; nj < 4; nj++) {
            int cc = c0 + wn * 32 + nj * 8 + 2 * (lane & 3);
            #pragma unroll
            for (int half = 0; half < 2; half++) {
                size_t go = (size_t)(rr + half*8) * 1024 + cc;
                float2 xv = *(const float2*)(RX + go);
                float2 bv = *(const float2*)(BIAS + cc);
                float2 o;
                o.x = acc[mi][nj][half*2]   + xv.x + bv.x;
                o.y = acc[mi][nj][half*2+1] + xv.y + bv.y;
                *(float2*)(Cf + go) = o;
            }
        }
    }
}

// ---------------------------------------------------------------------------
// Single-pass fused attention per (n, b, 32-row tile), 256 threads.
// Q plain fp16 (QK = 2-pass: qh*kh + qh*kl). V plain fp16 (PV = 1-pass).
// Per-row diagonal shift keeps exp values in fp16 range.
// ---------------------------------------------------------------------------
#define PSTR 1032                       // halves per score row
#define A_QH  66048                     // pscore: 32*1032*2 = 66048
#define A_KB  70656                     // Q tile: 32*72*2 = 4608
#define A_KBUF 36864                    // KH 18432 + KL 18432
#define ASMEM (A_KB + 2*A_KBUF)         // 144384

__global__ __launch_bounds__(256, 1) void attn_kernel(
    const __half* __restrict__ LHI, const __half* __restrict__ LLO,
    float* __restrict__ out_attn, __half* __restrict__ OH)
{
    extern __shared__ char sm[];
    const uint32_t sb = smem_u32(sm);
    __half* psc = (__half*)sm;
    __shared__ float rs[32];
    __shared__ float rsw[8][32];
    __shared__ float qsq[32];

    const int rt = blockIdx.x, b = blockIdx.y, n = blockIdx.z;
    const int s0 = rt * 32;
    const int tid = threadIdx.x, w = tid >> 5, lane = tid & 31;
    const size_t rowbase = (size_t)b * 1024;
    const int colbase = n * 64;
    const int lrow = tid >> 3, lc8 = tid & 7;

    auto load_kv = [&](int buf, int tile) {
        const uint32_t bh = sb + A_KB + buf * A_KBUF;
        #pragma unroll
        for (int it = 0; it < 4; it++) {
            int row = lrow + it * 32;
            size_t go = (rowbase + tile * 128 + row) * 1024 + colbase + lc8 * 8;
            uint32_t so = (row * 72 + lc8 * 8) * 2;
            cp16(bh + so,         LHI + go);
            cp16(bh + 18432 + so, LLO + go);
        }
    };

    // prefetch K tile 0; load Q tile (32 x 64, plain fp16) direct
    load_kv(0, 0);
    CP_COMMIT();
    {
        int row = tid >> 3, c8 = tid & 7;
        uint32_t so = (row * 72 + c8 * 8) * 2;
        size_t go = (rowbase + s0 + row) * 1024 + colbase + c8 * 8;
        *(uint4*)(sm + A_QH + so) = *(const uint4*)(LHI + go);
    }
    __syncthreads();

    // per-row |q|^2 (diagonal softmax shift; consistency matters, not exactness)
    {
        int row = tid >> 3, c = (tid & 7) * 8;
        const __half* qhp = (const __half*)(sm + A_QH) + row * 72 + c;
        float s = 0.f;
        #pragma unroll
        for (int j = 0; j < 8; j++) {
            float v = __half2float(qhp[j]);
            s += v * v;
        }
        s += __shfl_xor_sync(0xffffffffu, s, 1);
        s += __shfl_xor_sync(0xffffffffu, s, 2);
        s += __shfl_xor_sync(0xffffffffu, s, 4);
        if ((tid & 7) == 0) qsq[row] = s;
    }

    // hoist Q fragments to registers (kt-invariant, plain fp16)
    unsigned qh[4][2][4];
    #pragma unroll
    for (int ks = 0; ks < 4; ks++) {
        uint32_t qb = sb + (((lane & 15)) * 72 + ks * 16 + (lane >> 4) * 8) * 2;
        #pragma unroll
        for (int mi = 0; mi < 2; mi++)
            ldsm4(qh[ks][mi], qb + A_QH + mi * 2304);
    }
    __syncthreads();

    // shift values for this thread's 4 row positions
    float mm[4];
    {
        int l4 = lane >> 2;
        mm[0] = qsq[l4];      mm[1] = qsq[l4 + 8];
        mm[2] = qsq[l4 + 16]; mm[3] = qsq[l4 + 24];
    }

    const float scale = 0.125f;
    float pacc[2][8][4] = {};
    float ssum[4] = {0.f, 0.f, 0.f, 0.f};

    // ---- fused loop over 8 key tiles (K == V, loaded once) ----
    #pragma unroll 1
    for (int kt = 0; kt < 8; kt++) {
        CP_WAIT0();
        __syncthreads();
        if (kt < 7) {
            load_kv((kt + 1) & 1, kt + 1);
            CP_COMMIT();
        }
        const uint32_t kbase = sb + A_KB + (kt & 1) * A_KBUF;

        // QK^T for this warp's 16 keys (fp16 2-pass: qh*kh + qh*kl)
        float sqk[2][2][4] = {};
        #pragma unroll
        for (int ks = 0; ks < 4; ks++) {
            unsigned kh[4], kl[4];
            uint32_t kb = kbase + ((w * 16 + (lane & 15)) * 72 + ks * 16 + (lane >> 4) * 8) * 2;
            ldsm4(kh, kb);
            ldsm4(kl, kb + 18432);
            #pragma unroll
            for (int mi = 0; mi < 2; mi++) {
                mma_fp16(sqk[mi][0], qh[ks][mi][0],qh[ks][mi][1],qh[ks][mi][2],qh[ks][mi][3], kh[0], kh[2]);
                mma_fp16(sqk[mi][1], qh[ks][mi][0],qh[ks][mi][1],qh[ks][mi][2],qh[ks][mi][3], kh[1], kh[3]);
                mma_fp16(sqk[mi][0], qh[ks][mi][0],qh[ks][mi][1],qh[ks][mi][2],qh[ks][mi][3], kl[0], kl[2]);
                mma_fp16(sqk[mi][1], qh[ks][mi][0],qh[ks][mi][1],qh[ks][mi][2],qh[ks][mi][3], kl[1], kl[3]);
            }
        }

        // exp with per-row diagonal shift; P kept in regs as fp16 + stored
        unsigned pa[2][4];
        #pragma unroll
        for (int mi = 0; mi < 2; mi++) {
            int r0q = mi * 16 + (lane >> 2);
            #pragma unroll
            for (int nj = 0; nj < 2; nj++) {
                float e0 = __expf((sqk[mi][nj][0] - mm[mi*2])   * scale);
                float e1 = __expf((sqk[mi][nj][1] - mm[mi*2])   * scale);
                float e2 = __expf((sqk[mi][nj][2] - mm[mi*2+1]) * scale);
                float e3 = __expf((sqk[mi][nj][3] - mm[mi*2+1]) * scale);
                ssum[mi*2]   += e0 + e1;
                ssum[mi*2+1] += e2 + e3;
                unsigned u01 = h2pack(e0, e1);
                unsigned u23 = h2pack(e2, e3);
                int cc = kt * 128 + w * 16 + nj * 8 + 2 * (lane & 3);
                *(unsigned*)&psc[r0q * PSTR + cc]       = u01;
                *(unsigned*)&psc[(r0q + 8) * PSTR + cc] = u23;
                pa[mi][nj*2]   = u01;
                pa[mi][nj*2+1] = u23;
            }
        }

        // P @ V on the same tile (V rows = this warp's 16 keys), fp16 1-pass
        #pragma unroll
        for (int hg = 0; hg < 4; hg++) {
            unsigned vh[4];
            uint32_t vb = kbase + ((w * 16 + (lane & 15)) * 72 + hg * 16 + (lane >> 4) * 8) * 2;
            ldsm4t(vh, vb);
            #pragma unroll
            for (int mi = 0; mi < 2; mi++) {
                mma_fp16(pacc[mi][2*hg],   pa[mi][0],pa[mi][1],pa[mi][2],pa[mi][3], vh[0], vh[1]);
                mma_fp16(pacc[mi][2*hg+1], pa[mi][0],pa[mi][1],pa[mi][2],pa[mi][3], vh[2], vh[3]);
            }
        }
    }
    __syncthreads();     // all warps done reading K buffers before reuse

    // ---- row sums: reduce over the 4 lanes sharing a row, then cross-warp ----
    #pragma unroll
    for (int i = 0; i < 4; i++) {
        ssum[i] += __shfl_xor_sync(0xffffffffu, ssum[i], 1);
        ssum[i] += __shfl_xor_sync(0xffffffffu, ssum[i], 2);
    }
    if ((lane & 3) == 0) {
        int rr = lane >> 2;
        rsw[w][rr]      = ssum[0];
        rsw[w][rr + 8]  = ssum[1];
        rsw[w][rr + 16] = ssum[2];
        rsw[w][rr + 24] = ssum[3];
    }

    // ---- stage out fragments into the freed K-buffer (stride 66 floats) ----
    {
        float* rb = (float*)(sm + A_KB) + w * 2112;
        #pragma unroll
        for (int mi = 0; mi < 2; mi++) {
            int q0 = mi * 16 + (lane >> 2);
            #pragma unroll
            for (int g = 0; g < 8; g++) {
                int c = g * 8 + 2 * (lane & 3);
                *(float2*)&rb[q0 * 66 + c]       = make_float2(pacc[mi][g][0], pacc[mi][g][1]);
                *(float2*)&rb[(q0 + 8) * 66 + c] = make_float2(pacc[mi][g][2], pacc[mi][g][3]);
            }
        }
    }
    __syncthreads();
    if (tid < 32) {
        float t = 0.f;
        #pragma unroll
        for (int ww = 0; ww < 8; ww++) t += rsw[ww][tid];
        rs[tid] = 1.0f / t;
    }
    __syncthreads();

    // ---- write normalized attention from fp16 P ----
    {
        float* ap = out_attn + ((size_t)(n * BB + b)) * SS * SS + (size_t)s0 * SS;
        #pragma unroll
        for (int it = 0; it < 16; it++) {
            int idx = tid + it * 256;        // 4096 chunks of 8 halves
            int r = idx >> 7;
            int c8 = (idx & 127) * 8;
            uint4 p = *(const uint4*)&psc[r * PSTR + c8];
            float iv = rs[r];
            float2 f0 = __half22float2(*(__half2*)&p.x);
            float2 f1 = __half22float2(*(__half2*)&p.y);
            float2 f2 = __half22float2(*(__half2*)&p.z);
            float2 f3 = __half22float2(*(__half2*)&p.w);
            float4 v0 = make_float4(f0.x * iv, f0.y * iv, f1.x * iv, f1.y * iv);
            float4 v1 = make_float4(f2.x * iv, f2.y * iv, f3.x * iv, f3.y * iv);
            *(float4*)&ap[(size_t)r * SS + c8]     = v0;
            *(float4*)&ap[(size_t)r * SS + c8 + 4] = v1;
        }
    }

    // ---- cross-warp out reduction + outh epilogue (plain fp16) ----
    {
        const float* rbase = (const float*)(sm + A_KB);
        int q = tid >> 3, hb = (tid & 7) * 8;
        float o[8] = {};
        #pragma unroll
        for (int ww = 0; ww < 8; ww++) {
            const float* r2 = rbase + ww * 2112 + q * 66 + hb;
            #pragma unroll
            for (int j = 0; j < 4; j++) {
                float2 a = *(const float2*)(r2 + j * 2);
                o[j*2]   += a.x;
                o[j*2+1] += a.y;
            }
        }
        float iv = rs[q];
        size_t go = (rowbase + s0 + q) * 1024 + colbase + hb;
        #pragma unroll
        for (int j = 0; j < 4; j++) {
            __half2 hv = __floats2half2_rn(o[j*2] * iv, o[j*2+1] * iv);
            *(__half2*)(OH + go + j * 2) = hv;
        }
    }
}

// ---------------------------------------------------------------------------
// Layernorm per row of 1024
// ---------------------------------------------------------------------------
__global__ __launch_bounds__(256) void ln_kernel(float* __restrict__ y,
                                                 const float* __restrict__ g,
                                                 const float* __restrict__ bfn) {
    const int r = blockIdx.x;
    const int tid = threadIdx.x;
    const int lane = tid & 31, wid = tid >> 5;
    __shared__ float red1[8];
    __shared__ float red2[8];
    __shared__ float sh_mu, sh_rstd;

    float4 v = *(const float4*)&g_ypre[r * 1024 + tid * 4];
    float s = v.x + v.y + v.z + v.w;
    #pragma unroll
    for (int o = 16; o > 0; o >>= 1) s += __shfl_xor_sync(0xffffffffu, s, o);
    if (lane == 0) red1[wid] = s;
    __syncthreads();
    if (tid == 0) {
        float t = 0.f;
        #pragma unroll
        for (int i = 0; i < 8; i++) t += red1[i];
        sh_mu = t * (1.0f / 1024.0f);
    }
    __syncthreads();
    float mu = sh_mu;
    float dx = v.x - mu, dy = v.y - mu, dz = v.z - mu, dw = v.w - mu;
    float sq = dx * dx + dy * dy + dz * dz + dw * dw;
    #pragma unroll
    for (int o = 16; o > 0; o >>= 1) sq += __shfl_xor_sync(0xffffffffu, sq, o);
    if (lane == 0) red2[wid] = sq;
    __syncthreads();
    if (tid == 0) {
        float t = 0.f;
        #pragma unroll
        for (int i = 0; i < 8; i++) t += red2[i];
        sh_rstd = rsqrtf(t * (1.0f / 1024.0f) + 1e-5f);
    }
    __syncthreads();
    float rstd = sh_rstd;
    float4 gv = *(const float4*)&g[tid * 4];
    float4 bv = *(const float4*)&bfn[tid * 4];
    float4 o;
    o.x = dx * rstd * gv.x + bv.x;
    o.y = dy * rstd * gv.y + bv.y;
    o.z = dz * rstd * gv.z + bv.z;
    o.w = dw * rstd * gv.w + bv.w;
    *(float4*)&y[r * 1024 + tid * 4] = o;
}

// ---------------------------------------------------------------------------
extern "C" void kernel_launch(void* const* d_in, const int* in_sizes, int n_in,
                              void* d_out, int out_size) {
    const float* x   = (const float*)d_in[0];
    const float* w   = (const float*)d_in[1];
    const float* lw  = (const float*)d_in[2];
    const float* lb  = (const float*)d_in[3];
    const float* lng = (const float*)d_in[4];
    const float* lnb = (const float*)d_in[5];
    float* out = (float*)d_out;

    __nv_bfloat16 *xhi, *xlo, *wthi, *wtlo;
    __half *lwh, *lhi, *llo, *oh;
    float *ypre;
    cudaGetSymbolAddress((void**)&xhi, g_xhi);   cudaGetSymbolAddress((void**)&xlo, g_xlo);
    cudaGetSymbolAddress((void**)&wthi, g_wThi); cudaGetSymbolAddress((void**)&wtlo, g_wTlo);
    cudaGetSymbolAddress((void**)&lwh, g_lwh);
    cudaGetSymbolAddress((void**)&lhi, g_lhi);   cudaGetSymbolAddress((void**)&llo, g_llo);
    cudaGetSymbolAddress((void**)&oh, g_oh);
    cudaGetSymbolAddress((void**)&ypre, g_ypre);

    cudaFuncSetAttribute(gemm_proj, cudaFuncAttributeMaxDynamicSharedMemorySize, GSMEM);
    cudaFuncSetAttribute(gemm_out, cudaFuncAttributeMaxDynamicSharedMemorySize, GOSMEM);
    cudaFuncSetAttribute(attn_kernel, cudaFuncAttributeMaxDynamicSharedMemorySize, ASMEM);

    // input splits
    split4_kernel<<<8192, 256>>>(x, xhi, xlo, MROWS * DD / 4);
    convw_kernel<<<4096, 256>>>(w);
    convlw_kernel<<<1024, 256>>>(lw, lwh, DD * DD / 4);

    // head projection -> logits (fp16 hi/lo, concat layout)
    gemm_proj<<<dim3(64, 8), 256, GSMEM>>>(xhi, xlo, wthi, wtlo, lhi, llo);
    // fused single-pass attention: writes attn matrix + outh (fp16)
    attn_kernel<<<dim3(32, 8, 16), 256, ASMEM>>>(lhi, llo, out + Y_SIZE, oh);
    // output projection (fp16 1-pass) + residual + bias
    gemm_out<<<dim3(64, 8), 256, GOSMEM>>>(oh, lwh, ypre, x, lb);
    // layernorm
    ln_kernel<<<MROWS, 256>>>(out, lng, lnb);
}

// round 17
// speedup vs baseline: 2.7267x; 1.2187x over previous
#include <cuda_runtime.h>
#include <cuda_bf16.h>
#include <cuda_fp16.h>
#include <cstdint>
#include <math.h>

#define BB 8
#define SS 1024
#define DD 1024
#define NH 16
#define HH 64
#define MROWS (BB*SS)            // 8192
#define Y_SIZE (BB*SS*DD)        // 8388608

// ---------------------------------------------------------------------------
// Scratch (device globals; no allocations allowed)
// ---------------------------------------------------------------------------
__device__ float g_ypre[MROWS*DD];                 // pre-layernorm y
__device__ __half g_xh[MROWS*DD];                  // x (plain fp16)
__device__ __half g_wTh[DD*DD], g_wTl[DD*DD];      // proj B fp16 hi/lo: [c=n*64+h][d]
__device__ __half g_lwh[DD*DD];                    // outproj B fp16 plain
__device__ __half g_lh[MROWS*DD];                  // logits (plain fp16) [r][n*64+h]
__device__ __half g_oh[MROWS*DD];                  // attn heads out (fp16)

// ---------------------------------------------------------------------------
// mma.sync / ldmatrix / cp.async helpers (base ISA)
// ---------------------------------------------------------------------------
__device__ __forceinline__ uint32_t smem_u32(const void* p) {
    uint32_t a;
    asm("{ .reg .u64 t; cvta.to.shared.u64 t, %1; cvt.u32.u64 %0, t; }" : "=r"(a) : "l"(p));
    return a;
}

__device__ __forceinline__ void mma_fp16(float c[4],
                                         unsigned a0, unsigned a1, unsigned a2, unsigned a3,
                                         unsigned b0, unsigned b1) {
    asm volatile("mma.sync.aligned.m16n8k16.row.col.f32.f16.f16.f32 "
        "{%0,%1,%2,%3}, {%4,%5,%6,%7}, {%8,%9}, {%0,%1,%2,%3};"
        : "+f"(c[0]), "+f"(c[1]), "+f"(c[2]), "+f"(c[3])
        : "r"(a0), "r"(a1), "r"(a2), "r"(a3), "r"(b0), "r"(b1));
}

__device__ __forceinline__ void ldsm4(unsigned r[4], uint32_t addr) {
    asm volatile("ldmatrix.sync.aligned.m8n8.x4.shared.b16 {%0,%1,%2,%3}, [%4];"
        : "=r"(r[0]), "=r"(r[1]), "=r"(r[2]), "=r"(r[3]) : "r"(addr));
}
__device__ __forceinline__ void ldsm4t(unsigned r[4], uint32_t addr) {
    asm volatile("ldmatrix.sync.aligned.m8n8.x4.trans.shared.b16 {%0,%1,%2,%3}, [%4];"
        : "=r"(r[0]), "=r"(r[1]), "=r"(r[2]), "=r"(r[3]) : "r"(addr));
}

__device__ __forceinline__ void cp16(uint32_t dst, const void* src) {
    asm volatile("cp.async.cg.shared.global [%0], [%1], 16;" :: "r"(dst), "l"(src));
}
#define CP_COMMIT() asm volatile("cp.async.commit_group;" ::: "memory")
#define CP_WAIT0()  asm volatile("cp.async.wait_group 0;" ::: "memory")

// fp16 hi/lo split of float pair
__device__ __forceinline__ void split2h(float x, float y, unsigned& h, unsigned& l) {
    __half hx = __float2half_rn(x), hy = __float2half_rn(y);
    __half2 hp = __halves2half2(hx, hy);
    __half2 lp = __halves2half2(__float2half_rn(x - __half2float(hx)),
                                __float2half_rn(y - __half2float(hy)));
    h = *(unsigned*)&hp;
    l = *(unsigned*)&lp;
}
__device__ __forceinline__ unsigned h2pack(float x, float y) {
    __half2 v = __floats2half2_rn(x, y);
    return *(unsigned*)&v;
}

// ---------------------------------------------------------------------------
// Converters
// ---------------------------------------------------------------------------
// plain fp16 convert (x and lin_w)
__global__ __launch_bounds__(256) void convh_kernel(const float* __restrict__ s,
                                                    __half* __restrict__ d, int n4) {
    int i = blockIdx.x * 256 + threadIdx.x;
    if (i >= n4) return;
    float4 v = ((const float4*)s)[i];
    ((unsigned*)d)[i*2]   = h2pack(v.x, v.y);
    ((unsigned*)d)[i*2+1] = h2pack(v.z, v.w);
}

// w [NH][DD][HH] -> wT[c=n*64+h][d], fp16 hi/lo
__global__ __launch_bounds__(256) void convw_kernel(const float* __restrict__ w) {
    int o = blockIdx.x * 256 + threadIdx.x;
    int c = o >> 10, d = o & 1023;
    int n = c >> 6, h = c & 63;
    float v = __ldg(&w[(n * 1024 + d) * 64 + h]);
    __half hv = __float2half_rn(v);
    g_wTh[o] = hv;
    g_wTl[o] = __float2half_rn(v - __half2float(hv));
}

// ---------------------------------------------------------------------------
// Proj GEMM, fp16 2-pass: A = x (plain fp16), B = wT (fp16 hi/lo).
// logits = a*bh + a*bl, written as plain fp16. K chunk 64, smem 55.3KB.
// Block 128x128, 8 warps (2m x 4n), warp 64x32.
// ---------------------------------------------------------------------------
#define GP_A  0
#define GP_BH 18432
#define GP_BL 36864
#define GPSMEM 55296

__global__ __launch_bounds__(256) void gemm_proj(
    const __half* __restrict__ A, const __half* __restrict__ Bh,
    const __half* __restrict__ Bl, __half* __restrict__ C)
{
    extern __shared__ char sm[];
    const uint32_t sb = smem_u32(sm);
    const int tid = threadIdx.x, w = tid >> 5, lane = tid & 31;
    const int wm = w >> 2, wn = w & 3;
    const int r0 = blockIdx.x * 128, c0 = blockIdx.y * 128;

    float acc[4][4][4] = {};
    const int lrow = tid >> 3, lc8 = tid & 7;

    #pragma unroll 1
    for (int k0 = 0; k0 < 1024; k0 += 64) {
        __syncthreads();
        #pragma unroll
        for (int it = 0; it < 4; it++) {
            int rr = lrow + it * 32;
            size_t goA = (size_t)(r0 + rr) * 1024 + k0 + lc8 * 8;
            size_t goB = (size_t)(c0 + rr) * 1024 + k0 + lc8 * 8;
            uint32_t so = (rr * 72 + lc8 * 8) * 2;
            *(uint4*)(sm + GP_A  + so) = *(const uint4*)(A  + goA);
            *(uint4*)(sm + GP_BH + so) = *(const uint4*)(Bh + goB);
            *(uint4*)(sm + GP_BL + so) = *(const uint4*)(Bl + goB);
        }
        __syncthreads();
        #pragma unroll
        for (int ks = 0; ks < 4; ks++) {
            unsigned ah[4][4], bh[2][4], bl[2][4];
            uint32_t abase = sb + ((wm * 64 + (lane & 15)) * 72 + ks * 16 + (lane >> 4) * 8) * 2;
            #pragma unroll
            for (int mi = 0; mi < 4; mi++) ldsm4(ah[mi], abase + GP_A + mi * 2304);
            uint32_t bbase = sb + ((wn * 32 + (lane & 15)) * 72 + ks * 16 + (lane >> 4) * 8) * 2;
            #pragma unroll
            for (int ni = 0; ni < 2; ni++) {
                ldsm4(bh[ni], bbase + GP_BH + ni * 2304);
                ldsm4(bl[ni], bbase + GP_BL + ni * 2304);
            }
            #pragma unroll
            for (int mi = 0; mi < 4; mi++)
                #pragma unroll
                for (int ni = 0; ni < 2; ni++) {
                    mma_fp16(acc[mi][2*ni],   ah[mi][0],ah[mi][1],ah[mi][2],ah[mi][3], bh[ni][0], bh[ni][2]);
                    mma_fp16(acc[mi][2*ni+1], ah[mi][0],ah[mi][1],ah[mi][2],ah[mi][3], bh[ni][1], bh[ni][3]);
                    mma_fp16(acc[mi][2*ni],   ah[mi][0],ah[mi][1],ah[mi][2],ah[mi][3], bl[ni][0], bl[ni][2]);
                    mma_fp16(acc[mi][2*ni+1], ah[mi][0],ah[mi][1],ah[mi][2],ah[mi][3], bl[ni][1], bl[ni][3]);
                }
        }
    }

    #pragma unroll
    for (int mi = 0; mi < 4; mi++) {
        int rr = r0 + wm * 64 + mi * 16 + (lane >> 2);
        #pragma unroll
        for (int nj = 0; nj < 4; nj++) {
            int cc = c0 + wn * 32 + nj * 8 + 2 * (lane & 3);
            #pragma unroll
            for (int half = 0; half < 2; half++) {
                size_t go = (size_t)(rr + half*8) * 1024 + cc;
                *(unsigned*)(C + go) = h2pack(acc[mi][nj][half*2], acc[mi][nj][half*2+1]);
            }
        }
    }
}

// ---------------------------------------------------------------------------
// Outproj GEMM, fp16 1-pass: A = outh (fp16), B = lin_w (fp16).
// ---------------------------------------------------------------------------
#define GO_A  0
#define GO_B  18432
#define GOSMEM 36864

__global__ __launch_bounds__(256) void gemm_out(
    const __half* __restrict__ A, const __half* __restrict__ B,
    float* __restrict__ Cf, const float* __restrict__ RX, const float* __restrict__ BIAS)
{
    extern __shared__ char sm[];
    const uint32_t sb = smem_u32(sm);
    const int tid = threadIdx.x, w = tid >> 5, lane = tid & 31;
    const int wm = w >> 2, wn = w & 3;
    const int r0 = blockIdx.x * 128, c0 = blockIdx.y * 128;

    float acc[4][4][4] = {};
    const int lrow = tid >> 3, lc8 = tid & 7;

    #pragma unroll 1
    for (int k0 = 0; k0 < 1024; k0 += 64) {
        __syncthreads();
        #pragma unroll
        for (int it = 0; it < 4; it++) {
            int rr = lrow + it * 32;
            size_t goA = (size_t)(r0 + rr) * 1024 + k0 + lc8 * 8;
            size_t goB = (size_t)(c0 + rr) * 1024 + k0 + lc8 * 8;
            uint32_t so = (rr * 72 + lc8 * 8) * 2;
            *(uint4*)(sm + GO_A + so) = *(const uint4*)(A + goA);
            *(uint4*)(sm + GO_B + so) = *(const uint4*)(B + goB);
        }
        __syncthreads();
        #pragma unroll
        for (int ks = 0; ks < 4; ks++) {
            unsigned ah[4][4], bh[2][4];
            uint32_t abase = sb + ((wm * 64 + (lane & 15)) * 72 + ks * 16 + (lane >> 4) * 8) * 2;
            #pragma unroll
            for (int mi = 0; mi < 4; mi++) ldsm4(ah[mi], abase + GO_A + mi * 2304);
            uint32_t bbase = sb + ((wn * 32 + (lane & 15)) * 72 + ks * 16 + (lane >> 4) * 8) * 2;
            #pragma unroll
            for (int ni = 0; ni < 2; ni++) ldsm4(bh[ni], bbase + GO_B + ni * 2304);
            #pragma unroll
            for (int mi = 0; mi < 4; mi++)
                #pragma unroll
                for (int ni = 0; ni < 2; ni++) {
                    mma_fp16(acc[mi][2*ni],   ah[mi][0],ah[mi][1],ah[mi][2],ah[mi][3], bh[ni][0], bh[ni][2]);
                    mma_fp16(acc[mi][2*ni+1], ah[mi][0],ah[mi][1],ah[mi][2],ah[mi][3], bh[ni][1], bh[ni][3]);
                }
        }
    }

    #pragma unroll
    for (int mi = 0; mi < 4; mi++) {
        int rr = r0 + wm * 64 + mi * 16 + (lane >> 2);
        #pragma unroll
        for (int nj = 0; nj < 4; nj++) {
            int cc = c0 + wn * 32 + nj * 8 + 2 * (lane & 3);
            #pragma unroll
            for (int half = 0; half < 2; half++) {
                size_t go = (size_t)(rr + half*8) * 1024 + cc;
                float2 xv = *(const float2*)(RX + go);
                float2 bv = *(const float2*)(BIAS + cc);
                float2 o;
                o.x = acc[mi][nj][half*2]   + xv.x + bv.x;
                o.y = acc[mi][nj][half*2+1] + xv.y + bv.y;
                *(float2*)(Cf + go) = o;
            }
        }
    }
}

// ---------------------------------------------------------------------------
// Single-pass fused attention per (n, b, 32-row tile), 256 threads.
// Logits plain fp16: QK 1-pass, PV 1-pass. Per-row diagonal shift keeps exp
// values in fp16 range. KV smem halved (one fp16 tile per buffer).
// ---------------------------------------------------------------------------
#define PSTR 1032                       // halves per score row
#define A_QH  66048                     // pscore: 32*1032*2 = 66048
#define A_KB  70656                     // Q tile: 32*72*2 = 4608
#define A_KBUF 18432                    // one fp16 K tile (128 x 72 halves)
#define ASMEM (A_KB + 2*A_KBUF)         // 107520

__global__ __launch_bounds__(256, 1) void attn_kernel(
    const __half* __restrict__ L,
    float* __restrict__ out_attn, __half* __restrict__ OH)
{
    extern __shared__ char sm[];
    const uint32_t sb = smem_u32(sm);
    __half* psc = (__half*)sm;
    __shared__ float rs[32];
    __shared__ float rsw[8][32];
    __shared__ float qsq[32];

    const int rt = blockIdx.x, b = blockIdx.y, n = blockIdx.z;
    const int s0 = rt * 32;
    const int tid = threadIdx.x, w = tid >> 5, lane = tid & 31;
    const size_t rowbase = (size_t)b * 1024;
    const int colbase = n * 64;
    const int lrow = tid >> 3, lc8 = tid & 7;

    auto load_kv = [&](int buf, int tile) {
        const uint32_t bh = sb + A_KB + buf * A_KBUF;
        #pragma unroll
        for (int it = 0; it < 4; it++) {
            int row = lrow + it * 32;
            size_t go = (rowbase + tile * 128 + row) * 1024 + colbase + lc8 * 8;
            uint32_t so = (row * 72 + lc8 * 8) * 2;
            cp16(bh + so, L + go);
        }
    };

    // prefetch K tile 0; load Q tile (32 x 64, plain fp16) direct
    load_kv(0, 0);
    CP_COMMIT();
    {
        int row = tid >> 3, c8 = tid & 7;
        uint32_t so = (row * 72 + c8 * 8) * 2;
        size_t go = (rowbase + s0 + row) * 1024 + colbase + c8 * 8;
        *(uint4*)(sm + A_QH + so) = *(const uint4*)(L + go);
    }
    __syncthreads();

    // per-row |q|^2 (diagonal softmax shift; consistency matters, not exactness)
    {
        int row = tid >> 3, c = (tid & 7) * 8;
        const __half* qhp = (const __half*)(sm + A_QH) + row * 72 + c;
        float s = 0.f;
        #pragma unroll
        for (int j = 0; j < 8; j++) {
            float v = __half2float(qhp[j]);
            s += v * v;
        }
        s += __shfl_xor_sync(0xffffffffu, s, 1);
        s += __shfl_xor_sync(0xffffffffu, s, 2);
        s += __shfl_xor_sync(0xffffffffu, s, 4);
        if ((tid & 7) == 0) qsq[row] = s;
    }

    // hoist Q fragments to registers (kt-invariant, plain fp16)
    unsigned qh[4][2][4];
    #pragma unroll
    for (int ks = 0; ks < 4; ks++) {
        uint32_t qb = sb + (((lane & 15)) * 72 + ks * 16 + (lane >> 4) * 8) * 2;
        #pragma unroll
        for (int mi = 0; mi < 2; mi++)
            ldsm4(qh[ks][mi], qb + A_QH + mi * 2304);
    }
    __syncthreads();

    // shift values for this thread's 4 row positions
    float mm[4];
    {
        int l4 = lane >> 2;
        mm[0] = qsq[l4];      mm[1] = qsq[l4 + 8];
        mm[2] = qsq[l4 + 16]; mm[3] = qsq[l4 + 24];
    }

    const float scale = 0.125f;
    float pacc[2][8][4] = {};
    float ssum[4] = {0.f, 0.f, 0.f, 0.f};

    // ---- fused loop over 8 key tiles (K == V, loaded once) ----
    #pragma unroll 1
    for (int kt = 0; kt < 8; kt++) {
        CP_WAIT0();
        __syncthreads();
        if (kt < 7) {
            load_kv((kt + 1) & 1, kt + 1);
            CP_COMMIT();
        }
        const uint32_t kbase = sb + A_KB + (kt & 1) * A_KBUF;

        // QK^T for this warp's 16 keys (fp16 1-pass)
        float sqk[2][2][4] = {};
        #pragma unroll
        for (int ks = 0; ks < 4; ks++) {
            unsigned kh[4];
            uint32_t kb = kbase + ((w * 16 + (lane & 15)) * 72 + ks * 16 + (lane >> 4) * 8) * 2;
            ldsm4(kh, kb);
            #pragma unroll
            for (int mi = 0; mi < 2; mi++) {
                mma_fp16(sqk[mi][0], qh[ks][mi][0],qh[ks][mi][1],qh[ks][mi][2],qh[ks][mi][3], kh[0], kh[2]);
                mma_fp16(sqk[mi][1], qh[ks][mi][0],qh[ks][mi][1],qh[ks][mi][2],qh[ks][mi][3], kh[1], kh[3]);
            }
        }

        // exp with per-row diagonal shift; P kept in regs as fp16 + stored
        unsigned pa[2][4];
        #pragma unroll
        for (int mi = 0; mi < 2; mi++) {
            int r0q = mi * 16 + (lane >> 2);
            #pragma unroll
            for (int nj = 0; nj < 2; nj++) {
                float e0 = __expf((sqk[mi][nj][0] - mm[mi*2])   * scale);
                float e1 = __expf((sqk[mi][nj][1] - mm[mi*2])   * scale);
                float e2 = __expf((sqk[mi][nj][2] - mm[mi*2+1]) * scale);
                float e3 = __expf((sqk[mi][nj][3] - mm[mi*2+1]) * scale);
                ssum[mi*2]   += e0 + e1;
                ssum[mi*2+1] += e2 + e3;
                unsigned u01 = h2pack(e0, e1);
                unsigned u23 = h2pack(e2, e3);
                int cc = kt * 128 + w * 16 + nj * 8 + 2 * (lane & 3);
                *(unsigned*)&psc[r0q * PSTR + cc]       = u01;
                *(unsigned*)&psc[(r0q + 8) * PSTR + cc] = u23;
                pa[mi][nj*2]   = u01;
                pa[mi][nj*2+1] = u23;
            }
        }

        // P @ V on the same tile (V rows = this warp's 16 keys), fp16 1-pass
        #pragma unroll
        for (int hg = 0; hg < 4; hg++) {
            unsigned vh[4];
            uint32_t vb = kbase + ((w * 16 + (lane & 15)) * 72 + hg * 16 + (lane >> 4) * 8) * 2;
            ldsm4t(vh, vb);
            #pragma unroll
            for (int mi = 0; mi < 2; mi++) {
                mma_fp16(pacc[mi][2*hg],   pa[mi][0],pa[mi][1],pa[mi][2],pa[mi][3], vh[0], vh[1]);
                mma_fp16(pacc[mi][2*hg+1], pa[mi][0],pa[mi][1],pa[mi][2],pa[mi][3], vh[2], vh[3]);
            }
        }
    }
    __syncthreads();     // all warps done reading K buffers before reuse

    // ---- row sums: reduce over the 4 lanes sharing a row, then cross-warp ----
    #pragma unroll
    for (int i = 0; i < 4; i++) {
        ssum[i] += __shfl_xor_sync(0xffffffffu, ssum[i], 1);
        ssum[i] += __shfl_xor_sync(0xffffffffu, ssum[i], 2);
    }
    if ((lane & 3) == 0) {
        int rr = lane >> 2;
        rsw[w][rr]      = ssum[0];
        rsw[w][rr + 8]  = ssum[1];
        rsw[w][rr + 16] = ssum[2];
        rsw[w][rr + 24] = ssum[3];
    }

    // ---- stage out fragments into the freed K-buffer (stride 66 floats) ----
    // NOTE: 8 warps x 32 rows x 66 floats = 67584 B > 2*A_KBUF (36864), so
    // overflow into the pscore region is NOT allowed; stage in two groups.
    // Group layout: 4 warps fit in 2*A_KBUF (4*8448=33792 B). Do warps 0-3,
    // reduce, then warps 4-7, reduce.
    {
        float iv = 0.f;
        int q = tid >> 3, hb = (tid & 7) * 8;
        float o[8] = {};
        #pragma unroll
        for (int grp = 0; grp < 2; grp++) {
            __syncthreads();
            if ((w >> 2) == grp) {
                float* rb = (float*)(sm + A_KB) + (w & 3) * 2112;
                #pragma unroll
                for (int mi = 0; mi < 2; mi++) {
                    int q0 = mi * 16 + (lane >> 2);
                    #pragma unroll
                    for (int g = 0; g < 8; g++) {
                        int c = g * 8 + 2 * (lane & 3);
                        *(float2*)&rb[q0 * 66 + c]       = make_float2(pacc[mi][g][0], pacc[mi][g][1]);
                        *(float2*)&rb[(q0 + 8) * 66 + c] = make_float2(pacc[mi][g][2], pacc[mi][g][3]);
                    }
                }
            }
            __syncthreads();
            const float* rbase = (const float*)(sm + A_KB);
            #pragma unroll
            for (int ww = 0; ww < 4; ww++) {
                const float* r2 = rbase + ww * 2112 + q * 66 + hb;
                #pragma unroll
                for (int j = 0; j < 4; j++) {
                    float2 a = *(const float2*)(r2 + j * 2);
                    o[j*2]   += a.x;
                    o[j*2+1] += a.y;
                }
            }
        }
        // row-sum reduce (placed here so rsw writes precede this barrier chain)
        if (tid < 32) {
            float t = 0.f;
            #pragma unroll
            for (int ww = 0; ww < 8; ww++) t += rsw[ww][tid];
            rs[tid] = 1.0f / t;
        }
        __syncthreads();
        iv = rs[q];
        size_t go = (rowbase + s0 + q) * 1024 + colbase + hb;
        #pragma unroll
        for (int j = 0; j < 4; j++) {
            __half2 hv = __floats2half2_rn(o[j*2] * iv, o[j*2+1] * iv);
            *(__half2*)(OH + go + j * 2) = hv;
        }
    }

    // ---- write normalized attention from fp16 P ----
    {
        float* ap = out_attn + ((size_t)(n * BB + b)) * SS * SS + (size_t)s0 * SS;
        #pragma unroll
        for (int it = 0; it < 16; it++) {
            int idx = tid + it * 256;        // 4096 chunks of 8 halves
            int r = idx >> 7;
            int c8 = (idx & 127) * 8;
            uint4 p = *(const uint4*)&psc[r * PSTR + c8];
            float iv = rs[r];
            float2 f0 = __half22float2(*(__half2*)&p.x);
            float2 f1 = __half22float2(*(__half2*)&p.y);
            float2 f2 = __half22float2(*(__half2*)&p.z);
            float2 f3 = __half22float2(*(__half2*)&p.w);
            float4 v0 = make_float4(f0.x * iv, f0.y * iv, f1.x * iv, f1.y * iv);
            float4 v1 = make_float4(f2.x * iv, f2.y * iv, f3.x * iv, f3.y * iv);
            *(float4*)&ap[(size_t)r * SS + c8]     = v0;
            *(float4*)&ap[(size_t)r * SS + c8 + 4] = v1;
        }
    }
}

// ---------------------------------------------------------------------------
// Layernorm per row of 1024
// ---------------------------------------------------------------------------
__global__ __launch_bounds__(256) void ln_kernel(float* __restrict__ y,
                                                 const float* __restrict__ g,
                                                 const float* __restrict__ bfn) {
    const int r = blockIdx.x;
    const int tid = threadIdx.x;
    const int lane = tid & 31, wid = tid >> 5;
    __shared__ float red1[8];
    __shared__ float red2[8];
    __shared__ float sh_mu, sh_rstd;

    float4 v = *(const float4*)&g_ypre[r * 1024 + tid * 4];
    float s = v.x + v.y + v.z + v.w;
    #pragma unroll
    for (int o = 16; o > 0; o >>= 1) s += __shfl_xor_sync(0xffffffffu, s, o);
    if (lane == 0) red1[wid] = s;
    __syncthreads();
    if (tid == 0) {
        float t = 0.f;
        #pragma unroll
        for (int i = 0; i < 8; i++) t += red1[i];
        sh_mu = t * (1.0f / 1024.0f);
    }
    __syncthreads();
    float mu = sh_mu;
    float dx = v.x - mu, dy = v.y - mu, dz = v.z - mu, dw = v.w - mu;
    float sq = dx * dx + dy * dy + dz * dz + dw * dw;
    #pragma unroll
    for (int o = 16; o > 0; o >>= 1) sq += __shfl_xor_sync(0xffffffffu, sq, o);
    if (lane == 0) red2[wid] = sq;
    __syncthreads();
    if (tid == 0) {
        float t = 0.f;
        #pragma unroll
        for (int i = 0; i < 8; i++) t += red2[i];
        sh_rstd = rsqrtf(t * (1.0f / 1024.0f) + 1e-5f);
    }
    __syncthreads();
    float rstd = sh_rstd;
    float4 gv = *(const float4*)&g[tid * 4];
    float4 bv = *(const float4*)&bfn[tid * 4];
    float4 o;
    o.x = dx * rstd * gv.x + bv.x;
    o.y = dy * rstd * gv.y + bv.y;
    o.z = dz * rstd * gv.z + bv.z;
    o.w = dw * rstd * gv.w + bv.w;
    *(float4*)&y[r * 1024 + tid * 4] = o;
}

// ---------------------------------------------------------------------------
extern "C" void kernel_launch(void* const* d_in, const int* in_sizes, int n_in,
                              void* d_out, int out_size) {
    const float* x   = (const float*)d_in[0];
    const float* w   = (const float*)d_in[1];
    const float* lw  = (const float*)d_in[2];
    const float* lb  = (const float*)d_in[3];
    const float* lng = (const float*)d_in[4];
    const float* lnb = (const float*)d_in[5];
    float* out = (float*)d_out;

    __half *xh, *wth, *wtl, *lwh, *lh, *oh;
    float *ypre;
    cudaGetSymbolAddress((void**)&xh, g_xh);
    cudaGetSymbolAddress((void**)&wth, g_wTh); cudaGetSymbolAddress((void**)&wtl, g_wTl);
    cudaGetSymbolAddress((void**)&lwh, g_lwh);
    cudaGetSymbolAddress((void**)&lh, g_lh);
    cudaGetSymbolAddress((void**)&oh, g_oh);
    cudaGetSymbolAddress((void**)&ypre, g_ypre);

    cudaFuncSetAttribute(gemm_proj, cudaFuncAttributeMaxDynamicSharedMemorySize, GPSMEM);
    cudaFuncSetAttribute(gemm_out, cudaFuncAttributeMaxDynamicSharedMemorySize, GOSMEM);
    cudaFuncSetAttribute(attn_kernel, cudaFuncAttributeMaxDynamicSharedMemorySize, ASMEM);

    // input conversions
    convh_kernel<<<8192, 256>>>(x, xh, MROWS * DD / 4);
    convw_kernel<<<4096, 256>>>(w);
    convh_kernel<<<1024, 256>>>(lw, lwh, DD * DD / 4);

    // head projection -> logits (plain fp16, concat layout)
    gemm_proj<<<dim3(64, 8), 256, GPSMEM>>>(xh, wth, wtl, lh);
    // fused single-pass attention: writes attn matrix + outh (fp16)
    attn_kernel<<<dim3(32, 8, 16), 256, ASMEM>>>(lh, out + Y_SIZE, oh);
    // output projection (fp16 1-pass) + residual + bias
    gemm_out<<<dim3(64, 8), 256, GOSMEM>>>(oh, lwh, ypre, x, lb);
    // layernorm
    ln_kernel<<<MROWS, 256>>>(out, lng, lnb);
}